// round 7
// baseline (speedup 1.0000x reference)
#include <cuda_runtime.h>
#include <cuda_bf16.h>

// ---------------------------------------------------------------------------
// Problem constants
// ---------------------------------------------------------------------------
#define NB    64          // batch
#define ZD    128         // latent dim
#define CIN   8
#define LL    1024        // W*H
#define C0C   256         // attention channels
#define CQKC  32
#define FFC   64          // filters
#define GG    65536       // NB * LL (total positions)

// ---------------------------------------------------------------------------
// Device scratch (allocation-free rule: __device__ globals)
// ---------------------------------------------------------------------------
__device__ __align__(16) float g_x0 [NB * CIN * LL];              //  2 MB
__device__ __align__(16) float g_y0 [(size_t)GG * C0C];           // 64 MB
__device__ __align__(16) float g_xa [(size_t)GG * C0C];           // 64 MB (PV residual)
__device__ __align__(16) __nv_bfloat16 g_xah[(size_t)GG * C0C];   // 32 MB
__device__ __align__(16) __nv_bfloat16 g_xal[(size_t)GG * C0C];   // 32 MB
__device__ __align__(16) __nv_bfloat16 g_qkh[(size_t)GG * 64];    //  8 MB [g][q32|k32] hi
__device__ __align__(16) __nv_bfloat16 g_qkl[(size_t)GG * 64];    //  8 MB lo
__device__ __align__(16) float g_E  [(size_t)NB * LL * LL];       // 256 MB fp32 energies
__device__ __align__(16) __nv_bfloat16 g_Eh [(size_t)GG * LL];    // 128 MB softmax hi
__device__ __align__(16) __nv_bfloat16 g_El [(size_t)GG * LL];    // 128 MB softmax lo
__device__ __align__(16) __nv_bfloat16 g_vTh[(size_t)NB * C0C * LL]; // 32 MB V^T hi
__device__ __align__(16) __nv_bfloat16 g_vTl[(size_t)NB * C0C * LL]; // 32 MB V^T lo
__device__ __align__(16) __nv_bfloat16 g_atth[(size_t)GG * C0C];  // 32 MB att hi
__device__ __align__(16) __nv_bfloat16 g_attl[(size_t)GG * C0C];  // 32 MB att lo
__device__ __align__(16) float g_x1 [(size_t)GG * FFC];           // 16 MB
// split weights
__device__ __align__(16) __nv_bfloat16 g_wqkh[64 * C0C],  g_wqkl[64 * C0C];
__device__ __align__(16) __nv_bfloat16 g_wvh [C0C * C0C], g_wvl [C0C * C0C];
__device__ __align__(16) __nv_bfloat16 g_w1h [FFC * C0C], g_w1l [FFC * C0C];
__device__ __align__(16) float g_bqk[64];
__device__ float g_pS[C0C * 64];
__device__ float g_pQ[C0C * 64];
__device__ __align__(16) float g_scale0[C0C], g_shift0[C0C];
__device__ __align__(16) float g_scale1[FFC], g_shift1[FFC];

// ---------------------------------------------------------------------------
// PTX helpers (sm_80-level only — harness ptxas targets plain sm_100)
// ---------------------------------------------------------------------------
__device__ __forceinline__ unsigned smem_u32(const void* p) {
    unsigned a;
    asm("{ .reg .u64 t; cvta.to.shared.u64 t, %1; cvt.u32.u64 %0, t; }" : "=r"(a) : "l"(p));
    return a;
}
__device__ __forceinline__ void cpasync16(unsigned d, const void* s) {
    asm volatile("cp.async.cg.shared.global [%0], [%1], 16;" :: "r"(d), "l"(s));
}
#define CP_COMMIT() asm volatile("cp.async.commit_group;" ::: "memory")
#define CP_WAIT0()  asm volatile("cp.async.wait_group 0;" ::: "memory")
#define CP_WAIT1()  asm volatile("cp.async.wait_group 1;" ::: "memory")

__device__ __forceinline__ void ldsm_x4(unsigned& r0, unsigned& r1,
                                        unsigned& r2, unsigned& r3, unsigned addr) {
    asm volatile("ldmatrix.sync.aligned.m8n8.x4.shared.b16 {%0,%1,%2,%3}, [%4];"
                 : "=r"(r0), "=r"(r1), "=r"(r2), "=r"(r3) : "r"(addr));
}
__device__ __forceinline__ void mma_bf16(float* c, const unsigned* a, const unsigned* b) {
    asm volatile("mma.sync.aligned.m16n8k16.row.col.f32.bf16.bf16.f32 "
                 "{%0,%1,%2,%3}, {%4,%5,%6,%7}, {%8,%9}, {%0,%1,%2,%3};"
                 : "+f"(c[0]), "+f"(c[1]), "+f"(c[2]), "+f"(c[3])
                 : "r"(a[0]), "r"(a[1]), "r"(a[2]), "r"(a[3]), "r"(b[0]), "r"(b[1]));
}
__device__ __forceinline__ void bf16split(float v, __nv_bfloat16& h, __nv_bfloat16& l) {
    h = __float2bfloat16(v);
    l = __float2bfloat16(v - __bfloat162float(h));
}

// ---------------------------------------------------------------------------
// Generic split-bf16 MMA GEMM.
//   OUT_MODE 0: fp32 C (+bias)
//   OUT_MODE 1: bf16 hi/lo split C (+bias)
//   OUT_MODE 2: V-projection special: stage to smem, write TRANSPOSED bf16
//               hi/lo (vT[b][n][l]); grid.y encodes g-tile (b = m0>>10).
// A: [M,K] row-major bf16 hi/lo, B: [N,K] row-major bf16 hi/lo.
// BM=128, BN in {64,128}. Kc=32 per stage, cp.async double buffer.
// smem rows at 80B pitch (64B data) -> conflict-free ldmatrix.
// ---------------------------------------------------------------------------
template<int BN>
__device__ __forceinline__ void mm_load(unsigned dst, int t,
    const char* Ah, const char* Al, const char* Bh, const char* Bl,
    int ldaB, int ldbB, int m0, int n0, int kByte)
{
    constexpr int AOP = 128 * 80, BOP = BN * 80;
    constexpr int TCA = 1024, TC = TCA + BN * 8;
#pragma unroll
    for (int u = 0; u < TC / 256; u++) {
        int i = t + u * 256;
        if (i < TCA) {
            int half = i >> 9, row = (i >> 2) & 127, c = i & 3;
            const char* s = half ? Al : Ah;
            cpasync16(dst + half * AOP + row * 80 + c * 16,
                      s + (size_t)(m0 + row) * ldaB + kByte + c * 16);
        } else {
            int j = i - TCA;
            int half = j / (BN * 4), row = (j >> 2) % BN, c = j & 3;
            const char* s = half ? Bl : Bh;
            cpasync16(dst + 2 * AOP + half * BOP + row * 80 + c * 16,
                      s + (size_t)(n0 + row) * ldbB + kByte + c * 16);
        }
    }
}

template<int BN, int OUT_MODE>
__global__ __launch_bounds__(256, 1)
void mma_gemm(const __nv_bfloat16* __restrict__ Ah, const __nv_bfloat16* __restrict__ Al,
              int lda, long long sA,
              const __nv_bfloat16* __restrict__ Bh, const __nv_bfloat16* __restrict__ Bl,
              int ldb, long long sB,
              const float* __restrict__ bias,
              float* __restrict__ C,
              __nv_bfloat16* __restrict__ Ch, __nv_bfloat16* __restrict__ Cl,
              int ldc, long long sC, int K)
{
    constexpr int AOP = 128 * 80, BOP = BN * 80;
    constexpr int ST = 2 * AOP + 2 * BOP;
    constexpr int NW = BN / 4;
    constexpr int NI = NW / 8;
    constexpr int NGI = NW / 16;

    extern __shared__ char smem[];
    const unsigned sb = smem_u32(smem);
    const int t = threadIdx.x;
    const int n0 = blockIdx.x * BN, m0 = blockIdx.y * 128, z = blockIdx.z;

    const char* cAh = (const char*)(Ah + (size_t)z * sA);
    const char* cAl = (const char*)(Al + (size_t)z * sA);
    const char* cBh = (const char*)(Bh + (size_t)z * sB);
    const char* cBl = (const char*)(Bl + (size_t)z * sB);
    const int ldaB = lda * 2, ldbB = ldb * 2;

    const int w = t >> 5, lane = t & 31;
    const int wm = (w & 1) * 64, wn = (w >> 1) * NW;
    const int aRowSel = (lane & 7) + ((lane >> 3) & 1) * 8;
    const int aChunk  = (lane >> 4) * 16;
    const int bRowSel = (lane & 7) + (lane >> 4) * 8;
    const int bChunk  = ((lane >> 3) & 1) * 16;

    float acc[4][NI][4];
#pragma unroll
    for (int mi = 0; mi < 4; mi++)
#pragma unroll
        for (int ni = 0; ni < NI; ni++)
#pragma unroll
            for (int r = 0; r < 4; r++) acc[mi][ni][r] = 0.f;

    const int nst = K / 32;
    mm_load<BN>(sb, t, cAh, cAl, cBh, cBl, ldaB, ldbB, m0, n0, 0);
    CP_COMMIT();

    for (int s = 0; s < nst; s++) {
        if (s + 1 < nst) {
            mm_load<BN>(sb + ((s + 1) & 1) * ST, t, cAh, cAl, cBh, cBl,
                        ldaB, ldbB, m0, n0, (s + 1) * 64);
            CP_COMMIT();
            CP_WAIT1();
        } else {
            CP_WAIT0();
        }
        __syncthreads();

        const unsigned base = sb + (s & 1) * ST;
#pragma unroll
        for (int s2 = 0; s2 < 2; s2++) {
            unsigned ah[4][4], al[4][4];
#pragma unroll
            for (int mi = 0; mi < 4; mi++) {
                unsigned ar = base + (wm + mi * 16 + aRowSel) * 80 + s2 * 32 + aChunk;
                ldsm_x4(ah[mi][0], ah[mi][1], ah[mi][2], ah[mi][3], ar);
                ldsm_x4(al[mi][0], al[mi][1], al[mi][2], al[mi][3], ar + AOP);
            }
            unsigned bh[NI][2], bl[NI][2];
#pragma unroll
            for (int ngi = 0; ngi < NGI; ngi++) {
                unsigned br = base + 2 * AOP + (wn + ngi * 16 + bRowSel) * 80 + s2 * 32 + bChunk;
                unsigned r0, r1, r2, r3;
                ldsm_x4(r0, r1, r2, r3, br);
                bh[2 * ngi][0] = r0; bh[2 * ngi][1] = r1;
                bh[2 * ngi + 1][0] = r2; bh[2 * ngi + 1][1] = r3;
                ldsm_x4(r0, r1, r2, r3, br + BOP);
                bl[2 * ngi][0] = r0; bl[2 * ngi][1] = r1;
                bl[2 * ngi + 1][0] = r2; bl[2 * ngi + 1][1] = r3;
            }
#pragma unroll
            for (int mi = 0; mi < 4; mi++)
#pragma unroll
                for (int ni = 0; ni < NI; ni++) {
                    mma_bf16(acc[mi][ni], ah[mi], bh[ni]);
                    mma_bf16(acc[mi][ni], ah[mi], bl[ni]);
                    mma_bf16(acc[mi][ni], al[mi], bh[ni]);
                }
        }
        __syncthreads();
    }

    const int g = lane >> 2, tg = lane & 3;

    if (OUT_MODE == 2) {
        // V-transpose epilogue: stage acc+bias (128x128) to smem, write vT.
        float* Ss = (float*)smem;
#pragma unroll
        for (int mi = 0; mi < 4; mi++)
#pragma unroll
            for (int ni = 0; ni < NI; ni++) {
                int col = wn + ni * 8 + 2 * tg;
                float b0 = __ldg(bias + n0 + col), b1 = __ldg(bias + n0 + col + 1);
#pragma unroll
                for (int half = 0; half < 2; half++) {
                    int row = wm + mi * 16 + half * 8 + g;
                    Ss[row * 132 + col]     = acc[mi][ni][2 * half + 0] + b0;
                    Ss[row * 132 + col + 1] = acc[mi][ni][2 * half + 1] + b1;
                }
            }
        __syncthreads();
        const int nn = t >> 1, mh = t & 1;
        const int b = m0 >> 10, l0 = m0 & 1023;
        size_t ob = ((size_t)(b * 256 + n0 + nn)) * 1024 + l0 + mh * 64;
#pragma unroll 8
        for (int m = 0; m < 64; m += 2) {
            float v0 = Ss[(mh * 64 + m) * 132 + nn];
            float v1 = Ss[(mh * 64 + m + 1) * 132 + nn];
            __nv_bfloat16 h0, l0b, h1, l1b;
            bf16split(v0, h0, l0b); bf16split(v1, h1, l1b);
            *(__nv_bfloat162*)(Ch + ob + m) = __halves2bfloat162(h0, h1);
            *(__nv_bfloat162*)(Cl + ob + m) = __halves2bfloat162(l0b, l1b);
        }
        return;
    }

#pragma unroll
    for (int mi = 0; mi < 4; mi++) {
#pragma unroll
        for (int ni = 0; ni < NI; ni++) {
            int gr = m0 + wm + mi * 16 + g;
            int gc = n0 + wn + ni * 8 + 2 * tg;
            float b0 = 0.f, b1 = 0.f;
            if (bias) { b0 = __ldg(bias + gc); b1 = __ldg(bias + gc + 1); }
#pragma unroll
            for (int half = 0; half < 2; half++) {
                size_t idx = (size_t)z * sC + (size_t)(gr + half * 8) * ldc + gc;
                float v0 = acc[mi][ni][2 * half + 0] + b0;
                float v1 = acc[mi][ni][2 * half + 1] + b1;
                if (OUT_MODE == 1) {
                    __nv_bfloat16 h0, l0b, h1, l1b;
                    bf16split(v0, h0, l0b); bf16split(v1, h1, l1b);
                    *(__nv_bfloat162*)(Ch + idx) = __halves2bfloat162(h0, h1);
                    *(__nv_bfloat162*)(Cl + idx) = __halves2bfloat162(l0b, l1b);
                } else {
                    float2 o; o.x = v0; o.y = v1;
                    *(float2*)(C + idx) = o;
                }
            }
        }
    }
}

// ---------------------------------------------------------------------------
// SIMT SGEMM (only for tiny pre-linear), B stored [N,K] row-major
// ---------------------------------------------------------------------------
__global__ __launch_bounds__(256)
void sgemm_kernel(const float* __restrict__ A, const float* __restrict__ Bm,
                  const float* __restrict__ bias, float* __restrict__ C,
                  int M, int N, int K, int lda, int ldb, int ldc)
{
    __shared__ float As[8][128];
    __shared__ float Bs[8][128];

    const int tid = threadIdx.x;
    const int m0 = blockIdx.y * 128;
    const int n0 = blockIdx.x * 128;

    const int aRow = tid >> 1;
    const int aK   = (tid & 1) << 2;
    const int tr = (tid >> 4) << 3;
    const int tc = (tid & 15) << 3;

    const bool aOK = (m0 + aRow) < M;
    const bool bOK = (n0 + aRow) < N;
    const float* aPtr = A + (long long)(m0 + aRow) * lda + aK;
    const float* bPtr = Bm + (long long)(n0 + aRow) * ldb + aK;

    float acc[8][8];
#pragma unroll
    for (int i = 0; i < 8; i++)
#pragma unroll
        for (int j = 0; j < 8; j++) acc[i][j] = 0.f;

    float4 aReg = make_float4(0.f, 0.f, 0.f, 0.f);
    float4 bReg = make_float4(0.f, 0.f, 0.f, 0.f);
    if (aOK) aReg = *(const float4*)aPtr;
    if (bOK) bReg = *(const float4*)bPtr;

    for (int k0 = 0; k0 < K; k0 += 8) {
        As[aK + 0][aRow] = aReg.x; As[aK + 1][aRow] = aReg.y;
        As[aK + 2][aRow] = aReg.z; As[aK + 3][aRow] = aReg.w;
        Bs[aK + 0][aRow] = bReg.x; Bs[aK + 1][aRow] = bReg.y;
        Bs[aK + 2][aRow] = bReg.z; Bs[aK + 3][aRow] = bReg.w;
        __syncthreads();

        if (k0 + 8 < K) {
            aReg = make_float4(0.f, 0.f, 0.f, 0.f);
            bReg = make_float4(0.f, 0.f, 0.f, 0.f);
            if (aOK) aReg = *(const float4*)(aPtr + (k0 + 8));
            if (bOK) bReg = *(const float4*)(bPtr + (k0 + 8));
        }

#pragma unroll
        for (int kk = 0; kk < 8; kk++) {
            float ar[8], br[8];
            *(float4*)&ar[0] = *(const float4*)&As[kk][tr];
            *(float4*)&ar[4] = *(const float4*)&As[kk][tr + 4];
            *(float4*)&br[0] = *(const float4*)&Bs[kk][tc];
            *(float4*)&br[4] = *(const float4*)&Bs[kk][tc + 4];
#pragma unroll
            for (int i = 0; i < 8; i++)
#pragma unroll
                for (int j = 0; j < 8; j++)
                    acc[i][j] = fmaf(ar[i], br[j], acc[i][j]);
        }
        __syncthreads();
    }

#pragma unroll
    for (int i = 0; i < 8; i++) {
        int gm = m0 + tr + i;
        if (gm < M) {
#pragma unroll
            for (int j = 0; j < 8; j += 4) {
                int gn = n0 + tc + j;
                if (gn < N) {
                    float4 o;
                    o.x = acc[i][j]; o.y = acc[i][j + 1];
                    o.z = acc[i][j + 2]; o.w = acc[i][j + 3];
                    if (bias) {
                        o.x += __ldg(bias + gn);     o.y += __ldg(bias + gn + 1);
                        o.z += __ldg(bias + gn + 2); o.w += __ldg(bias + gn + 3);
                    }
                    *(float4*)(C + (long long)gm * ldc + gn) = o;
                }
            }
        }
    }
}

// ---------------------------------------------------------------------------
// Weight prep: split wq||wk, wv, w1 into bf16 hi/lo; merge bq||bk
// ---------------------------------------------------------------------------
__global__ void wprep_kernel(const float* __restrict__ wq, const float* __restrict__ wk,
                             const float* __restrict__ wv, const float* __restrict__ w1,
                             const float* __restrict__ bq, const float* __restrict__ bk,
                             float* __restrict__ bqk,
                             __nv_bfloat16* __restrict__ wqkh, __nv_bfloat16* __restrict__ wqkl,
                             __nv_bfloat16* __restrict__ wvh,  __nv_bfloat16* __restrict__ wvl,
                             __nv_bfloat16* __restrict__ w1h,  __nv_bfloat16* __restrict__ w1l)
{
    int i = blockIdx.x * 256 + threadIdx.x;
    if (i < 16384) {
        int n = i >> 8, k = i & 255;
        float v = (n < 32) ? wq[n * 256 + k] : wk[(n - 32) * 256 + k];
        __nv_bfloat16 h, l;
        bf16split(v, h, l);
        wqkh[i] = h; wqkl[i] = l;
    } else if (i < 81920) {
        int j = i - 16384;
        __nv_bfloat16 h, l;
        bf16split(wv[j], h, l);
        wvh[j] = h; wvl[j] = l;
    } else if (i < 98304) {
        int j = i - 81920;
        __nv_bfloat16 h, l;
        bf16split(w1[j], h, l);
        w1h[j] = h; w1l[j] = l;
    }
    if (i < 64) bqk[i] = (i < 32) ? bq[i] : bk[i - 32];
}

// ---------------------------------------------------------------------------
// conv0: y0[g][o] = b0[o] + sum_c w0[o][c] * x0[b][c][l]   (K = 8)
// ---------------------------------------------------------------------------
__global__ __launch_bounds__(256)
void conv0_kernel(const float* __restrict__ x0, const float* __restrict__ w0,
                  const float* __restrict__ b0, float* __restrict__ y0)
{
    __shared__ float ws[C0C * CIN];
    __shared__ float xs[CIN][16];
    const int t = threadIdx.x;
    for (int i = t; i < C0C * CIN; i += 256) ws[i] = w0[i];
    const int g0 = blockIdx.x * 16;
    const int b = g0 >> 10, l0 = g0 & 1023;
    if (t < 128) {
        int c = t >> 4, i = t & 15;
        xs[c][i] = x0[b * (CIN * LL) + c * LL + l0 + i];
    }
    __syncthreads();

    float wreg[CIN];
#pragma unroll
    for (int c = 0; c < CIN; c++) wreg[c] = ws[t * CIN + c];
    const float bb = __ldg(b0 + t);
#pragma unroll
    for (int i = 0; i < 16; i++) {
        float acc = bb;
#pragma unroll
        for (int c = 0; c < CIN; c++) acc = fmaf(wreg[c], xs[c][i], acc);
        y0[(size_t)(g0 + i) * C0C + t] = acc;
    }
}

// ---------------------------------------------------------------------------
// BN stats (deterministic two-stage) + apply (+ bf16 hi/lo emit)
// ---------------------------------------------------------------------------
__global__ __launch_bounds__(256)
void bnstats_partial(const float* __restrict__ y, int nch,
                     float* __restrict__ pS, float* __restrict__ pQ)
{
    const int chunk = blockIdx.x;
    const int group = blockIdx.y;
    const int t = threadIdx.x;
    const int warp = t >> 5, lane = t & 31;
    const int ch = group * 32 + lane;
    const long long base = (long long)chunk * 1024;

    float s = 0.f, q = 0.f;
    for (int r = warp; r < 1024; r += 8) {
        float v = y[(base + r) * nch + ch];
        s += v; q = fmaf(v, v, q);
    }
    __shared__ float ss[8][32], sq[8][32];
    ss[warp][lane] = s; sq[warp][lane] = q;
    __syncthreads();
    if (warp == 0) {
        float S = ss[0][lane], Q = sq[0][lane];
#pragma unroll
        for (int w = 1; w < 8; w++) { S += ss[w][lane]; Q += sq[w][lane]; }
        pS[ch * 64 + chunk] = S;
        pQ[ch * 64 + chunk] = Q;
    }
}

__global__ void bnfinalize(const float* __restrict__ pS, const float* __restrict__ pQ,
                           const float* __restrict__ g, const float* __restrict__ be,
                           float* __restrict__ scale, float* __restrict__ shift, int nch)
{
    int ch = blockIdx.x * blockDim.x + threadIdx.x;
    if (ch >= nch) return;
    float s0 = 0.f, s1 = 0.f, s2 = 0.f, s3 = 0.f;
    float q0 = 0.f, q1 = 0.f, q2 = 0.f, q3 = 0.f;
#pragma unroll
    for (int i = 0; i < 64; i += 4) {
        s0 += pS[ch * 64 + i];     q0 += pQ[ch * 64 + i];
        s1 += pS[ch * 64 + i + 1]; q1 += pQ[ch * 64 + i + 1];
        s2 += pS[ch * 64 + i + 2]; q2 += pQ[ch * 64 + i + 2];
        s3 += pS[ch * 64 + i + 3]; q3 += pQ[ch * 64 + i + 3];
    }
    float s = (s0 + s1) + (s2 + s3);
    float q = (q0 + q1) + (q2 + q3);
    const float inv = 1.f / 65536.f;
    float mean = s * inv;
    float var = q * inv - mean * mean;
    float sc = __ldg(g + ch) * rsqrtf(var + 1e-5f);
    scale[ch] = sc;
    shift[ch] = __ldg(be + ch) - mean * sc;
}

// BN apply + ReLU -> fp32 xa + bf16 hi/lo
__global__ __launch_bounds__(256)
void bnapply_relu(const float* __restrict__ y, const float* __restrict__ scale,
                  const float* __restrict__ shift, float* __restrict__ o,
                  __nv_bfloat16* __restrict__ oh, __nv_bfloat16* __restrict__ ol, int nch)
{
    long long i = ((long long)blockIdx.x * blockDim.x + threadIdx.x) * 4;
    float4 v = *(const float4*)(y + i);
    int ch = (int)(i & (nch - 1));
    float4 sc = *(const float4*)(scale + ch);
    float4 sh = *(const float4*)(shift + ch);
    v.x = fmaxf(fmaf(v.x, sc.x, sh.x), 0.f);
    v.y = fmaxf(fmaf(v.y, sc.y, sh.y), 0.f);
    v.z = fmaxf(fmaf(v.z, sc.z, sh.z), 0.f);
    v.w = fmaxf(fmaf(v.w, sc.w, sh.w), 0.f);
    *(float4*)(o + i) = v;
    __nv_bfloat16 h0, l0, h1, l1, h2, l2, h3, l3;
    bf16split(v.x, h0, l0); bf16split(v.y, h1, l1);
    bf16split(v.z, h2, l2); bf16split(v.w, h3, l3);
    *(__nv_bfloat162*)(oh + i)     = __halves2bfloat162(h0, h1);
    *(__nv_bfloat162*)(oh + i + 2) = __halves2bfloat162(h2, h3);
    *(__nv_bfloat162*)(ol + i)     = __halves2bfloat162(l0, l1);
    *(__nv_bfloat162*)(ol + i + 2) = __halves2bfloat162(l2, l3);
}

// ---------------------------------------------------------------------------
// Row softmax over 1024 elems; emits bf16 hi/lo split
// ---------------------------------------------------------------------------
__global__ __launch_bounds__(256)
void softmax_kernel(const float* __restrict__ E,
                    __nv_bfloat16* __restrict__ Eh, __nv_bfloat16* __restrict__ El)
{
    const long long row = blockIdx.x;
    const float4* rp = (const float4*)(E + row * 1024);
    const int t = threadIdx.x;
    float4 v = rp[t];

    float m = fmaxf(fmaxf(v.x, v.y), fmaxf(v.z, v.w));
#pragma unroll
    for (int o = 16; o; o >>= 1) m = fmaxf(m, __shfl_xor_sync(0xffffffffu, m, o));
    __shared__ float smax[8], ssum[8];
    const int warp = t >> 5, lane = t & 31;
    if (lane == 0) smax[warp] = m;
    __syncthreads();
    float bm = smax[0];
#pragma unroll
    for (int w = 1; w < 8; w++) bm = fmaxf(bm, smax[w]);

    v.x = __expf(v.x - bm); v.y = __expf(v.y - bm);
    v.z = __expf(v.z - bm); v.w = __expf(v.w - bm);
    float s = v.x + v.y + v.z + v.w;
#pragma unroll
    for (int o = 16; o; o >>= 1) s += __shfl_xor_sync(0xffffffffu, s, o);
    if (lane == 0) ssum[warp] = s;
    __syncthreads();
    float bs = ssum[0];
#pragma unroll
    for (int w = 1; w < 8; w++) bs += ssum[w];

    const float inv = 1.f / bs;
    v.x *= inv; v.y *= inv; v.z *= inv; v.w *= inv;

    __nv_bfloat16 h0, l0, h1, l1, h2, l2, h3, l3;
    bf16split(v.x, h0, l0); bf16split(v.y, h1, l1);
    bf16split(v.z, h2, l2); bf16split(v.w, h3, l3);
    size_t o = (size_t)row * 1024 + t * 4;
    *(__nv_bfloat162*)(Eh + o)     = __halves2bfloat162(h0, h1);
    *(__nv_bfloat162*)(Eh + o + 2) = __halves2bfloat162(h2, h3);
    *(__nv_bfloat162*)(El + o)     = __halves2bfloat162(l0, l1);
    *(__nv_bfloat162*)(El + o + 2) = __halves2bfloat162(l2, l3);
}

// ---------------------------------------------------------------------------
// PV mma.sync kernel: att = gamma * (P @ V) + resid, emits att as bf16 hi/lo
// ---------------------------------------------------------------------------
#define PV_OP_BYTES 10240
#define PV_STAGE_BYTES 40960
#define PV_SMEM (2 * PV_STAGE_BYTES)   // 81920

__device__ __forceinline__ void pv_load(unsigned dst, int t,
    const char* a0, const char* a1, const char* b0, const char* b1, int kByte)
{
#pragma unroll
    for (int u = 0; u < 8; u++) {
        int i = t + u * 256;
        int op = i >> 9, row = (i >> 2) & 127, c = i & 3;
        const char* s = (op == 0) ? a0 : (op == 1) ? a1 : (op == 2) ? b0 : b1;
        cpasync16(dst + op * PV_OP_BYTES + row * 80 + c * 16,
                  s + (size_t)row * 2048 + kByte + c * 16);
    }
}

__global__ __launch_bounds__(256, 1)
void pv_kernel(const __nv_bfloat16* __restrict__ Eh, const __nv_bfloat16* __restrict__ El,
               const __nv_bfloat16* __restrict__ vTh, const __nv_bfloat16* __restrict__ vTl,
               const float* __restrict__ resid, const float* __restrict__ gammaPtr,
               __nv_bfloat16* __restrict__ atth, __nv_bfloat16* __restrict__ attl)
{
    extern __shared__ char smem[];
    const unsigned sb = smem_u32(smem);
    const int t = threadIdx.x;
    const int m0 = blockIdx.x * 128, n0 = blockIdx.y * 128, b = blockIdx.z;

    const char* gAh = (const char*)Eh  + (size_t)(b * 1024 + m0) * 2048;
    const char* gAl = (const char*)El  + (size_t)(b * 1024 + m0) * 2048;
    const char* gBh = (const char*)vTh + (size_t)(b * 256 + n0) * 2048;
    const char* gBl = (const char*)vTl + (size_t)(b * 256 + n0) * 2048;

    const int w = t >> 5, lane = t & 31;
    const int wm = (w & 1) * 64, wn = (w >> 1) * 32;
    const int aRowSel = (lane & 7) + ((lane >> 3) & 1) * 8;
    const int aChunk  = (lane >> 4) * 16;
    const int bRowSel = (lane & 7) + (lane >> 4) * 8;
    const int bChunk  = ((lane >> 3) & 1) * 16;

    float acc[4][4][4];
#pragma unroll
    for (int mi = 0; mi < 4; mi++)
#pragma unroll
        for (int ni = 0; ni < 4; ni++)
#pragma unroll
            for (int r = 0; r < 4; r++) acc[mi][ni][r] = 0.f;

    pv_load(sb, t, gAh, gAl, gBh, gBl, 0);
    CP_COMMIT();

    for (int s = 0; s < 32; s++) {
        if (s + 1 < 32) {
            pv_load(sb + ((s + 1) & 1) * PV_STAGE_BYTES, t, gAh, gAl, gBh, gBl, (s + 1) * 64);
            CP_COMMIT();
            CP_WAIT1();
        } else {
            CP_WAIT0();
        }
        __syncthreads();

        const unsigned base = sb + (s & 1) * PV_STAGE_BYTES;
#pragma unroll
        for (int s2 = 0; s2 < 2; s2++) {
            unsigned ah[4][4], al[4][4];
#pragma unroll
            for (int mi = 0; mi < 4; mi++) {
                unsigned ar = base + (wm + mi * 16 + aRowSel) * 80 + s2 * 32 + aChunk;
                ldsm_x4(ah[mi][0], ah[mi][1], ah[mi][2], ah[mi][3], ar);
                ldsm_x4(al[mi][0], al[mi][1], al[mi][2], al[mi][3], ar + PV_OP_BYTES);
            }
            unsigned bh[4][2], bl[4][2];
#pragma unroll
            for (int ngi = 0; ngi < 2; ngi++) {
                unsigned br = base + 2 * PV_OP_BYTES + (wn + ngi * 16 + bRowSel) * 80 + s2 * 32 + bChunk;
                unsigned r0, r1, r2, r3;
                ldsm_x4(r0, r1, r2, r3, br);
                bh[2 * ngi][0] = r0; bh[2 * ngi][1] = r1;
                bh[2 * ngi + 1][0] = r2; bh[2 * ngi + 1][1] = r3;
                ldsm_x4(r0, r1, r2, r3, br + PV_OP_BYTES);
                bl[2 * ngi][0] = r0; bl[2 * ngi][1] = r1;
                bl[2 * ngi + 1][0] = r2; bl[2 * ngi + 1][1] = r3;
            }
#pragma unroll
            for (int mi = 0; mi < 4; mi++)
#pragma unroll
                for (int ni = 0; ni < 4; ni++) {
                    mma_bf16(acc[mi][ni], ah[mi], bh[ni]);
                    mma_bf16(acc[mi][ni], ah[mi], bl[ni]);
                    mma_bf16(acc[mi][ni], al[mi], bh[ni]);
                }
        }
        __syncthreads();
    }

    const float gam = __ldg(gammaPtr);
    const int g = lane >> 2, tg = lane & 3;
#pragma unroll
    for (int mi = 0; mi < 4; mi++) {
#pragma unroll
        for (int ni = 0; ni < 4; ni++) {
            int gr = b * 1024 + m0 + wm + mi * 16 + g;
            int gc = n0 + wn + ni * 8 + 2 * tg;
#pragma unroll
            for (int half = 0; half < 2; half++) {
                size_t idx = (size_t)(gr + half * 8) * 256 + gc;
                float2 r = *(const float2*)(resid + idx);
                float v0 = fmaf(gam, acc[mi][ni][2 * half + 0], r.x);
                float v1 = fmaf(gam, acc[mi][ni][2 * half + 1], r.y);
                __nv_bfloat16 h0, l0, h1, l1;
                bf16split(v0, h0, l0); bf16split(v1, h1, l1);
                *(__nv_bfloat162*)(atth + idx) = __halves2bfloat162(h0, h1);
                *(__nv_bfloat162*)(attl + idx) = __halves2bfloat162(l0, l1);
            }
        }
    }
}

// ---------------------------------------------------------------------------
// Final: out[b][cin][l] = b_out[cin] + sum_f w_out[cin][f] * relu(bn1(x1[g][f]))
// ---------------------------------------------------------------------------
__global__ __launch_bounds__(256)
void final_kernel(const float* __restrict__ x1,
                  const float* __restrict__ scale1, const float* __restrict__ shift1,
                  const float* __restrict__ w_out, const float* __restrict__ b_out,
                  float* __restrict__ out)
{
    __shared__ float xs[32][65];
    __shared__ float wsh[8][64];
    const int t = threadIdx.x;
    const int g0 = blockIdx.x * 32;

    for (int i = t; i < 32 * 64; i += 256) {
        int pos = i >> 6, f = i & 63;
        float v = x1[(size_t)(g0 + pos) * FFC + f];
        v = fmaf(v, __ldg(scale1 + f), __ldg(shift1 + f));
        xs[pos][f] = fmaxf(v, 0.f);
    }
    for (int i = t; i < 8 * 64; i += 256) wsh[i >> 6][i & 63] = w_out[i];
    __syncthreads();

    const int pos = t & 31, cin = t >> 5;
    float acc = __ldg(b_out + cin);
#pragma unroll
    for (int f = 0; f < 64; f++) acc = fmaf(wsh[cin][f], xs[pos][f], acc);

    const int b = g0 >> 10, l0 = g0 & 1023;
    out[b * (CIN * LL) + cin * LL + l0 + pos] = acc;
}

// ---------------------------------------------------------------------------
// Host launcher (graph-capturable: kernel launches only)
// ---------------------------------------------------------------------------
extern "C" void kernel_launch(void* const* d_in, const int* in_sizes, int n_in,
                              void* d_out, int out_size)
{
    const float* z     = (const float*)d_in[0];
    const float* w_pre = (const float*)d_in[1];
    const float* b_pre = (const float*)d_in[2];
    const float* w0    = (const float*)d_in[3];
    const float* b0    = (const float*)d_in[4];
    const float* g0    = (const float*)d_in[5];
    const float* be0   = (const float*)d_in[6];
    const float* wq    = (const float*)d_in[7];
    const float* bq    = (const float*)d_in[8];
    const float* wk    = (const float*)d_in[9];
    const float* bk    = (const float*)d_in[10];
    const float* wv    = (const float*)d_in[11];
    const float* bv    = (const float*)d_in[12];
    const float* gamma = (const float*)d_in[13];
    const float* w1    = (const float*)d_in[14];
    const float* b1    = (const float*)d_in[15];
    const float* g1    = (const float*)d_in[16];
    const float* be1   = (const float*)d_in[17];
    const float* w_out = (const float*)d_in[18];
    const float* b_out = (const float*)d_in[19];
    float* out = (float*)d_out;

    float *x0, *y0, *xa, *E, *x1, *pS, *pQ, *sc0, *sh0, *sc1, *sh1, *bqk;
    __nv_bfloat16 *xah, *xal, *qkh, *qkl, *Eh, *El, *vTh, *vTl, *atth, *attl;
    __nv_bfloat16 *wqkh, *wqkl, *wvh, *wvl, *w1h, *w1l;
    cudaGetSymbolAddress((void**)&x0,   g_x0);
    cudaGetSymbolAddress((void**)&y0,   g_y0);
    cudaGetSymbolAddress((void**)&xa,   g_xa);
    cudaGetSymbolAddress((void**)&xah,  g_xah);
    cudaGetSymbolAddress((void**)&xal,  g_xal);
    cudaGetSymbolAddress((void**)&qkh,  g_qkh);
    cudaGetSymbolAddress((void**)&qkl,  g_qkl);
    cudaGetSymbolAddress((void**)&E,    g_E);
    cudaGetSymbolAddress((void**)&Eh,   g_Eh);
    cudaGetSymbolAddress((void**)&El,   g_El);
    cudaGetSymbolAddress((void**)&vTh,  g_vTh);
    cudaGetSymbolAddress((void**)&vTl,  g_vTl);
    cudaGetSymbolAddress((void**)&atth, g_atth);
    cudaGetSymbolAddress((void**)&attl, g_attl);
    cudaGetSymbolAddress((void**)&x1,   g_x1);
    cudaGetSymbolAddress((void**)&pS,   g_pS);
    cudaGetSymbolAddress((void**)&pQ,   g_pQ);
    cudaGetSymbolAddress((void**)&sc0,  g_scale0);
    cudaGetSymbolAddress((void**)&sh0,  g_shift0);
    cudaGetSymbolAddress((void**)&sc1,  g_scale1);
    cudaGetSymbolAddress((void**)&sh1,  g_shift1);
    cudaGetSymbolAddress((void**)&wqkh, g_wqkh);
    cudaGetSymbolAddress((void**)&wqkl, g_wqkl);
    cudaGetSymbolAddress((void**)&wvh,  g_wvh);
    cudaGetSymbolAddress((void**)&wvl,  g_wvl);
    cudaGetSymbolAddress((void**)&w1h,  g_w1h);
    cudaGetSymbolAddress((void**)&w1l,  g_w1l);
    cudaGetSymbolAddress((void**)&bqk,  g_bqk);

    const int ST64  = 2 * (2 * 128 * 80 + 2 * 64 * 80);    // 61440
    const int ST128 = 2 * (2 * 128 * 80 + 2 * 128 * 80);   // 81920
    cudaFuncSetAttribute(pv_kernel, cudaFuncAttributeMaxDynamicSharedMemorySize, PV_SMEM);
    cudaFuncSetAttribute(mma_gemm<64, 0>,  cudaFuncAttributeMaxDynamicSharedMemorySize, ST64);
    cudaFuncSetAttribute(mma_gemm<64, 1>,  cudaFuncAttributeMaxDynamicSharedMemorySize, ST64);
    cudaFuncSetAttribute(mma_gemm<128, 0>, cudaFuncAttributeMaxDynamicSharedMemorySize, ST128);
    cudaFuncSetAttribute(mma_gemm<128, 2>, cudaFuncAttributeMaxDynamicSharedMemorySize, ST128);

    // 1) pre-linear: x0 = z @ w_pre^T + b_pre   [64 x 8192], K=128
    sgemm_kernel<<<dim3(8192 / 128, 1, 1), 256>>>(
        z, w_pre, b_pre, x0, NB, CIN * LL, ZD, ZD, ZD, CIN * LL);

    // 2) conv0 (K=8) -> y0 [g][256]; weight prep in parallel
    conv0_kernel<<<GG / 16, 256>>>(x0, w0, b0, y0);
    wprep_kernel<<<384, 256>>>(wq, wk, wv, w1, bq, bk, bqk,
                               wqkh, wqkl, wvh, wvl, w1h, w1l);

    // 3) BN0 stats + apply + relu -> xa fp32 + bf16 hi/lo
    bnstats_partial<<<dim3(64, C0C / 32), 256>>>(y0, C0C, pS, pQ);
    bnfinalize<<<1, 256>>>(pS, pQ, g0, be0, sc0, sh0, C0C);
    bnapply_relu<<<(GG * C0C) / (256 * 4), 256>>>(y0, sc0, sh0, xa, xah, xal, C0C);

    // 4) Q+K projection (split out): [g][64], K=256
    mma_gemm<64, 1><<<dim3(1, GG / 128, 1), 256, ST64>>>(
        xah, xal, C0C, 0, wqkh, wqkl, C0C, 0, bqk,
        nullptr, qkh, qkl, 64, 0, C0C);

    // 5) V projection with fused transpose -> vT bf16 hi/lo, K=256
    mma_gemm<128, 2><<<dim3(2, GG / 128, 1), 256, ST128>>>(
        xah, xal, C0C, 0, wvh, wvl, C0C, 0, bv,
        nullptr, vTh, vTl, 0, 0, C0C);

    // 6) energy: E[b] = Q[b] K[b]^T  (M=N=1024, K=32), batched over 64
    mma_gemm<128, 0><<<dim3(8, 8, NB), 256, ST128>>>(
        qkh, qkl, 64, (long long)LL * 64,
        qkh + 32, qkl + 32, 64, (long long)LL * 64,
        nullptr, E, nullptr, nullptr, LL, (long long)LL * LL, CQKC);

    // 7) row softmax -> bf16 hi/lo probabilities
    softmax_kernel<<<GG, 256>>>(E, Eh, El);

    // 8) att = gamma * (P @ V) + xa  -> bf16 hi/lo (mma.sync split)
    pv_kernel<<<dim3(8, 2, NB), 256, PV_SMEM>>>(Eh, El, vTh, vTl, xa, gamma, atth, attl);

    // 9) conv1: x1 = att @ w1^T + b1  [g][64], K=256
    mma_gemm<64, 0><<<dim3(1, GG / 128, 1), 256, ST64>>>(
        atth, attl, C0C, 0, w1h, w1l, C0C, 0, b1,
        x1, nullptr, nullptr, FFC, 0, C0C);

    // 10) BN1 stats
    bnstats_partial<<<dim3(64, FFC / 32), 256>>>(x1, FFC, pS, pQ);
    bnfinalize<<<1, 64>>>(pS, pQ, g1, be1, sc1, sh1, FFC);

    // 11) fused BN1 + relu + w_out conv -> out [b][8][1024]
    final_kernel<<<GG / 32, 256>>>(x1, sc1, sh1, w_out, b_out, out);

    (void)in_sizes; (void)n_in; (void)out_size;
}

// round 8
// speedup vs baseline: 1.0713x; 1.0713x over previous
#include <cuda_runtime.h>
#include <cuda_bf16.h>

// ---------------------------------------------------------------------------
// Problem constants
// ---------------------------------------------------------------------------
#define NB    64          // batch
#define ZD    128         // latent dim
#define CIN   8
#define LL    1024        // W*H
#define C0C   256         // attention channels
#define CQKC  32
#define FFC   64          // filters
#define GG    65536       // NB * LL (total positions)

// ---------------------------------------------------------------------------
// Device scratch (allocation-free rule: __device__ globals)
// ---------------------------------------------------------------------------
__device__ __align__(16) float g_x0 [NB * CIN * LL];              //  2 MB
__device__ __align__(16) float g_y0 [(size_t)GG * C0C];           // 64 MB
__device__ __align__(16) float g_xa [(size_t)GG * C0C];           // 64 MB (PV residual)
__device__ __align__(16) __nv_bfloat16 g_xah[(size_t)GG * C0C];   // 32 MB
__device__ __align__(16) __nv_bfloat16 g_xal[(size_t)GG * C0C];   // 32 MB
__device__ __align__(16) __nv_bfloat16 g_qkh[(size_t)GG * 64];    //  8 MB [g][q32|k32] hi
__device__ __align__(16) __nv_bfloat16 g_qkl[(size_t)GG * 64];    //  8 MB lo
__device__ __align__(16) float g_E  [(size_t)NB * LL * LL];       // 256 MB fp32 energies
__device__ __align__(16) __nv_bfloat16 g_Eh [(size_t)GG * LL];    // 128 MB softmax hi
__device__ __align__(16) __nv_bfloat16 g_El [(size_t)GG * LL];    // 128 MB softmax lo
__device__ __align__(16) __nv_bfloat16 g_vTh[(size_t)NB * C0C * LL]; // 32 MB V^T hi
__device__ __align__(16) __nv_bfloat16 g_vTl[(size_t)NB * C0C * LL]; // 32 MB V^T lo
__device__ __align__(16) __nv_bfloat16 g_atth[(size_t)GG * C0C];  // 32 MB att hi
__device__ __align__(16) __nv_bfloat16 g_attl[(size_t)GG * C0C];  // 32 MB att lo
__device__ __align__(16) float g_x1 [(size_t)GG * FFC];           // 16 MB
// split weights
__device__ __align__(16) __nv_bfloat16 g_wqkh[64 * C0C],  g_wqkl[64 * C0C];
__device__ __align__(16) __nv_bfloat16 g_wvh [C0C * C0C], g_wvl [C0C * C0C];
__device__ __align__(16) __nv_bfloat16 g_w1h [FFC * C0C], g_w1l [FFC * C0C];
__device__ __align__(16) float g_bqk[64];
__device__ float g_pS[C0C * 64];
__device__ float g_pQ[C0C * 64];
__device__ __align__(16) float g_scale0[C0C], g_shift0[C0C];
__device__ __align__(16) float g_scale1[FFC], g_shift1[FFC];

// ---------------------------------------------------------------------------
// PTX helpers (sm_80-level only — harness ptxas targets plain sm_100)
// ---------------------------------------------------------------------------
__device__ __forceinline__ unsigned smem_u32(const void* p) {
    unsigned a;
    asm("{ .reg .u64 t; cvta.to.shared.u64 t, %1; cvt.u32.u64 %0, t; }" : "=r"(a) : "l"(p));
    return a;
}
__device__ __forceinline__ void cpasync16(unsigned d, const void* s) {
    asm volatile("cp.async.cg.shared.global [%0], [%1], 16;" :: "r"(d), "l"(s));
}
#define CP_COMMIT() asm volatile("cp.async.commit_group;" ::: "memory")
#define CP_WAIT0()  asm volatile("cp.async.wait_group 0;" ::: "memory")
#define CP_WAIT1()  asm volatile("cp.async.wait_group 1;" ::: "memory")

__device__ __forceinline__ void ldsm_x4(unsigned& r0, unsigned& r1,
                                        unsigned& r2, unsigned& r3, unsigned addr) {
    asm volatile("ldmatrix.sync.aligned.m8n8.x4.shared.b16 {%0,%1,%2,%3}, [%4];"
                 : "=r"(r0), "=r"(r1), "=r"(r2), "=r"(r3) : "r"(addr));
}
__device__ __forceinline__ void mma_bf16(float* c, const unsigned* a, const unsigned* b) {
    asm volatile("mma.sync.aligned.m16n8k16.row.col.f32.bf16.bf16.f32 "
                 "{%0,%1,%2,%3}, {%4,%5,%6,%7}, {%8,%9}, {%0,%1,%2,%3};"
                 : "+f"(c[0]), "+f"(c[1]), "+f"(c[2]), "+f"(c[3])
                 : "r"(a[0]), "r"(a[1]), "r"(a[2]), "r"(a[3]), "r"(b[0]), "r"(b[1]));
}
__device__ __forceinline__ void bf16split(float v, __nv_bfloat16& h, __nv_bfloat16& l) {
    h = __float2bfloat16(v);
    l = __float2bfloat16(v - __bfloat162float(h));
}
__device__ __forceinline__ unsigned pack2(__nv_bfloat16 a, __nv_bfloat16 b) {
    return ((unsigned)__bfloat16_as_ushort(b) << 16) | __bfloat16_as_ushort(a);
}

// ---------------------------------------------------------------------------
// Generic split-bf16 MMA GEMM.
//   OUT_MODE 0: fp32 C (+bias)
//   OUT_MODE 1: bf16 hi/lo split C (+bias)
//   OUT_MODE 2: V-projection special: stage to smem, write TRANSPOSED bf16
//               hi/lo (vT[b][n][l]) with warp-per-row coalesced stores.
// A: [M,K] row-major bf16 hi/lo, B: [N,K] row-major bf16 hi/lo.
// BM=128, BN in {64,128}. Kc=32 per stage, cp.async double buffer.
// smem rows at 80B pitch (64B data) -> conflict-free ldmatrix.
// ---------------------------------------------------------------------------
template<int BN>
__device__ __forceinline__ void mm_load(unsigned dst, int t,
    const char* Ah, const char* Al, const char* Bh, const char* Bl,
    int ldaB, int ldbB, int m0, int n0, int kByte)
{
    constexpr int AOP = 128 * 80, BOP = BN * 80;
    constexpr int TCA = 1024, TC = TCA + BN * 8;
#pragma unroll
    for (int u = 0; u < TC / 256; u++) {
        int i = t + u * 256;
        if (i < TCA) {
            int half = i >> 9, row = (i >> 2) & 127, c = i & 3;
            const char* s = half ? Al : Ah;
            cpasync16(dst + half * AOP + row * 80 + c * 16,
                      s + (size_t)(m0 + row) * ldaB + kByte + c * 16);
        } else {
            int j = i - TCA;
            int half = j / (BN * 4), row = (j >> 2) % BN, c = j & 3;
            const char* s = half ? Bl : Bh;
            cpasync16(dst + 2 * AOP + half * BOP + row * 80 + c * 16,
                      s + (size_t)(n0 + row) * ldbB + kByte + c * 16);
        }
    }
}

template<int BN, int OUT_MODE>
__global__ __launch_bounds__(256, 1)
void mma_gemm(const __nv_bfloat16* __restrict__ Ah, const __nv_bfloat16* __restrict__ Al,
              int lda, long long sA,
              const __nv_bfloat16* __restrict__ Bh, const __nv_bfloat16* __restrict__ Bl,
              int ldb, long long sB,
              const float* __restrict__ bias,
              float* __restrict__ C,
              __nv_bfloat16* __restrict__ Ch, __nv_bfloat16* __restrict__ Cl,
              int ldc, long long sC, int K)
{
    constexpr int AOP = 128 * 80, BOP = BN * 80;
    constexpr int ST = 2 * AOP + 2 * BOP;
    constexpr int NW = BN / 4;
    constexpr int NI = NW / 8;
    constexpr int NGI = NW / 16;

    extern __shared__ char smem[];
    const unsigned sb = smem_u32(smem);
    const int t = threadIdx.x;
    const int n0 = blockIdx.x * BN, m0 = blockIdx.y * 128, z = blockIdx.z;

    const char* cAh = (const char*)(Ah + (size_t)z * sA);
    const char* cAl = (const char*)(Al + (size_t)z * sA);
    const char* cBh = (const char*)(Bh + (size_t)z * sB);
    const char* cBl = (const char*)(Bl + (size_t)z * sB);
    const int ldaB = lda * 2, ldbB = ldb * 2;

    const int w = t >> 5, lane = t & 31;
    const int wm = (w & 1) * 64, wn = (w >> 1) * NW;
    const int aRowSel = (lane & 7) + ((lane >> 3) & 1) * 8;
    const int aChunk  = (lane >> 4) * 16;
    const int bRowSel = (lane & 7) + (lane >> 4) * 8;
    const int bChunk  = ((lane >> 3) & 1) * 16;

    float acc[4][NI][4];
#pragma unroll
    for (int mi = 0; mi < 4; mi++)
#pragma unroll
        for (int ni = 0; ni < NI; ni++)
#pragma unroll
            for (int r = 0; r < 4; r++) acc[mi][ni][r] = 0.f;

    const int nst = K / 32;
    mm_load<BN>(sb, t, cAh, cAl, cBh, cBl, ldaB, ldbB, m0, n0, 0);
    CP_COMMIT();

    for (int s = 0; s < nst; s++) {
        if (s + 1 < nst) {
            mm_load<BN>(sb + ((s + 1) & 1) * ST, t, cAh, cAl, cBh, cBl,
                        ldaB, ldbB, m0, n0, (s + 1) * 64);
            CP_COMMIT();
            CP_WAIT1();
        } else {
            CP_WAIT0();
        }
        __syncthreads();

        const unsigned base = sb + (s & 1) * ST;
#pragma unroll
        for (int s2 = 0; s2 < 2; s2++) {
            unsigned ah[4][4], al[4][4];
#pragma unroll
            for (int mi = 0; mi < 4; mi++) {
                unsigned ar = base + (wm + mi * 16 + aRowSel) * 80 + s2 * 32 + aChunk;
                ldsm_x4(ah[mi][0], ah[mi][1], ah[mi][2], ah[mi][3], ar);
                ldsm_x4(al[mi][0], al[mi][1], al[mi][2], al[mi][3], ar + AOP);
            }
            unsigned bh[NI][2], bl[NI][2];
#pragma unroll
            for (int ngi = 0; ngi < NGI; ngi++) {
                unsigned br = base + 2 * AOP + (wn + ngi * 16 + bRowSel) * 80 + s2 * 32 + bChunk;
                unsigned r0, r1, r2, r3;
                ldsm_x4(r0, r1, r2, r3, br);
                bh[2 * ngi][0] = r0; bh[2 * ngi][1] = r1;
                bh[2 * ngi + 1][0] = r2; bh[2 * ngi + 1][1] = r3;
                ldsm_x4(r0, r1, r2, r3, br + BOP);
                bl[2 * ngi][0] = r0; bl[2 * ngi][1] = r1;
                bl[2 * ngi + 1][0] = r2; bl[2 * ngi + 1][1] = r3;
            }
#pragma unroll
            for (int mi = 0; mi < 4; mi++)
#pragma unroll
                for (int ni = 0; ni < NI; ni++) {
                    mma_bf16(acc[mi][ni], ah[mi], bh[ni]);
                    mma_bf16(acc[mi][ni], ah[mi], bl[ni]);
                    mma_bf16(acc[mi][ni], al[mi], bh[ni]);
                }
        }
        __syncthreads();
    }

    const int g = lane >> 2, tg = lane & 3;

    if (OUT_MODE == 2) {
        // V-transpose epilogue: stage acc+bias (128 m x 128 n) to smem, then
        // warp-per-output-row coalesced write of vT[b][n][l].
        float* Ss = (float*)smem;
#pragma unroll
        for (int mi = 0; mi < 4; mi++)
#pragma unroll
            for (int ni = 0; ni < NI; ni++) {
                int col = wn + ni * 8 + 2 * tg;
                float b0 = __ldg(bias + n0 + col), b1 = __ldg(bias + n0 + col + 1);
#pragma unroll
                for (int half = 0; half < 2; half++) {
                    int row = wm + mi * 16 + half * 8 + g;
                    Ss[row * 132 + col]     = acc[mi][ni][2 * half + 0] + b0;
                    Ss[row * 132 + col + 1] = acc[mi][ni][2 * half + 1] + b1;
                }
            }
        __syncthreads();
        // warp w handles n = w*16 + i; lane l writes m = 4l..4l+3 as one 8B
        // store per operand -> 256B contiguous per warp-store (fully coalesced)
        const int b = m0 >> 10, l0 = m0 & 1023;
        const int m = lane * 4;
#pragma unroll
        for (int i = 0; i < 16; i++) {
            int n = w * 16 + i;
            float v0 = Ss[(m + 0) * 132 + n];
            float v1 = Ss[(m + 1) * 132 + n];
            float v2 = Ss[(m + 2) * 132 + n];
            float v3 = Ss[(m + 3) * 132 + n];
            __nv_bfloat16 h0, lo0, h1, lo1, h2, lo2, h3, lo3;
            bf16split(v0, h0, lo0); bf16split(v1, h1, lo1);
            bf16split(v2, h2, lo2); bf16split(v3, h3, lo3);
            size_t ob = ((size_t)(b * 256 + n0 + n)) * 1024 + l0 + m;
            uint2 uh, ul;
            uh.x = pack2(h0, h1);  uh.y = pack2(h2, h3);
            ul.x = pack2(lo0, lo1); ul.y = pack2(lo2, lo3);
            *(uint2*)(Ch + ob) = uh;
            *(uint2*)(Cl + ob) = ul;
        }
        return;
    }

#pragma unroll
    for (int mi = 0; mi < 4; mi++) {
#pragma unroll
        for (int ni = 0; ni < NI; ni++) {
            int gr = m0 + wm + mi * 16 + g;
            int gc = n0 + wn + ni * 8 + 2 * tg;
            float b0 = 0.f, b1 = 0.f;
            if (bias) { b0 = __ldg(bias + gc); b1 = __ldg(bias + gc + 1); }
#pragma unroll
            for (int half = 0; half < 2; half++) {
                size_t idx = (size_t)z * sC + (size_t)(gr + half * 8) * ldc + gc;
                float v0 = acc[mi][ni][2 * half + 0] + b0;
                float v1 = acc[mi][ni][2 * half + 1] + b1;
                if (OUT_MODE == 1) {
                    __nv_bfloat16 h0, l0b, h1, l1b;
                    bf16split(v0, h0, l0b); bf16split(v1, h1, l1b);
                    *(__nv_bfloat162*)(Ch + idx) = __halves2bfloat162(h0, h1);
                    *(__nv_bfloat162*)(Cl + idx) = __halves2bfloat162(l0b, l1b);
                } else {
                    float2 o; o.x = v0; o.y = v1;
                    *(float2*)(C + idx) = o;
                }
            }
        }
    }
}

// ---------------------------------------------------------------------------
// SIMT SGEMM (only for tiny pre-linear), B stored [N,K] row-major
// ---------------------------------------------------------------------------
__global__ __launch_bounds__(256)
void sgemm_kernel(const float* __restrict__ A, const float* __restrict__ Bm,
                  const float* __restrict__ bias, float* __restrict__ C,
                  int M, int N, int K, int lda, int ldb, int ldc)
{
    __shared__ float As[8][128];
    __shared__ float Bs[8][128];

    const int tid = threadIdx.x;
    const int m0 = blockIdx.y * 128;
    const int n0 = blockIdx.x * 128;

    const int aRow = tid >> 1;
    const int aK   = (tid & 1) << 2;
    const int tr = (tid >> 4) << 3;
    const int tc = (tid & 15) << 3;

    const bool aOK = (m0 + aRow) < M;
    const bool bOK = (n0 + aRow) < N;
    const float* aPtr = A + (long long)(m0 + aRow) * lda + aK;
    const float* bPtr = Bm + (long long)(n0 + aRow) * ldb + aK;

    float acc[8][8];
#pragma unroll
    for (int i = 0; i < 8; i++)
#pragma unroll
        for (int j = 0; j < 8; j++) acc[i][j] = 0.f;

    float4 aReg = make_float4(0.f, 0.f, 0.f, 0.f);
    float4 bReg = make_float4(0.f, 0.f, 0.f, 0.f);
    if (aOK) aReg = *(const float4*)aPtr;
    if (bOK) bReg = *(const float4*)bPtr;

    for (int k0 = 0; k0 < K; k0 += 8) {
        As[aK + 0][aRow] = aReg.x; As[aK + 1][aRow] = aReg.y;
        As[aK + 2][aRow] = aReg.z; As[aK + 3][aRow] = aReg.w;
        Bs[aK + 0][aRow] = bReg.x; Bs[aK + 1][aRow] = bReg.y;
        Bs[aK + 2][aRow] = bReg.z; Bs[aK + 3][aRow] = bReg.w;
        __syncthreads();

        if (k0 + 8 < K) {
            aReg = make_float4(0.f, 0.f, 0.f, 0.f);
            bReg = make_float4(0.f, 0.f, 0.f, 0.f);
            if (aOK) aReg = *(const float4*)(aPtr + (k0 + 8));
            if (bOK) bReg = *(const float4*)(bPtr + (k0 + 8));
        }

#pragma unroll
        for (int kk = 0; kk < 8; kk++) {
            float ar[8], br[8];
            *(float4*)&ar[0] = *(const float4*)&As[kk][tr];
            *(float4*)&ar[4] = *(const float4*)&As[kk][tr + 4];
            *(float4*)&br[0] = *(const float4*)&Bs[kk][tc];
            *(float4*)&br[4] = *(const float4*)&Bs[kk][tc + 4];
#pragma unroll
            for (int i = 0; i < 8; i++)
#pragma unroll
                for (int j = 0; j < 8; j++)
                    acc[i][j] = fmaf(ar[i], br[j], acc[i][j]);
        }
        __syncthreads();
    }

#pragma unroll
    for (int i = 0; i < 8; i++) {
        int gm = m0 + tr + i;
        if (gm < M) {
#pragma unroll
            for (int j = 0; j < 8; j += 4) {
                int gn = n0 + tc + j;
                if (gn < N) {
                    float4 o;
                    o.x = acc[i][j]; o.y = acc[i][j + 1];
                    o.z = acc[i][j + 2]; o.w = acc[i][j + 3];
                    if (bias) {
                        o.x += __ldg(bias + gn);     o.y += __ldg(bias + gn + 1);
                        o.z += __ldg(bias + gn + 2); o.w += __ldg(bias + gn + 3);
                    }
                    *(float4*)(C + (long long)gm * ldc + gn) = o;
                }
            }
        }
    }
}

// ---------------------------------------------------------------------------
// Weight prep: split wq||wk, wv, w1 into bf16 hi/lo; merge bq||bk
// ---------------------------------------------------------------------------
__global__ void wprep_kernel(const float* __restrict__ wq, const float* __restrict__ wk,
                             const float* __restrict__ wv, const float* __restrict__ w1,
                             const float* __restrict__ bq, const float* __restrict__ bk,
                             float* __restrict__ bqk,
                             __nv_bfloat16* __restrict__ wqkh, __nv_bfloat16* __restrict__ wqkl,
                             __nv_bfloat16* __restrict__ wvh,  __nv_bfloat16* __restrict__ wvl,
                             __nv_bfloat16* __restrict__ w1h,  __nv_bfloat16* __restrict__ w1l)
{
    int i = blockIdx.x * 256 + threadIdx.x;
    if (i < 16384) {
        int n = i >> 8, k = i & 255;
        float v = (n < 32) ? wq[n * 256 + k] : wk[(n - 32) * 256 + k];
        __nv_bfloat16 h, l;
        bf16split(v, h, l);
        wqkh[i] = h; wqkl[i] = l;
    } else if (i < 81920) {
        int j = i - 16384;
        __nv_bfloat16 h, l;
        bf16split(wv[j], h, l);
        wvh[j] = h; wvl[j] = l;
    } else if (i < 98304) {
        int j = i - 81920;
        __nv_bfloat16 h, l;
        bf16split(w1[j], h, l);
        w1h[j] = h; w1l[j] = l;
    }
    if (i < 64) bqk[i] = (i < 32) ? bq[i] : bk[i - 32];
}

// ---------------------------------------------------------------------------
// conv0: y0[g][o] = b0[o] + sum_c w0[o][c] * x0[b][c][l]   (K = 8)
// ---------------------------------------------------------------------------
__global__ __launch_bounds__(256)
void conv0_kernel(const float* __restrict__ x0, const float* __restrict__ w0,
                  const float* __restrict__ b0, float* __restrict__ y0)
{
    __shared__ float ws[C0C * CIN];
    __shared__ float xs[CIN][16];
    const int t = threadIdx.x;
    for (int i = t; i < C0C * CIN; i += 256) ws[i] = w0[i];
    const int g0 = blockIdx.x * 16;
    const int b = g0 >> 10, l0 = g0 & 1023;
    if (t < 128) {
        int c = t >> 4, i = t & 15;
        xs[c][i] = x0[b * (CIN * LL) + c * LL + l0 + i];
    }
    __syncthreads();

    float wreg[CIN];
#pragma unroll
    for (int c = 0; c < CIN; c++) wreg[c] = ws[t * CIN + c];
    const float bb = __ldg(b0 + t);
#pragma unroll
    for (int i = 0; i < 16; i++) {
        float acc = bb;
#pragma unroll
        for (int c = 0; c < CIN; c++) acc = fmaf(wreg[c], xs[c][i], acc);
        y0[(size_t)(g0 + i) * C0C + t] = acc;
    }
}

// ---------------------------------------------------------------------------
// BN stats (deterministic two-stage) + apply (+ bf16 hi/lo emit)
// ---------------------------------------------------------------------------
__global__ __launch_bounds__(256)
void bnstats_partial(const float* __restrict__ y, int nch,
                     float* __restrict__ pS, float* __restrict__ pQ)
{
    const int chunk = blockIdx.x;
    const int group = blockIdx.y;
    const int t = threadIdx.x;
    const int warp = t >> 5, lane = t & 31;
    const int ch = group * 32 + lane;
    const long long base = (long long)chunk * 1024;

    float s = 0.f, q = 0.f;
    for (int r = warp; r < 1024; r += 8) {
        float v = y[(base + r) * nch + ch];
        s += v; q = fmaf(v, v, q);
    }
    __shared__ float ss[8][32], sq[8][32];
    ss[warp][lane] = s; sq[warp][lane] = q;
    __syncthreads();
    if (warp == 0) {
        float S = ss[0][lane], Q = sq[0][lane];
#pragma unroll
        for (int w = 1; w < 8; w++) { S += ss[w][lane]; Q += sq[w][lane]; }
        pS[ch * 64 + chunk] = S;
        pQ[ch * 64 + chunk] = Q;
    }
}

__global__ void bnfinalize(const float* __restrict__ pS, const float* __restrict__ pQ,
                           const float* __restrict__ g, const float* __restrict__ be,
                           float* __restrict__ scale, float* __restrict__ shift, int nch)
{
    int ch = blockIdx.x * blockDim.x + threadIdx.x;
    if (ch >= nch) return;
    float s0 = 0.f, s1 = 0.f, s2 = 0.f, s3 = 0.f;
    float q0 = 0.f, q1 = 0.f, q2 = 0.f, q3 = 0.f;
#pragma unroll
    for (int i = 0; i < 64; i += 4) {
        s0 += pS[ch * 64 + i];     q0 += pQ[ch * 64 + i];
        s1 += pS[ch * 64 + i + 1]; q1 += pQ[ch * 64 + i + 1];
        s2 += pS[ch * 64 + i + 2]; q2 += pQ[ch * 64 + i + 2];
        s3 += pS[ch * 64 + i + 3]; q3 += pQ[ch * 64 + i + 3];
    }
    float s = (s0 + s1) + (s2 + s3);
    float q = (q0 + q1) + (q2 + q3);
    const float inv = 1.f / 65536.f;
    float mean = s * inv;
    float var = q * inv - mean * mean;
    float sc = __ldg(g + ch) * rsqrtf(var + 1e-5f);
    scale[ch] = sc;
    shift[ch] = __ldg(be + ch) - mean * sc;
}

// BN apply + ReLU -> fp32 xa + bf16 hi/lo
__global__ __launch_bounds__(256)
void bnapply_relu(const float* __restrict__ y, const float* __restrict__ scale,
                  const float* __restrict__ shift, float* __restrict__ o,
                  __nv_bfloat16* __restrict__ oh, __nv_bfloat16* __restrict__ ol, int nch)
{
    long long i = ((long long)blockIdx.x * blockDim.x + threadIdx.x) * 4;
    float4 v = *(const float4*)(y + i);
    int ch = (int)(i & (nch - 1));
    float4 sc = *(const float4*)(scale + ch);
    float4 sh = *(const float4*)(shift + ch);
    v.x = fmaxf(fmaf(v.x, sc.x, sh.x), 0.f);
    v.y = fmaxf(fmaf(v.y, sc.y, sh.y), 0.f);
    v.z = fmaxf(fmaf(v.z, sc.z, sh.z), 0.f);
    v.w = fmaxf(fmaf(v.w, sc.w, sh.w), 0.f);
    *(float4*)(o + i) = v;
    __nv_bfloat16 h0, l0, h1, l1, h2, l2, h3, l3;
    bf16split(v.x, h0, l0); bf16split(v.y, h1, l1);
    bf16split(v.z, h2, l2); bf16split(v.w, h3, l3);
    *(__nv_bfloat162*)(oh + i)     = __halves2bfloat162(h0, h1);
    *(__nv_bfloat162*)(oh + i + 2) = __halves2bfloat162(h2, h3);
    *(__nv_bfloat162*)(ol + i)     = __halves2bfloat162(l0, l1);
    *(__nv_bfloat162*)(ol + i + 2) = __halves2bfloat162(l2, l3);
}

// ---------------------------------------------------------------------------
// Row softmax over 1024 elems; emits bf16 hi/lo split
// ---------------------------------------------------------------------------
__global__ __launch_bounds__(256)
void softmax_kernel(const float* __restrict__ E,
                    __nv_bfloat16* __restrict__ Eh, __nv_bfloat16* __restrict__ El)
{
    const long long row = blockIdx.x;
    const float4* rp = (const float4*)(E + row * 1024);
    const int t = threadIdx.x;
    float4 v = rp[t];

    float m = fmaxf(fmaxf(v.x, v.y), fmaxf(v.z, v.w));
#pragma unroll
    for (int o = 16; o; o >>= 1) m = fmaxf(m, __shfl_xor_sync(0xffffffffu, m, o));
    __shared__ float smax[8], ssum[8];
    const int warp = t >> 5, lane = t & 31;
    if (lane == 0) smax[warp] = m;
    __syncthreads();
    float bm = smax[0];
#pragma unroll
    for (int w = 1; w < 8; w++) bm = fmaxf(bm, smax[w]);

    v.x = __expf(v.x - bm); v.y = __expf(v.y - bm);
    v.z = __expf(v.z - bm); v.w = __expf(v.w - bm);
    float s = v.x + v.y + v.z + v.w;
#pragma unroll
    for (int o = 16; o; o >>= 1) s += __shfl_xor_sync(0xffffffffu, s, o);
    if (lane == 0) ssum[warp] = s;
    __syncthreads();
    float bs = ssum[0];
#pragma unroll
    for (int w = 1; w < 8; w++) bs += ssum[w];

    const float inv = 1.f / bs;
    v.x *= inv; v.y *= inv; v.z *= inv; v.w *= inv;

    __nv_bfloat16 h0, l0, h1, l1, h2, l2, h3, l3;
    bf16split(v.x, h0, l0); bf16split(v.y, h1, l1);
    bf16split(v.z, h2, l2); bf16split(v.w, h3, l3);
    size_t o = (size_t)row * 1024 + t * 4;
    *(__nv_bfloat162*)(Eh + o)     = __halves2bfloat162(h0, h1);
    *(__nv_bfloat162*)(Eh + o + 2) = __halves2bfloat162(h2, h3);
    *(__nv_bfloat162*)(El + o)     = __halves2bfloat162(l0, l1);
    *(__nv_bfloat162*)(El + o + 2) = __halves2bfloat162(l2, l3);
}

// ---------------------------------------------------------------------------
// PV mma.sync kernel: att = gamma * (P @ V) + resid, emits att as bf16 hi/lo
// ---------------------------------------------------------------------------
#define PV_OP_BYTES 10240
#define PV_STAGE_BYTES 40960
#define PV_SMEM (2 * PV_STAGE_BYTES)   // 81920

__device__ __forceinline__ void pv_load(unsigned dst, int t,
    const char* a0, const char* a1, const char* b0, const char* b1, int kByte)
{
#pragma unroll
    for (int u = 0; u < 8; u++) {
        int i = t + u * 256;
        int op = i >> 9, row = (i >> 2) & 127, c = i & 3;
        const char* s = (op == 0) ? a0 : (op == 1) ? a1 : (op == 2) ? b0 : b1;
        cpasync16(dst + op * PV_OP_BYTES + row * 80 + c * 16,
                  s + (size_t)row * 2048 + kByte + c * 16);
    }
}

__global__ __launch_bounds__(256, 1)
void pv_kernel(const __nv_bfloat16* __restrict__ Eh, const __nv_bfloat16* __restrict__ El,
               const __nv_bfloat16* __restrict__ vTh, const __nv_bfloat16* __restrict__ vTl,
               const float* __restrict__ resid, const float* __restrict__ gammaPtr,
               __nv_bfloat16* __restrict__ atth, __nv_bfloat16* __restrict__ attl)
{
    extern __shared__ char smem[];
    const unsigned sb = smem_u32(smem);
    const int t = threadIdx.x;
    const int m0 = blockIdx.x * 128, n0 = blockIdx.y * 128, b = blockIdx.z;

    const char* gAh = (const char*)Eh  + (size_t)(b * 1024 + m0) * 2048;
    const char* gAl = (const char*)El  + (size_t)(b * 1024 + m0) * 2048;
    const char* gBh = (const char*)vTh + (size_t)(b * 256 + n0) * 2048;
    const char* gBl = (const char*)vTl + (size_t)(b * 256 + n0) * 2048;

    const int w = t >> 5, lane = t & 31;
    const int wm = (w & 1) * 64, wn = (w >> 1) * 32;
    const int aRowSel = (lane & 7) + ((lane >> 3) & 1) * 8;
    const int aChunk  = (lane >> 4) * 16;
    const int bRowSel = (lane & 7) + (lane >> 4) * 8;
    const int bChunk  = ((lane >> 3) & 1) * 16;

    float acc[4][4][4];
#pragma unroll
    for (int mi = 0; mi < 4; mi++)
#pragma unroll
        for (int ni = 0; ni < 4; ni++)
#pragma unroll
            for (int r = 0; r < 4; r++) acc[mi][ni][r] = 0.f;

    pv_load(sb, t, gAh, gAl, gBh, gBl, 0);
    CP_COMMIT();

    for (int s = 0; s < 32; s++) {
        if (s + 1 < 32) {
            pv_load(sb + ((s + 1) & 1) * PV_STAGE_BYTES, t, gAh, gAl, gBh, gBl, (s + 1) * 64);
            CP_COMMIT();
            CP_WAIT1();
        } else {
            CP_WAIT0();
        }
        __syncthreads();

        const unsigned base = sb + (s & 1) * PV_STAGE_BYTES;
#pragma unroll
        for (int s2 = 0; s2 < 2; s2++) {
            unsigned ah[4][4], al[4][4];
#pragma unroll
            for (int mi = 0; mi < 4; mi++) {
                unsigned ar = base + (wm + mi * 16 + aRowSel) * 80 + s2 * 32 + aChunk;
                ldsm_x4(ah[mi][0], ah[mi][1], ah[mi][2], ah[mi][3], ar);
                ldsm_x4(al[mi][0], al[mi][1], al[mi][2], al[mi][3], ar + PV_OP_BYTES);
            }
            unsigned bh[4][2], bl[4][2];
#pragma unroll
            for (int ngi = 0; ngi < 2; ngi++) {
                unsigned br = base + 2 * PV_OP_BYTES + (wn + ngi * 16 + bRowSel) * 80 + s2 * 32 + bChunk;
                unsigned r0, r1, r2, r3;
                ldsm_x4(r0, r1, r2, r3, br);
                bh[2 * ngi][0] = r0; bh[2 * ngi][1] = r1;
                bh[2 * ngi + 1][0] = r2; bh[2 * ngi + 1][1] = r3;
                ldsm_x4(r0, r1, r2, r3, br + PV_OP_BYTES);
                bl[2 * ngi][0] = r0; bl[2 * ngi][1] = r1;
                bl[2 * ngi + 1][0] = r2; bl[2 * ngi + 1][1] = r3;
            }
#pragma unroll
            for (int mi = 0; mi < 4; mi++)
#pragma unroll
                for (int ni = 0; ni < 4; ni++) {
                    mma_bf16(acc[mi][ni], ah[mi], bh[ni]);
                    mma_bf16(acc[mi][ni], ah[mi], bl[ni]);
                    mma_bf16(acc[mi][ni], al[mi], bh[ni]);
                }
        }
        __syncthreads();
    }

    const float gam = __ldg(gammaPtr);
    const int g = lane >> 2, tg = lane & 3;
#pragma unroll
    for (int mi = 0; mi < 4; mi++) {
#pragma unroll
        for (int ni = 0; ni < 4; ni++) {
            int gr = b * 1024 + m0 + wm + mi * 16 + g;
            int gc = n0 + wn + ni * 8 + 2 * tg;
#pragma unroll
            for (int half = 0; half < 2; half++) {
                size_t idx = (size_t)(gr + half * 8) * 256 + gc;
                float2 r = *(const float2*)(resid + idx);
                float v0 = fmaf(gam, acc[mi][ni][2 * half + 0], r.x);
                float v1 = fmaf(gam, acc[mi][ni][2 * half + 1], r.y);
                __nv_bfloat16 h0, l0, h1, l1;
                bf16split(v0, h0, l0); bf16split(v1, h1, l1);
                *(__nv_bfloat162*)(atth + idx) = __halves2bfloat162(h0, h1);
                *(__nv_bfloat162*)(attl + idx) = __halves2bfloat162(l0, l1);
            }
        }
    }
}

// ---------------------------------------------------------------------------
// Final: out[b][cin][l] = b_out[cin] + sum_f w_out[cin][f] * relu(bn1(x1[g][f]))
// ---------------------------------------------------------------------------
__global__ __launch_bounds__(256)
void final_kernel(const float* __restrict__ x1,
                  const float* __restrict__ scale1, const float* __restrict__ shift1,
                  const float* __restrict__ w_out, const float* __restrict__ b_out,
                  float* __restrict__ out)
{
    __shared__ float xs[32][65];
    __shared__ float wsh[8][64];
    const int t = threadIdx.x;
    const int g0 = blockIdx.x * 32;

    for (int i = t; i < 32 * 64; i += 256) {
        int pos = i >> 6, f = i & 63;
        float v = x1[(size_t)(g0 + pos) * FFC + f];
        v = fmaf(v, __ldg(scale1 + f), __ldg(shift1 + f));
        xs[pos][f] = fmaxf(v, 0.f);
    }
    for (int i = t; i < 8 * 64; i += 256) wsh[i >> 6][i & 63] = w_out[i];
    __syncthreads();

    const int pos = t & 31, cin = t >> 5;
    float acc = __ldg(b_out + cin);
#pragma unroll
    for (int f = 0; f < 64; f++) acc = fmaf(wsh[cin][f], xs[pos][f], acc);

    const int b = g0 >> 10, l0 = g0 & 1023;
    out[b * (CIN * LL) + cin * LL + l0 + pos] = acc;
}

// ---------------------------------------------------------------------------
// Host launcher (graph-capturable: kernel launches only)
// ---------------------------------------------------------------------------
extern "C" void kernel_launch(void* const* d_in, const int* in_sizes, int n_in,
                              void* d_out, int out_size)
{
    const float* z     = (const float*)d_in[0];
    const float* w_pre = (const float*)d_in[1];
    const float* b_pre = (const float*)d_in[2];
    const float* w0    = (const float*)d_in[3];
    const float* b0    = (const float*)d_in[4];
    const float* g0    = (const float*)d_in[5];
    const float* be0   = (const float*)d_in[6];
    const float* wq    = (const float*)d_in[7];
    const float* bq    = (const float*)d_in[8];
    const float* wk    = (const float*)d_in[9];
    const float* bk    = (const float*)d_in[10];
    const float* wv    = (const float*)d_in[11];
    const float* bv    = (const float*)d_in[12];
    const float* gamma = (const float*)d_in[13];
    const float* w1    = (const float*)d_in[14];
    const float* b1    = (const float*)d_in[15];
    const float* g1    = (const float*)d_in[16];
    const float* be1   = (const float*)d_in[17];
    const float* w_out = (const float*)d_in[18];
    const float* b_out = (const float*)d_in[19];
    float* out = (float*)d_out;

    float *x0, *y0, *xa, *E, *x1, *pS, *pQ, *sc0, *sh0, *sc1, *sh1, *bqk;
    __nv_bfloat16 *xah, *xal, *qkh, *qkl, *Eh, *El, *vTh, *vTl, *atth, *attl;
    __nv_bfloat16 *wqkh, *wqkl, *wvh, *wvl, *w1h, *w1l;
    cudaGetSymbolAddress((void**)&x0,   g_x0);
    cudaGetSymbolAddress((void**)&y0,   g_y0);
    cudaGetSymbolAddress((void**)&xa,   g_xa);
    cudaGetSymbolAddress((void**)&xah,  g_xah);
    cudaGetSymbolAddress((void**)&xal,  g_xal);
    cudaGetSymbolAddress((void**)&qkh,  g_qkh);
    cudaGetSymbolAddress((void**)&qkl,  g_qkl);
    cudaGetSymbolAddress((void**)&E,    g_E);
    cudaGetSymbolAddress((void**)&Eh,   g_Eh);
    cudaGetSymbolAddress((void**)&El,   g_El);
    cudaGetSymbolAddress((void**)&vTh,  g_vTh);
    cudaGetSymbolAddress((void**)&vTl,  g_vTl);
    cudaGetSymbolAddress((void**)&atth, g_atth);
    cudaGetSymbolAddress((void**)&attl, g_attl);
    cudaGetSymbolAddress((void**)&x1,   g_x1);
    cudaGetSymbolAddress((void**)&pS,   g_pS);
    cudaGetSymbolAddress((void**)&pQ,   g_pQ);
    cudaGetSymbolAddress((void**)&sc0,  g_scale0);
    cudaGetSymbolAddress((void**)&sh0,  g_shift0);
    cudaGetSymbolAddress((void**)&sc1,  g_scale1);
    cudaGetSymbolAddress((void**)&sh1,  g_shift1);
    cudaGetSymbolAddress((void**)&wqkh, g_wqkh);
    cudaGetSymbolAddress((void**)&wqkl, g_wqkl);
    cudaGetSymbolAddress((void**)&wvh,  g_wvh);
    cudaGetSymbolAddress((void**)&wvl,  g_wvl);
    cudaGetSymbolAddress((void**)&w1h,  g_w1h);
    cudaGetSymbolAddress((void**)&w1l,  g_w1l);
    cudaGetSymbolAddress((void**)&bqk,  g_bqk);

    const int ST64  = 2 * (2 * 128 * 80 + 2 * 64 * 80);    // 61440
    const int ST128 = 2 * (2 * 128 * 80 + 2 * 128 * 80);   // 81920
    cudaFuncSetAttribute(pv_kernel, cudaFuncAttributeMaxDynamicSharedMemorySize, PV_SMEM);
    cudaFuncSetAttribute(mma_gemm<64, 0>,  cudaFuncAttributeMaxDynamicSharedMemorySize, ST64);
    cudaFuncSetAttribute(mma_gemm<64, 1>,  cudaFuncAttributeMaxDynamicSharedMemorySize, ST64);
    cudaFuncSetAttribute(mma_gemm<128, 0>, cudaFuncAttributeMaxDynamicSharedMemorySize, ST128);
    cudaFuncSetAttribute(mma_gemm<128, 2>, cudaFuncAttributeMaxDynamicSharedMemorySize, ST128);

    // 1) pre-linear: x0 = z @ w_pre^T + b_pre   [64 x 8192], K=128
    sgemm_kernel<<<dim3(8192 / 128, 1, 1), 256>>>(
        z, w_pre, b_pre, x0, NB, CIN * LL, ZD, ZD, ZD, CIN * LL);

    // 2) conv0 (K=8) -> y0 [g][256]; weight prep in parallel
    conv0_kernel<<<GG / 16, 256>>>(x0, w0, b0, y0);
    wprep_kernel<<<384, 256>>>(wq, wk, wv, w1, bq, bk, bqk,
                               wqkh, wqkl, wvh, wvl, w1h, w1l);

    // 3) BN0 stats + apply + relu -> xa fp32 + bf16 hi/lo
    bnstats_partial<<<dim3(64, C0C / 32), 256>>>(y0, C0C, pS, pQ);
    bnfinalize<<<1, 256>>>(pS, pQ, g0, be0, sc0, sh0, C0C);
    bnapply_relu<<<(GG * C0C) / (256 * 4), 256>>>(y0, sc0, sh0, xa, xah, xal, C0C);

    // 4) Q+K projection (split out): [g][64], K=256
    mma_gemm<64, 1><<<dim3(1, GG / 128, 1), 256, ST64>>>(
        xah, xal, C0C, 0, wqkh, wqkl, C0C, 0, bqk,
        nullptr, qkh, qkl, 64, 0, C0C);

    // 5) V projection with fused transpose (coalesced) -> vT bf16 hi/lo, K=256
    mma_gemm<128, 2><<<dim3(2, GG / 128, 1), 256, ST128>>>(
        xah, xal, C0C, 0, wvh, wvl, C0C, 0, bv,
        nullptr, vTh, vTl, 0, 0, C0C);

    // 6) energy: E[b] = Q[b] K[b]^T  (M=N=1024, K=32), batched over 64
    mma_gemm<128, 0><<<dim3(8, 8, NB), 256, ST128>>>(
        qkh, qkl, 64, (long long)LL * 64,
        qkh + 32, qkl + 32, 64, (long long)LL * 64,
        nullptr, E, nullptr, nullptr, LL, (long long)LL * LL, CQKC);

    // 7) row softmax -> bf16 hi/lo probabilities
    softmax_kernel<<<GG, 256>>>(E, Eh, El);

    // 8) att = gamma * (P @ V) + xa  -> bf16 hi/lo (mma.sync split)
    pv_kernel<<<dim3(8, 2, NB), 256, PV_SMEM>>>(Eh, El, vTh, vTl, xa, gamma, atth, attl);

    // 9) conv1: x1 = att @ w1^T + b1  [g][64], K=256
    mma_gemm<64, 0><<<dim3(1, GG / 128, 1), 256, ST64>>>(
        atth, attl, C0C, 0, w1h, w1l, C0C, 0, b1,
        x1, nullptr, nullptr, FFC, 0, C0C);

    // 10) BN1 stats
    bnstats_partial<<<dim3(64, FFC / 32), 256>>>(x1, FFC, pS, pQ);
    bnfinalize<<<1, 64>>>(pS, pQ, g1, be1, sc1, sh1, FFC);

    // 11) fused BN1 + relu + w_out conv -> out [b][8][1024]
    final_kernel<<<GG / 32, 256>>>(x1, sc1, sh1, w_out, b_out, out);

    (void)in_sizes; (void)n_in; (void)out_size;
}

// round 9
// speedup vs baseline: 1.1231x; 1.0484x over previous
#include <cuda_runtime.h>
#include <cuda_bf16.h>

// ---------------------------------------------------------------------------
// Problem constants
// ---------------------------------------------------------------------------
#define NB    64          // batch
#define ZD    128         // latent dim
#define CIN   8
#define LL    1024        // W*H
#define C0C   256         // attention channels
#define CQKC  32
#define FFC   64          // filters
#define GG    65536       // NB * LL (total positions)

// ---------------------------------------------------------------------------
// Device scratch (allocation-free rule: __device__ globals)
// ---------------------------------------------------------------------------
__device__ __align__(16) float g_x0 [NB * CIN * LL];              //  2 MB
__device__ __align__(16) __nv_bfloat16 g_xah[(size_t)GG * C0C];   // 32 MB
__device__ __align__(16) __nv_bfloat16 g_xal[(size_t)GG * C0C];   // 32 MB
__device__ __align__(16) __nv_bfloat16 g_qkh[(size_t)GG * 64];    //  8 MB [g][q32|k32] hi
__device__ __align__(16) __nv_bfloat16 g_qkl[(size_t)GG * 64];    //  8 MB lo
__device__ __align__(16) float g_E  [(size_t)NB * LL * LL];       // 256 MB fp32 energies
__device__ __align__(16) __nv_bfloat16 g_Eh [(size_t)GG * LL];    // 128 MB softmax hi
__device__ __align__(16) __nv_bfloat16 g_El [(size_t)GG * LL];    // 128 MB softmax lo
__device__ __align__(16) __nv_bfloat16 g_vTh[(size_t)NB * C0C * LL]; // 32 MB V^T hi
__device__ __align__(16) __nv_bfloat16 g_vTl[(size_t)NB * C0C * LL]; // 32 MB V^T lo
__device__ __align__(16) __nv_bfloat16 g_atth[(size_t)GG * C0C];  // 32 MB att hi
__device__ __align__(16) __nv_bfloat16 g_attl[(size_t)GG * C0C];  // 32 MB att lo
__device__ __align__(16) float g_x1 [(size_t)GG * FFC];           // 16 MB
// split weights
__device__ __align__(16) __nv_bfloat16 g_wqkh[64 * C0C],  g_wqkl[64 * C0C];
__device__ __align__(16) __nv_bfloat16 g_wvh [C0C * C0C], g_wvl [C0C * C0C];
__device__ __align__(16) __nv_bfloat16 g_w1h [FFC * C0C], g_w1l [FFC * C0C];
__device__ __align__(16) float g_bqk[64];
__device__ float g_pS[C0C * 64];           // reused: x0 moment partials [64][44]
__device__ float g_pQ[C0C * 64];
__device__ __align__(16) float g_scale0[C0C], g_shift0[C0C];
__device__ __align__(16) float g_scale1[FFC], g_shift1[FFC];

// ---------------------------------------------------------------------------
// PTX helpers (sm_80-level only — harness ptxas targets plain sm_100)
// ---------------------------------------------------------------------------
__device__ __forceinline__ unsigned smem_u32(const void* p) {
    unsigned a;
    asm("{ .reg .u64 t; cvta.to.shared.u64 t, %1; cvt.u32.u64 %0, t; }" : "=r"(a) : "l"(p));
    return a;
}
__device__ __forceinline__ void cpasync16(unsigned d, const void* s) {
    asm volatile("cp.async.cg.shared.global [%0], [%1], 16;" :: "r"(d), "l"(s));
}
#define CP_COMMIT() asm volatile("cp.async.commit_group;" ::: "memory")
#define CP_WAIT0()  asm volatile("cp.async.wait_group 0;" ::: "memory")
#define CP_WAIT1()  asm volatile("cp.async.wait_group 1;" ::: "memory")

__device__ __forceinline__ void ldsm_x4(unsigned& r0, unsigned& r1,
                                        unsigned& r2, unsigned& r3, unsigned addr) {
    asm volatile("ldmatrix.sync.aligned.m8n8.x4.shared.b16 {%0,%1,%2,%3}, [%4];"
                 : "=r"(r0), "=r"(r1), "=r"(r2), "=r"(r3) : "r"(addr));
}
__device__ __forceinline__ void mma_bf16(float* c, const unsigned* a, const unsigned* b) {
    asm volatile("mma.sync.aligned.m16n8k16.row.col.f32.bf16.bf16.f32 "
                 "{%0,%1,%2,%3}, {%4,%5,%6,%7}, {%8,%9}, {%0,%1,%2,%3};"
                 : "+f"(c[0]), "+f"(c[1]), "+f"(c[2]), "+f"(c[3])
                 : "r"(a[0]), "r"(a[1]), "r"(a[2]), "r"(a[3]), "r"(b[0]), "r"(b[1]));
}
__device__ __forceinline__ void bf16split(float v, __nv_bfloat16& h, __nv_bfloat16& l) {
    h = __float2bfloat16(v);
    l = __float2bfloat16(v - __bfloat162float(h));
}
__device__ __forceinline__ unsigned pack2(__nv_bfloat16 a, __nv_bfloat16 b) {
    return ((unsigned)__bfloat16_as_ushort(b) << 16) | __bfloat16_as_ushort(a);
}

// ---------------------------------------------------------------------------
// Generic split-bf16 MMA GEMM (unchanged R8 winner).
//   OUT_MODE 0: fp32 C (+bias)
//   OUT_MODE 1: bf16 hi/lo split C (+bias)
//   OUT_MODE 2: V-projection: stage to smem, coalesced transposed vT write.
// ---------------------------------------------------------------------------
template<int BN>
__device__ __forceinline__ void mm_load(unsigned dst, int t,
    const char* Ah, const char* Al, const char* Bh, const char* Bl,
    int ldaB, int ldbB, int m0, int n0, int kByte)
{
    constexpr int AOP = 128 * 80, BOP = BN * 80;
    constexpr int TCA = 1024, TC = TCA + BN * 8;
#pragma unroll
    for (int u = 0; u < TC / 256; u++) {
        int i = t + u * 256;
        if (i < TCA) {
            int half = i >> 9, row = (i >> 2) & 127, c = i & 3;
            const char* s = half ? Al : Ah;
            cpasync16(dst + half * AOP + row * 80 + c * 16,
                      s + (size_t)(m0 + row) * ldaB + kByte + c * 16);
        } else {
            int j = i - TCA;
            int half = j / (BN * 4), row = (j >> 2) % BN, c = j & 3;
            const char* s = half ? Bl : Bh;
            cpasync16(dst + 2 * AOP + half * BOP + row * 80 + c * 16,
                      s + (size_t)(n0 + row) * ldbB + kByte + c * 16);
        }
    }
}

template<int BN, int OUT_MODE>
__global__ __launch_bounds__(256, 1)
void mma_gemm(const __nv_bfloat16* __restrict__ Ah, const __nv_bfloat16* __restrict__ Al,
              int lda, long long sA,
              const __nv_bfloat16* __restrict__ Bh, const __nv_bfloat16* __restrict__ Bl,
              int ldb, long long sB,
              const float* __restrict__ bias,
              float* __restrict__ C,
              __nv_bfloat16* __restrict__ Ch, __nv_bfloat16* __restrict__ Cl,
              int ldc, long long sC, int K)
{
    constexpr int AOP = 128 * 80, BOP = BN * 80;
    constexpr int ST = 2 * AOP + 2 * BOP;
    constexpr int NW = BN / 4;
    constexpr int NI = NW / 8;
    constexpr int NGI = NW / 16;

    extern __shared__ char smem[];
    const unsigned sb = smem_u32(smem);
    const int t = threadIdx.x;
    const int n0 = blockIdx.x * BN, m0 = blockIdx.y * 128, z = blockIdx.z;

    const char* cAh = (const char*)(Ah + (size_t)z * sA);
    const char* cAl = (const char*)(Al + (size_t)z * sA);
    const char* cBh = (const char*)(Bh + (size_t)z * sB);
    const char* cBl = (const char*)(Bl + (size_t)z * sB);
    const int ldaB = lda * 2, ldbB = ldb * 2;

    const int w = t >> 5, lane = t & 31;
    const int wm = (w & 1) * 64, wn = (w >> 1) * NW;
    const int aRowSel = (lane & 7) + ((lane >> 3) & 1) * 8;
    const int aChunk  = (lane >> 4) * 16;
    const int bRowSel = (lane & 7) + (lane >> 4) * 8;
    const int bChunk  = ((lane >> 3) & 1) * 16;

    float acc[4][NI][4];
#pragma unroll
    for (int mi = 0; mi < 4; mi++)
#pragma unroll
        for (int ni = 0; ni < NI; ni++)
#pragma unroll
            for (int r = 0; r < 4; r++) acc[mi][ni][r] = 0.f;

    const int nst = K / 32;
    mm_load<BN>(sb, t, cAh, cAl, cBh, cBl, ldaB, ldbB, m0, n0, 0);
    CP_COMMIT();

    for (int s = 0; s < nst; s++) {
        if (s + 1 < nst) {
            mm_load<BN>(sb + ((s + 1) & 1) * ST, t, cAh, cAl, cBh, cBl,
                        ldaB, ldbB, m0, n0, (s + 1) * 64);
            CP_COMMIT();
            CP_WAIT1();
        } else {
            CP_WAIT0();
        }
        __syncthreads();

        const unsigned base = sb + (s & 1) * ST;
#pragma unroll
        for (int s2 = 0; s2 < 2; s2++) {
            unsigned ah[4][4], al[4][4];
#pragma unroll
            for (int mi = 0; mi < 4; mi++) {
                unsigned ar = base + (wm + mi * 16 + aRowSel) * 80 + s2 * 32 + aChunk;
                ldsm_x4(ah[mi][0], ah[mi][1], ah[mi][2], ah[mi][3], ar);
                ldsm_x4(al[mi][0], al[mi][1], al[mi][2], al[mi][3], ar + AOP);
            }
            unsigned bh[NI][2], bl[NI][2];
#pragma unroll
            for (int ngi = 0; ngi < NGI; ngi++) {
                unsigned br = base + 2 * AOP + (wn + ngi * 16 + bRowSel) * 80 + s2 * 32 + bChunk;
                unsigned r0, r1, r2, r3;
                ldsm_x4(r0, r1, r2, r3, br);
                bh[2 * ngi][0] = r0; bh[2 * ngi][1] = r1;
                bh[2 * ngi + 1][0] = r2; bh[2 * ngi + 1][1] = r3;
                ldsm_x4(r0, r1, r2, r3, br + BOP);
                bl[2 * ngi][0] = r0; bl[2 * ngi][1] = r1;
                bl[2 * ngi + 1][0] = r2; bl[2 * ngi + 1][1] = r3;
            }
#pragma unroll
            for (int mi = 0; mi < 4; mi++)
#pragma unroll
                for (int ni = 0; ni < NI; ni++) {
                    mma_bf16(acc[mi][ni], ah[mi], bh[ni]);
                    mma_bf16(acc[mi][ni], ah[mi], bl[ni]);
                    mma_bf16(acc[mi][ni], al[mi], bh[ni]);
                }
        }
        __syncthreads();
    }

    const int g = lane >> 2, tg = lane & 3;

    if (OUT_MODE == 2) {
        float* Ss = (float*)smem;
#pragma unroll
        for (int mi = 0; mi < 4; mi++)
#pragma unroll
            for (int ni = 0; ni < NI; ni++) {
                int col = wn + ni * 8 + 2 * tg;
                float b0 = __ldg(bias + n0 + col), b1 = __ldg(bias + n0 + col + 1);
#pragma unroll
                for (int half = 0; half < 2; half++) {
                    int row = wm + mi * 16 + half * 8 + g;
                    Ss[row * 132 + col]     = acc[mi][ni][2 * half + 0] + b0;
                    Ss[row * 132 + col + 1] = acc[mi][ni][2 * half + 1] + b1;
                }
            }
        __syncthreads();
        const int b = m0 >> 10, l0 = m0 & 1023;
        const int m = lane * 4;
#pragma unroll
        for (int i = 0; i < 16; i++) {
            int n = w * 16 + i;
            float v0 = Ss[(m + 0) * 132 + n];
            float v1 = Ss[(m + 1) * 132 + n];
            float v2 = Ss[(m + 2) * 132 + n];
            float v3 = Ss[(m + 3) * 132 + n];
            __nv_bfloat16 h0, lo0, h1, lo1, h2, lo2, h3, lo3;
            bf16split(v0, h0, lo0); bf16split(v1, h1, lo1);
            bf16split(v2, h2, lo2); bf16split(v3, h3, lo3);
            size_t ob = ((size_t)(b * 256 + n0 + n)) * 1024 + l0 + m;
            uint2 uh, ul;
            uh.x = pack2(h0, h1);  uh.y = pack2(h2, h3);
            ul.x = pack2(lo0, lo1); ul.y = pack2(lo2, lo3);
            *(uint2*)(Ch + ob) = uh;
            *(uint2*)(Cl + ob) = ul;
        }
        return;
    }

#pragma unroll
    for (int mi = 0; mi < 4; mi++) {
#pragma unroll
        for (int ni = 0; ni < NI; ni++) {
            int gr = m0 + wm + mi * 16 + g;
            int gc = n0 + wn + ni * 8 + 2 * tg;
            float b0 = 0.f, b1 = 0.f;
            if (bias) { b0 = __ldg(bias + gc); b1 = __ldg(bias + gc + 1); }
#pragma unroll
            for (int half = 0; half < 2; half++) {
                size_t idx = (size_t)z * sC + (size_t)(gr + half * 8) * ldc + gc;
                float v0 = acc[mi][ni][2 * half + 0] + b0;
                float v1 = acc[mi][ni][2 * half + 1] + b1;
                if (OUT_MODE == 1) {
                    __nv_bfloat16 h0, l0b, h1, l1b;
                    bf16split(v0, h0, l0b); bf16split(v1, h1, l1b);
                    *(__nv_bfloat162*)(Ch + idx) = __halves2bfloat162(h0, h1);
                    *(__nv_bfloat162*)(Cl + idx) = __halves2bfloat162(l0b, l1b);
                } else {
                    float2 o; o.x = v0; o.y = v1;
                    *(float2*)(C + idx) = o;
                }
            }
        }
    }
}

// ---------------------------------------------------------------------------
// SIMT SGEMM (only for tiny pre-linear), B stored [N,K] row-major
// ---------------------------------------------------------------------------
__global__ __launch_bounds__(256)
void sgemm_kernel(const float* __restrict__ A, const float* __restrict__ Bm,
                  const float* __restrict__ bias, float* __restrict__ C,
                  int M, int N, int K, int lda, int ldb, int ldc)
{
    __shared__ float As[8][128];
    __shared__ float Bs[8][128];

    const int tid = threadIdx.x;
    const int m0 = blockIdx.y * 128;
    const int n0 = blockIdx.x * 128;

    const int aRow = tid >> 1;
    const int aK   = (tid & 1) << 2;
    const int tr = (tid >> 4) << 3;
    const int tc = (tid & 15) << 3;

    const bool aOK = (m0 + aRow) < M;
    const bool bOK = (n0 + aRow) < N;
    const float* aPtr = A + (long long)(m0 + aRow) * lda + aK;
    const float* bPtr = Bm + (long long)(n0 + aRow) * ldb + aK;

    float acc[8][8];
#pragma unroll
    for (int i = 0; i < 8; i++)
#pragma unroll
        for (int j = 0; j < 8; j++) acc[i][j] = 0.f;

    float4 aReg = make_float4(0.f, 0.f, 0.f, 0.f);
    float4 bReg = make_float4(0.f, 0.f, 0.f, 0.f);
    if (aOK) aReg = *(const float4*)aPtr;
    if (bOK) bReg = *(const float4*)bPtr;

    for (int k0 = 0; k0 < K; k0 += 8) {
        As[aK + 0][aRow] = aReg.x; As[aK + 1][aRow] = aReg.y;
        As[aK + 2][aRow] = aReg.z; As[aK + 3][aRow] = aReg.w;
        Bs[aK + 0][aRow] = bReg.x; Bs[aK + 1][aRow] = bReg.y;
        Bs[aK + 2][aRow] = bReg.z; Bs[aK + 3][aRow] = bReg.w;
        __syncthreads();

        if (k0 + 8 < K) {
            aReg = make_float4(0.f, 0.f, 0.f, 0.f);
            bReg = make_float4(0.f, 0.f, 0.f, 0.f);
            if (aOK) aReg = *(const float4*)(aPtr + (k0 + 8));
            if (bOK) bReg = *(const float4*)(bPtr + (k0 + 8));
        }

#pragma unroll
        for (int kk = 0; kk < 8; kk++) {
            float ar[8], br[8];
            *(float4*)&ar[0] = *(const float4*)&As[kk][tr];
            *(float4*)&ar[4] = *(const float4*)&As[kk][tr + 4];
            *(float4*)&br[0] = *(const float4*)&Bs[kk][tc];
            *(float4*)&br[4] = *(const float4*)&Bs[kk][tc + 4];
#pragma unroll
            for (int i = 0; i < 8; i++)
#pragma unroll
                for (int j = 0; j < 8; j++)
                    acc[i][j] = fmaf(ar[i], br[j], acc[i][j]);
        }
        __syncthreads();
    }

#pragma unroll
    for (int i = 0; i < 8; i++) {
        int gm = m0 + tr + i;
        if (gm < M) {
#pragma unroll
            for (int j = 0; j < 8; j += 4) {
                int gn = n0 + tc + j;
                if (gn < N) {
                    float4 o;
                    o.x = acc[i][j]; o.y = acc[i][j + 1];
                    o.z = acc[i][j + 2]; o.w = acc[i][j + 3];
                    if (bias) {
                        o.x += __ldg(bias + gn);     o.y += __ldg(bias + gn + 1);
                        o.z += __ldg(bias + gn + 2); o.w += __ldg(bias + gn + 3);
                    }
                    *(float4*)(C + (long long)gm * ldc + gn) = o;
                }
            }
        }
    }
}

// ---------------------------------------------------------------------------
// Weight prep: split wq||wk, wv, w1 into bf16 hi/lo; merge bq||bk
// ---------------------------------------------------------------------------
__global__ void wprep_kernel(const float* __restrict__ wq, const float* __restrict__ wk,
                             const float* __restrict__ wv, const float* __restrict__ w1,
                             const float* __restrict__ bq, const float* __restrict__ bk,
                             float* __restrict__ bqk,
                             __nv_bfloat16* __restrict__ wqkh, __nv_bfloat16* __restrict__ wqkl,
                             __nv_bfloat16* __restrict__ wvh,  __nv_bfloat16* __restrict__ wvl,
                             __nv_bfloat16* __restrict__ w1h,  __nv_bfloat16* __restrict__ w1l)
{
    int i = blockIdx.x * 256 + threadIdx.x;
    if (i < 16384) {
        int n = i >> 8, k = i & 255;
        float v = (n < 32) ? wq[n * 256 + k] : wk[(n - 32) * 256 + k];
        __nv_bfloat16 h, l;
        bf16split(v, h, l);
        wqkh[i] = h; wqkl[i] = l;
    } else if (i < 81920) {
        int j = i - 16384;
        __nv_bfloat16 h, l;
        bf16split(wv[j], h, l);
        wvh[j] = h; wvl[j] = l;
    } else if (i < 98304) {
        int j = i - 81920;
        __nv_bfloat16 h, l;
        bf16split(w1[j], h, l);
        w1h[j] = h; w1l[j] = l;
    }
    if (i < 64) bqk[i] = (i < 32) ? bq[i] : bk[i - 32];
}

// ---------------------------------------------------------------------------
// x0 moment stats: per-batch partial sums of x_c and x_c1*x_c2 (8 + 36 vals).
// grid = 64 (one per batch image), block = 256. Deterministic shuffle+fixed-
// order reduction. Partials -> pX[b*44 + j].
// ---------------------------------------------------------------------------
__global__ __launch_bounds__(256)
void xstats_partial(const float* __restrict__ x0, float* __restrict__ pX)
{
    const int b = blockIdx.x, t = threadIdx.x;
    const int warp = t >> 5, lane = t & 31;
    float a[44];
#pragma unroll
    for (int j = 0; j < 44; j++) a[j] = 0.f;

#pragma unroll
    for (int r = 0; r < 4; r++) {
        int l = t + r * 256;
        float v[CIN];
#pragma unroll
        for (int c = 0; c < CIN; c++)
            v[c] = x0[b * (CIN * LL) + c * LL + l];
#pragma unroll
        for (int c = 0; c < CIN; c++) a[c] += v[c];
        int idx = CIN;
#pragma unroll
        for (int c1 = 0; c1 < CIN; c1++)
#pragma unroll
            for (int c2 = c1; c2 < CIN; c2++)
                a[idx++] = fmaf(v[c1], v[c2], a[idx]);
    }
    // warp reduce (deterministic xor tree)
#pragma unroll
    for (int j = 0; j < 44; j++)
#pragma unroll
        for (int o = 16; o; o >>= 1)
            a[j] += __shfl_xor_sync(0xffffffffu, a[j], o);

    __shared__ float ws[8][44];
    if (lane == 0)
#pragma unroll
        for (int j = 0; j < 44; j++) ws[warp][j] = a[j];
    __syncthreads();
    if (t < 44) {
        float s = ws[0][t];
#pragma unroll
        for (int w = 1; w < 8; w++) s += ws[w][t];
        pX[b * 44 + t] = s;
    }
}

// Finalize: moments -> analytic BN0 scale/shift per output channel.
// mean_o = W_o . mu + b_o ; var_o = W_o^T Cov W_o (Cov from moments).
__global__ void xstats_final(const float* __restrict__ pX,
                             const float* __restrict__ w0, const float* __restrict__ b0,
                             const float* __restrict__ g0, const float* __restrict__ be0,
                             float* __restrict__ scale, float* __restrict__ shift)
{
    __shared__ float mom[44];
    __shared__ float mu[CIN];
    __shared__ float cov[CIN][CIN];
    const int t = threadIdx.x;
    if (t < 44) {
        float s = 0.f;
        for (int b = 0; b < 64; b++) s += pX[b * 44 + t];
        mom[t] = s;
    }
    __syncthreads();
    if (t == 0) {
        const float inv = 1.f / 65536.f;
        for (int c = 0; c < CIN; c++) mu[c] = mom[c] * inv;
        int idx = CIN;
        for (int c1 = 0; c1 < CIN; c1++)
            for (int c2 = c1; c2 < CIN; c2++) {
                float cv = mom[idx++] * inv - mu[c1] * mu[c2];
                cov[c1][c2] = cv; cov[c2][c1] = cv;
            }
    }
    __syncthreads();
    // t = output channel (256)
    float w[CIN];
#pragma unroll
    for (int c = 0; c < CIN; c++) w[c] = w0[t * CIN + c];
    float mean = __ldg(b0 + t);
#pragma unroll
    for (int c = 0; c < CIN; c++) mean = fmaf(w[c], mu[c], mean);
    float var = 0.f;
#pragma unroll
    for (int c1 = 0; c1 < CIN; c1++) {
        float acc = 0.f;
#pragma unroll
        for (int c2 = 0; c2 < CIN; c2++) acc = fmaf(w[c2], cov[c1][c2], acc);
        var = fmaf(w[c1], acc, var);
    }
    float sc = __ldg(g0 + t) * rsqrtf(var + 1e-5f);
    scale[t] = sc;
    shift[t] = __ldg(be0 + t) - mean * sc;
}

// ---------------------------------------------------------------------------
// Fused conv0 + BN0 + ReLU + bf16 split:
// xa[g][o] = relu((b0 + sum_c w0[o][c] x0[b][c][l]) * sc0[o] + sh0[o])
// emits xah/xal only (no fp32 intermediate). 16 positions per block.
// ---------------------------------------------------------------------------
__global__ __launch_bounds__(256)
void conv0_fused(const float* __restrict__ x0, const float* __restrict__ w0,
                 const float* __restrict__ b0,
                 const float* __restrict__ sc0, const float* __restrict__ sh0,
                 __nv_bfloat16* __restrict__ xah, __nv_bfloat16* __restrict__ xal)
{
    __shared__ float ws[C0C * CIN];
    __shared__ float xs[CIN][16];
    const int t = threadIdx.x;
    for (int i = t; i < C0C * CIN; i += 256) ws[i] = w0[i];
    const int g0 = blockIdx.x * 16;
    const int b = g0 >> 10, l0 = g0 & 1023;
    if (t < 128) {
        int c = t >> 4, i = t & 15;
        xs[c][i] = x0[b * (CIN * LL) + c * LL + l0 + i];
    }
    __syncthreads();

    float wreg[CIN];
#pragma unroll
    for (int c = 0; c < CIN; c++) wreg[c] = ws[t * CIN + c];
    const float bb = __ldg(b0 + t);
    const float sc = __ldg(sc0 + t), sh = __ldg(sh0 + t);
#pragma unroll
    for (int i = 0; i < 16; i++) {
        float acc = bb;
#pragma unroll
        for (int c = 0; c < CIN; c++) acc = fmaf(wreg[c], xs[c][i], acc);
        float v = fmaxf(fmaf(acc, sc, sh), 0.f);
        __nv_bfloat16 h, l;
        bf16split(v, h, l);
        size_t o = (size_t)(g0 + i) * C0C + t;
        xah[o] = h; xal[o] = l;
    }
}

// ---------------------------------------------------------------------------
// BN stats (deterministic two-stage) — used for BN1 only
// ---------------------------------------------------------------------------
__global__ __launch_bounds__(256)
void bnstats_partial(const float* __restrict__ y, int nch,
                     float* __restrict__ pS, float* __restrict__ pQ)
{
    const int chunk = blockIdx.x;
    const int group = blockIdx.y;
    const int t = threadIdx.x;
    const int warp = t >> 5, lane = t & 31;
    const int ch = group * 32 + lane;
    const long long base = (long long)chunk * 1024;

    float s = 0.f, q = 0.f;
    for (int r = warp; r < 1024; r += 8) {
        float v = y[(base + r) * nch + ch];
        s += v; q = fmaf(v, v, q);
    }
    __shared__ float ss[8][32], sq[8][32];
    ss[warp][lane] = s; sq[warp][lane] = q;
    __syncthreads();
    if (warp == 0) {
        float S = ss[0][lane], Q = sq[0][lane];
#pragma unroll
        for (int w = 1; w < 8; w++) { S += ss[w][lane]; Q += sq[w][lane]; }
        pS[ch * 64 + chunk] = S;
        pQ[ch * 64 + chunk] = Q;
    }
}

__global__ void bnfinalize(const float* __restrict__ pS, const float* __restrict__ pQ,
                           const float* __restrict__ g, const float* __restrict__ be,
                           float* __restrict__ scale, float* __restrict__ shift, int nch)
{
    int ch = blockIdx.x * blockDim.x + threadIdx.x;
    if (ch >= nch) return;
    float s0 = 0.f, s1 = 0.f, s2 = 0.f, s3 = 0.f;
    float q0 = 0.f, q1 = 0.f, q2 = 0.f, q3 = 0.f;
#pragma unroll
    for (int i = 0; i < 64; i += 4) {
        s0 += pS[ch * 64 + i];     q0 += pQ[ch * 64 + i];
        s1 += pS[ch * 64 + i + 1]; q1 += pQ[ch * 64 + i + 1];
        s2 += pS[ch * 64 + i + 2]; q2 += pQ[ch * 64 + i + 2];
        s3 += pS[ch * 64 + i + 3]; q3 += pQ[ch * 64 + i + 3];
    }
    float s = (s0 + s1) + (s2 + s3);
    float q = (q0 + q1) + (q2 + q3);
    const float inv = 1.f / 65536.f;
    float mean = s * inv;
    float var = q * inv - mean * mean;
    float sc = __ldg(g + ch) * rsqrtf(var + 1e-5f);
    scale[ch] = sc;
    shift[ch] = __ldg(be + ch) - mean * sc;
}

// ---------------------------------------------------------------------------
// Row softmax over 1024 elems; emits bf16 hi/lo split
// ---------------------------------------------------------------------------
__global__ __launch_bounds__(256)
void softmax_kernel(const float* __restrict__ E,
                    __nv_bfloat16* __restrict__ Eh, __nv_bfloat16* __restrict__ El)
{
    const long long row = blockIdx.x;
    const float4* rp = (const float4*)(E + row * 1024);
    const int t = threadIdx.x;
    float4 v = rp[t];

    float m = fmaxf(fmaxf(v.x, v.y), fmaxf(v.z, v.w));
#pragma unroll
    for (int o = 16; o; o >>= 1) m = fmaxf(m, __shfl_xor_sync(0xffffffffu, m, o));
    __shared__ float smax[8], ssum[8];
    const int warp = t >> 5, lane = t & 31;
    if (lane == 0) smax[warp] = m;
    __syncthreads();
    float bm = smax[0];
#pragma unroll
    for (int w = 1; w < 8; w++) bm = fmaxf(bm, smax[w]);

    v.x = __expf(v.x - bm); v.y = __expf(v.y - bm);
    v.z = __expf(v.z - bm); v.w = __expf(v.w - bm);
    float s = v.x + v.y + v.z + v.w;
#pragma unroll
    for (int o = 16; o; o >>= 1) s += __shfl_xor_sync(0xffffffffu, s, o);
    if (lane == 0) ssum[warp] = s;
    __syncthreads();
    float bs = ssum[0];
#pragma unroll
    for (int w = 1; w < 8; w++) bs += ssum[w];

    const float inv = 1.f / bs;
    v.x *= inv; v.y *= inv; v.z *= inv; v.w *= inv;

    __nv_bfloat16 h0, l0, h1, l1, h2, l2, h3, l3;
    bf16split(v.x, h0, l0); bf16split(v.y, h1, l1);
    bf16split(v.z, h2, l2); bf16split(v.w, h3, l3);
    size_t o = (size_t)row * 1024 + t * 4;
    *(__nv_bfloat162*)(Eh + o)     = __halves2bfloat162(h0, h1);
    *(__nv_bfloat162*)(Eh + o + 2) = __halves2bfloat162(h2, h3);
    *(__nv_bfloat162*)(El + o)     = __halves2bfloat162(l0, l1);
    *(__nv_bfloat162*)(El + o + 2) = __halves2bfloat162(l2, l3);
}

// ---------------------------------------------------------------------------
// PV mma.sync kernel: att = gamma * (P @ V) + (xah+xal), emits bf16 hi/lo
// ---------------------------------------------------------------------------
#define PV_OP_BYTES 10240
#define PV_STAGE_BYTES 40960
#define PV_SMEM (2 * PV_STAGE_BYTES)   // 81920

__device__ __forceinline__ void pv_load(unsigned dst, int t,
    const char* a0, const char* a1, const char* b0, const char* b1, int kByte)
{
#pragma unroll
    for (int u = 0; u < 8; u++) {
        int i = t + u * 256;
        int op = i >> 9, row = (i >> 2) & 127, c = i & 3;
        const char* s = (op == 0) ? a0 : (op == 1) ? a1 : (op == 2) ? b0 : b1;
        cpasync16(dst + op * PV_OP_BYTES + row * 80 + c * 16,
                  s + (size_t)row * 2048 + kByte + c * 16);
    }
}

__global__ __launch_bounds__(256, 1)
void pv_kernel(const __nv_bfloat16* __restrict__ Eh, const __nv_bfloat16* __restrict__ El,
               const __nv_bfloat16* __restrict__ vTh, const __nv_bfloat16* __restrict__ vTl,
               const __nv_bfloat16* __restrict__ resh, const __nv_bfloat16* __restrict__ resl,
               const float* __restrict__ gammaPtr,
               __nv_bfloat16* __restrict__ atth, __nv_bfloat16* __restrict__ attl)
{
    extern __shared__ char smem[];
    const unsigned sb = smem_u32(smem);
    const int t = threadIdx.x;
    const int m0 = blockIdx.x * 128, n0 = blockIdx.y * 128, b = blockIdx.z;

    const char* gAh = (const char*)Eh  + (size_t)(b * 1024 + m0) * 2048;
    const char* gAl = (const char*)El  + (size_t)(b * 1024 + m0) * 2048;
    const char* gBh = (const char*)vTh + (size_t)(b * 256 + n0) * 2048;
    const char* gBl = (const char*)vTl + (size_t)(b * 256 + n0) * 2048;

    const int w = t >> 5, lane = t & 31;
    const int wm = (w & 1) * 64, wn = (w >> 1) * 32;
    const int aRowSel = (lane & 7) + ((lane >> 3) & 1) * 8;
    const int aChunk  = (lane >> 4) * 16;
    const int bRowSel = (lane & 7) + (lane >> 4) * 8;
    const int bChunk  = ((lane >> 3) & 1) * 16;

    float acc[4][4][4];
#pragma unroll
    for (int mi = 0; mi < 4; mi++)
#pragma unroll
        for (int ni = 0; ni < 4; ni++)
#pragma unroll
            for (int r = 0; r < 4; r++) acc[mi][ni][r] = 0.f;

    pv_load(sb, t, gAh, gAl, gBh, gBl, 0);
    CP_COMMIT();

    for (int s = 0; s < 32; s++) {
        if (s + 1 < 32) {
            pv_load(sb + ((s + 1) & 1) * PV_STAGE_BYTES, t, gAh, gAl, gBh, gBl, (s + 1) * 64);
            CP_COMMIT();
            CP_WAIT1();
        } else {
            CP_WAIT0();
        }
        __syncthreads();

        const unsigned base = sb + (s & 1) * PV_STAGE_BYTES;
#pragma unroll
        for (int s2 = 0; s2 < 2; s2++) {
            unsigned ah[4][4], al[4][4];
#pragma unroll
            for (int mi = 0; mi < 4; mi++) {
                unsigned ar = base + (wm + mi * 16 + aRowSel) * 80 + s2 * 32 + aChunk;
                ldsm_x4(ah[mi][0], ah[mi][1], ah[mi][2], ah[mi][3], ar);
                ldsm_x4(al[mi][0], al[mi][1], al[mi][2], al[mi][3], ar + PV_OP_BYTES);
            }
            unsigned bh[4][2], bl[4][2];
#pragma unroll
            for (int ngi = 0; ngi < 2; ngi++) {
                unsigned br = base + 2 * PV_OP_BYTES + (wn + ngi * 16 + bRowSel) * 80 + s2 * 32 + bChunk;
                unsigned r0, r1, r2, r3;
                ldsm_x4(r0, r1, r2, r3, br);
                bh[2 * ngi][0] = r0; bh[2 * ngi][1] = r1;
                bh[2 * ngi + 1][0] = r2; bh[2 * ngi + 1][1] = r3;
                ldsm_x4(r0, r1, r2, r3, br + PV_OP_BYTES);
                bl[2 * ngi][0] = r0; bl[2 * ngi][1] = r1;
                bl[2 * ngi + 1][0] = r2; bl[2 * ngi + 1][1] = r3;
            }
#pragma unroll
            for (int mi = 0; mi < 4; mi++)
#pragma unroll
                for (int ni = 0; ni < 4; ni++) {
                    mma_bf16(acc[mi][ni], ah[mi], bh[ni]);
                    mma_bf16(acc[mi][ni], ah[mi], bl[ni]);
                    mma_bf16(acc[mi][ni], al[mi], bh[ni]);
                }
        }
        __syncthreads();
    }

    const float gam = __ldg(gammaPtr);
    const int g = lane >> 2, tg = lane & 3;
#pragma unroll
    for (int mi = 0; mi < 4; mi++) {
#pragma unroll
        for (int ni = 0; ni < 4; ni++) {
            int gr = b * 1024 + m0 + wm + mi * 16 + g;
            int gc = n0 + wn + ni * 8 + 2 * tg;
#pragma unroll
            for (int half = 0; half < 2; half++) {
                size_t idx = (size_t)(gr + half * 8) * 256 + gc;
                __nv_bfloat162 rh = *(const __nv_bfloat162*)(resh + idx);
                __nv_bfloat162 rl = *(const __nv_bfloat162*)(resl + idx);
                float r0 = __bfloat162float(rh.x) + __bfloat162float(rl.x);
                float r1 = __bfloat162float(rh.y) + __bfloat162float(rl.y);
                float v0 = fmaf(gam, acc[mi][ni][2 * half + 0], r0);
                float v1 = fmaf(gam, acc[mi][ni][2 * half + 1], r1);
                __nv_bfloat16 h0, l0, h1, l1;
                bf16split(v0, h0, l0); bf16split(v1, h1, l1);
                *(__nv_bfloat162*)(atth + idx) = __halves2bfloat162(h0, h1);
                *(__nv_bfloat162*)(attl + idx) = __halves2bfloat162(l0, l1);
            }
        }
    }
}

// ---------------------------------------------------------------------------
// Final: out[b][cin][l] = b_out[cin] + sum_f w_out[cin][f] * relu(bn1(x1[g][f]))
// ---------------------------------------------------------------------------
__global__ __launch_bounds__(256)
void final_kernel(const float* __restrict__ x1,
                  const float* __restrict__ scale1, const float* __restrict__ shift1,
                  const float* __restrict__ w_out, const float* __restrict__ b_out,
                  float* __restrict__ out)
{
    __shared__ float xs[32][65];
    __shared__ float wsh[8][64];
    const int t = threadIdx.x;
    const int g0 = blockIdx.x * 32;

    for (int i = t; i < 32 * 64; i += 256) {
        int pos = i >> 6, f = i & 63;
        float v = x1[(size_t)(g0 + pos) * FFC + f];
        v = fmaf(v, __ldg(scale1 + f), __ldg(shift1 + f));
        xs[pos][f] = fmaxf(v, 0.f);
    }
    for (int i = t; i < 8 * 64; i += 256) wsh[i >> 6][i & 63] = w_out[i];
    __syncthreads();

    const int pos = t & 31, cin = t >> 5;
    float acc = __ldg(b_out + cin);
#pragma unroll
    for (int f = 0; f < 64; f++) acc = fmaf(wsh[cin][f], xs[pos][f], acc);

    const int b = g0 >> 10, l0 = g0 & 1023;
    out[b * (CIN * LL) + cin * LL + l0 + pos] = acc;
}

// ---------------------------------------------------------------------------
// Host launcher (graph-capturable: kernel launches only)
// ---------------------------------------------------------------------------
extern "C" void kernel_launch(void* const* d_in, const int* in_sizes, int n_in,
                              void* d_out, int out_size)
{
    const float* z     = (const float*)d_in[0];
    const float* w_pre = (const float*)d_in[1];
    const float* b_pre = (const float*)d_in[2];
    const float* w0    = (const float*)d_in[3];
    const float* b0    = (const float*)d_in[4];
    const float* g0    = (const float*)d_in[5];
    const float* be0   = (const float*)d_in[6];
    const float* wq    = (const float*)d_in[7];
    const float* bq    = (const float*)d_in[8];
    const float* wk    = (const float*)d_in[9];
    const float* bk    = (const float*)d_in[10];
    const float* wv    = (const float*)d_in[11];
    const float* bv    = (const float*)d_in[12];
    const float* gamma = (const float*)d_in[13];
    const float* w1    = (const float*)d_in[14];
    const float* b1    = (const float*)d_in[15];
    const float* g1    = (const float*)d_in[16];
    const float* be1   = (const float*)d_in[17];
    const float* w_out = (const float*)d_in[18];
    const float* b_out = (const float*)d_in[19];
    float* out = (float*)d_out;

    float *x0, *E, *x1, *pS, *pQ, *sc0, *sh0, *sc1, *sh1, *bqk;
    __nv_bfloat16 *xah, *xal, *qkh, *qkl, *Eh, *El, *vTh, *vTl, *atth, *attl;
    __nv_bfloat16 *wqkh, *wqkl, *wvh, *wvl, *w1h, *w1l;
    cudaGetSymbolAddress((void**)&x0,   g_x0);
    cudaGetSymbolAddress((void**)&xah,  g_xah);
    cudaGetSymbolAddress((void**)&xal,  g_xal);
    cudaGetSymbolAddress((void**)&qkh,  g_qkh);
    cudaGetSymbolAddress((void**)&qkl,  g_qkl);
    cudaGetSymbolAddress((void**)&E,    g_E);
    cudaGetSymbolAddress((void**)&Eh,   g_Eh);
    cudaGetSymbolAddress((void**)&El,   g_El);
    cudaGetSymbolAddress((void**)&vTh,  g_vTh);
    cudaGetSymbolAddress((void**)&vTl,  g_vTl);
    cudaGetSymbolAddress((void**)&atth, g_atth);
    cudaGetSymbolAddress((void**)&attl, g_attl);
    cudaGetSymbolAddress((void**)&x1,   g_x1);
    cudaGetSymbolAddress((void**)&pS,   g_pS);
    cudaGetSymbolAddress((void**)&pQ,   g_pQ);
    cudaGetSymbolAddress((void**)&sc0,  g_scale0);
    cudaGetSymbolAddress((void**)&sh0,  g_shift0);
    cudaGetSymbolAddress((void**)&sc1,  g_scale1);
    cudaGetSymbolAddress((void**)&sh1,  g_shift1);
    cudaGetSymbolAddress((void**)&wqkh, g_wqkh);
    cudaGetSymbolAddress((void**)&wqkl, g_wqkl);
    cudaGetSymbolAddress((void**)&wvh,  g_wvh);
    cudaGetSymbolAddress((void**)&wvl,  g_wvl);
    cudaGetSymbolAddress((void**)&w1h,  g_w1h);
    cudaGetSymbolAddress((void**)&w1l,  g_w1l);
    cudaGetSymbolAddress((void**)&bqk,  g_bqk);

    const int ST64  = 2 * (2 * 128 * 80 + 2 * 64 * 80);    // 61440
    const int ST128 = 2 * (2 * 128 * 80 + 2 * 128 * 80);   // 81920
    cudaFuncSetAttribute(pv_kernel, cudaFuncAttributeMaxDynamicSharedMemorySize, PV_SMEM);
    cudaFuncSetAttribute(mma_gemm<64, 0>,  cudaFuncAttributeMaxDynamicSharedMemorySize, ST64);
    cudaFuncSetAttribute(mma_gemm<64, 1>,  cudaFuncAttributeMaxDynamicSharedMemorySize, ST64);
    cudaFuncSetAttribute(mma_gemm<128, 0>, cudaFuncAttributeMaxDynamicSharedMemorySize, ST128);
    cudaFuncSetAttribute(mma_gemm<128, 2>, cudaFuncAttributeMaxDynamicSharedMemorySize, ST128);

    // 1) pre-linear: x0 = z @ w_pre^T + b_pre   [64 x 8192], K=128
    sgemm_kernel<<<dim3(8192 / 128, 1, 1), 256>>>(
        z, w_pre, b_pre, x0, NB, CIN * LL, ZD, ZD, ZD, CIN * LL);

    // 2) weight prep (independent)
    wprep_kernel<<<384, 256>>>(wq, wk, wv, w1, bq, bk, bqk,
                               wqkh, wqkl, wvh, wvl, w1h, w1l);

    // 3) BN0 via x0 moments (2 MB) -> analytic scale/shift
    xstats_partial<<<64, 256>>>(x0, pS);
    xstats_final<<<1, 256>>>(pS, w0, b0, g0, be0, sc0, sh0);

    // 4) fused conv0 + BN0 + ReLU -> xah/xal bf16 (no fp32 intermediates)
    conv0_fused<<<GG / 16, 256>>>(x0, w0, b0, sc0, sh0, xah, xal);

    // 5) Q+K projection (split out): [g][64], K=256
    mma_gemm<64, 1><<<dim3(1, GG / 128, 1), 256, ST64>>>(
        xah, xal, C0C, 0, wqkh, wqkl, C0C, 0, bqk,
        nullptr, qkh, qkl, 64, 0, C0C);

    // 6) V projection with fused transpose (coalesced) -> vT bf16 hi/lo, K=256
    mma_gemm<128, 2><<<dim3(2, GG / 128, 1), 256, ST128>>>(
        xah, xal, C0C, 0, wvh, wvl, C0C, 0, bv,
        nullptr, vTh, vTl, 0, 0, C0C);

    // 7) energy: E[b] = Q[b] K[b]^T  (M=N=1024, K=32), batched over 64
    mma_gemm<128, 0><<<dim3(8, 8, NB), 256, ST128>>>(
        qkh, qkl, 64, (long long)LL * 64,
        qkh + 32, qkl + 32, 64, (long long)LL * 64,
        nullptr, E, nullptr, nullptr, LL, (long long)LL * LL, CQKC);

    // 8) row softmax -> bf16 hi/lo probabilities
    softmax_kernel<<<GG, 256>>>(E, Eh, El);

    // 9) att = gamma * (P @ V) + (xah+xal)  -> bf16 hi/lo
    pv_kernel<<<dim3(8, 2, NB), 256, PV_SMEM>>>(Eh, El, vTh, vTl, xah, xal,
                                                gamma, atth, attl);

    // 10) conv1: x1 = att @ w1^T + b1  [g][64], K=256
    mma_gemm<64, 0><<<dim3(1, GG / 128, 1), 256, ST64>>>(
        atth, attl, C0C, 0, w1h, w1l, C0C, 0, b1,
        x1, nullptr, nullptr, FFC, 0, C0C);

    // 11) BN1 stats
    bnstats_partial<<<dim3(64, FFC / 32), 256>>>(x1, FFC, pS, pQ);
    bnfinalize<<<1, 64>>>(pS, pQ, g1, be1, sc1, sh1, FFC);

    // 12) fused BN1 + relu + w_out conv -> out [b][8][1024]
    final_kernel<<<GG / 32, 256>>>(x1, sc1, sh1, w_out, b_out, out);

    (void)in_sizes; (void)n_in; (void)out_size;
}

// round 10
// speedup vs baseline: 1.5850x; 1.4112x over previous
#include <cuda_runtime.h>
#include <cuda_bf16.h>

// ---------------------------------------------------------------------------
// Problem constants
// ---------------------------------------------------------------------------
#define NB    64          // batch
#define ZD    128         // latent dim
#define CIN   8
#define LL    1024        // W*H
#define C0C   256         // attention channels
#define CQKC  32
#define FFC   64          // filters
#define GG    65536       // NB * LL (total positions)

// ---------------------------------------------------------------------------
// Device scratch (allocation-free rule: __device__ globals)
// ---------------------------------------------------------------------------
__device__ __align__(16) float g_x0 [NB * CIN * LL];              //  2 MB
__device__ __align__(16) __nv_bfloat16 g_xah[(size_t)GG * C0C];   // 32 MB
__device__ __align__(16) __nv_bfloat16 g_xal[(size_t)GG * C0C];   // 32 MB
__device__ __align__(16) __nv_bfloat16 g_qkh[(size_t)GG * 64];    //  8 MB [g][q32|k32] hi
__device__ __align__(16) __nv_bfloat16 g_qkl[(size_t)GG * 64];    //  8 MB lo
__device__ __align__(16) float g_E  [(size_t)NB * LL * LL];       // 256 MB fp32 energies
__device__ __align__(16) __nv_bfloat16 g_Eh [(size_t)GG * LL];    // 128 MB softmax P bf16
__device__ __align__(16) __nv_bfloat16 g_vTh[(size_t)NB * C0C * LL]; // 32 MB V^T bf16
__device__ __align__(16) __nv_bfloat16 g_atth[(size_t)GG * C0C];  // 32 MB att hi
__device__ __align__(16) __nv_bfloat16 g_attl[(size_t)GG * C0C];  // 32 MB att lo
__device__ __align__(16) float g_x1 [(size_t)GG * FFC];           // 16 MB
// split weights
__device__ __align__(16) __nv_bfloat16 g_wqkh[64 * C0C],  g_wqkl[64 * C0C];
__device__ __align__(16) __nv_bfloat16 g_wvh [C0C * C0C], g_wvl [C0C * C0C];
__device__ __align__(16) __nv_bfloat16 g_w1h [FFC * C0C], g_w1l [FFC * C0C];
__device__ __align__(16) float g_bqk[64];
__device__ float g_pS[C0C * 64];           // reused: x0 moment partials [64][44]
__device__ float g_pQ[C0C * 64];
__device__ __align__(16) float g_scale0[C0C], g_shift0[C0C];
__device__ __align__(16) float g_scale1[FFC], g_shift1[FFC];

// ---------------------------------------------------------------------------
// PTX helpers (sm_80-level only — harness ptxas targets plain sm_100)
// ---------------------------------------------------------------------------
__device__ __forceinline__ unsigned smem_u32(const void* p) {
    unsigned a;
    asm("{ .reg .u64 t; cvta.to.shared.u64 t, %1; cvt.u32.u64 %0, t; }" : "=r"(a) : "l"(p));
    return a;
}
__device__ __forceinline__ void cpasync16(unsigned d, const void* s) {
    asm volatile("cp.async.cg.shared.global [%0], [%1], 16;" :: "r"(d), "l"(s));
}
#define CP_COMMIT() asm volatile("cp.async.commit_group;" ::: "memory")
#define CP_WAIT0()  asm volatile("cp.async.wait_group 0;" ::: "memory")
#define CP_WAIT1()  asm volatile("cp.async.wait_group 1;" ::: "memory")

__device__ __forceinline__ void ldsm_x4(unsigned& r0, unsigned& r1,
                                        unsigned& r2, unsigned& r3, unsigned addr) {
    asm volatile("ldmatrix.sync.aligned.m8n8.x4.shared.b16 {%0,%1,%2,%3}, [%4];"
                 : "=r"(r0), "=r"(r1), "=r"(r2), "=r"(r3) : "r"(addr));
}
__device__ __forceinline__ void mma_bf16(float* c, const unsigned* a, const unsigned* b) {
    asm volatile("mma.sync.aligned.m16n8k16.row.col.f32.bf16.bf16.f32 "
                 "{%0,%1,%2,%3}, {%4,%5,%6,%7}, {%8,%9}, {%0,%1,%2,%3};"
                 : "+f"(c[0]), "+f"(c[1]), "+f"(c[2]), "+f"(c[3])
                 : "r"(a[0]), "r"(a[1]), "r"(a[2]), "r"(a[3]), "r"(b[0]), "r"(b[1]));
}
__device__ __forceinline__ void bf16split(float v, __nv_bfloat16& h, __nv_bfloat16& l) {
    h = __float2bfloat16(v);
    l = __float2bfloat16(v - __bfloat162float(h));
}
__device__ __forceinline__ unsigned pack2(__nv_bfloat16 a, __nv_bfloat16 b) {
    return ((unsigned)__bfloat16_as_ushort(b) << 16) | __bfloat16_as_ushort(a);
}

// ---------------------------------------------------------------------------
// Generic split-bf16 MMA GEMM.
//   OUT_MODE 0: fp32 C (+bias)
//   OUT_MODE 1: bf16 hi/lo split C (+bias)
//   OUT_MODE 2: V-projection: stage to smem, coalesced transposed vTh write
//               (single bf16 output — PV consumes plain bf16 V).
// ---------------------------------------------------------------------------
template<int BN>
__device__ __forceinline__ void mm_load(unsigned dst, int t,
    const char* Ah, const char* Al, const char* Bh, const char* Bl,
    int ldaB, int ldbB, int m0, int n0, int kByte)
{
    constexpr int AOP = 128 * 80, BOP = BN * 80;
    constexpr int TCA = 1024, TC = TCA + BN * 8;
#pragma unroll
    for (int u = 0; u < TC / 256; u++) {
        int i = t + u * 256;
        if (i < TCA) {
            int half = i >> 9, row = (i >> 2) & 127, c = i & 3;
            const char* s = half ? Al : Ah;
            cpasync16(dst + half * AOP + row * 80 + c * 16,
                      s + (size_t)(m0 + row) * ldaB + kByte + c * 16);
        } else {
            int j = i - TCA;
            int half = j / (BN * 4), row = (j >> 2) % BN, c = j & 3;
            const char* s = half ? Bl : Bh;
            cpasync16(dst + 2 * AOP + half * BOP + row * 80 + c * 16,
                      s + (size_t)(n0 + row) * ldbB + kByte + c * 16);
        }
    }
}

template<int BN, int OUT_MODE>
__global__ __launch_bounds__(256, 1)
void mma_gemm(const __nv_bfloat16* __restrict__ Ah, const __nv_bfloat16* __restrict__ Al,
              int lda, long long sA,
              const __nv_bfloat16* __restrict__ Bh, const __nv_bfloat16* __restrict__ Bl,
              int ldb, long long sB,
              const float* __restrict__ bias,
              float* __restrict__ C,
              __nv_bfloat16* __restrict__ Ch, __nv_bfloat16* __restrict__ Cl,
              int ldc, long long sC, int K)
{
    constexpr int AOP = 128 * 80, BOP = BN * 80;
    constexpr int ST = 2 * AOP + 2 * BOP;
    constexpr int NW = BN / 4;
    constexpr int NI = NW / 8;
    constexpr int NGI = NW / 16;

    extern __shared__ char smem[];
    const unsigned sb = smem_u32(smem);
    const int t = threadIdx.x;
    const int n0 = blockIdx.x * BN, m0 = blockIdx.y * 128, z = blockIdx.z;

    const char* cAh = (const char*)(Ah + (size_t)z * sA);
    const char* cAl = (const char*)(Al + (size_t)z * sA);
    const char* cBh = (const char*)(Bh + (size_t)z * sB);
    const char* cBl = (const char*)(Bl + (size_t)z * sB);
    const int ldaB = lda * 2, ldbB = ldb * 2;

    const int w = t >> 5, lane = t & 31;
    const int wm = (w & 1) * 64, wn = (w >> 1) * NW;
    const int aRowSel = (lane & 7) + ((lane >> 3) & 1) * 8;
    const int aChunk  = (lane >> 4) * 16;
    const int bRowSel = (lane & 7) + (lane >> 4) * 8;
    const int bChunk  = ((lane >> 3) & 1) * 16;

    float acc[4][NI][4];
#pragma unroll
    for (int mi = 0; mi < 4; mi++)
#pragma unroll
        for (int ni = 0; ni < NI; ni++)
#pragma unroll
            for (int r = 0; r < 4; r++) acc[mi][ni][r] = 0.f;

    const int nst = K / 32;
    mm_load<BN>(sb, t, cAh, cAl, cBh, cBl, ldaB, ldbB, m0, n0, 0);
    CP_COMMIT();

    for (int s = 0; s < nst; s++) {
        if (s + 1 < nst) {
            mm_load<BN>(sb + ((s + 1) & 1) * ST, t, cAh, cAl, cBh, cBl,
                        ldaB, ldbB, m0, n0, (s + 1) * 64);
            CP_COMMIT();
            CP_WAIT1();
        } else {
            CP_WAIT0();
        }
        __syncthreads();

        const unsigned base = sb + (s & 1) * ST;
#pragma unroll
        for (int s2 = 0; s2 < 2; s2++) {
            unsigned ah[4][4], al[4][4];
#pragma unroll
            for (int mi = 0; mi < 4; mi++) {
                unsigned ar = base + (wm + mi * 16 + aRowSel) * 80 + s2 * 32 + aChunk;
                ldsm_x4(ah[mi][0], ah[mi][1], ah[mi][2], ah[mi][3], ar);
                ldsm_x4(al[mi][0], al[mi][1], al[mi][2], al[mi][3], ar + AOP);
            }
            unsigned bh[NI][2], bl[NI][2];
#pragma unroll
            for (int ngi = 0; ngi < NGI; ngi++) {
                unsigned br = base + 2 * AOP + (wn + ngi * 16 + bRowSel) * 80 + s2 * 32 + bChunk;
                unsigned r0, r1, r2, r3;
                ldsm_x4(r0, r1, r2, r3, br);
                bh[2 * ngi][0] = r0; bh[2 * ngi][1] = r1;
                bh[2 * ngi + 1][0] = r2; bh[2 * ngi + 1][1] = r3;
                ldsm_x4(r0, r1, r2, r3, br + BOP);
                bl[2 * ngi][0] = r0; bl[2 * ngi][1] = r1;
                bl[2 * ngi + 1][0] = r2; bl[2 * ngi + 1][1] = r3;
            }
#pragma unroll
            for (int mi = 0; mi < 4; mi++)
#pragma unroll
                for (int ni = 0; ni < NI; ni++) {
                    mma_bf16(acc[mi][ni], ah[mi], bh[ni]);
                    mma_bf16(acc[mi][ni], ah[mi], bl[ni]);
                    mma_bf16(acc[mi][ni], al[mi], bh[ni]);
                }
        }
        __syncthreads();
    }

    const int g = lane >> 2, tg = lane & 3;

    if (OUT_MODE == 2) {
        float* Ss = (float*)smem;
#pragma unroll
        for (int mi = 0; mi < 4; mi++)
#pragma unroll
            for (int ni = 0; ni < NI; ni++) {
                int col = wn + ni * 8 + 2 * tg;
                float b0 = __ldg(bias + n0 + col), b1 = __ldg(bias + n0 + col + 1);
#pragma unroll
                for (int half = 0; half < 2; half++) {
                    int row = wm + mi * 16 + half * 8 + g;
                    Ss[row * 132 + col]     = acc[mi][ni][2 * half + 0] + b0;
                    Ss[row * 132 + col + 1] = acc[mi][ni][2 * half + 1] + b1;
                }
            }
        __syncthreads();
        const int b = m0 >> 10, l0 = m0 & 1023;
        const int m = lane * 4;
#pragma unroll
        for (int i = 0; i < 16; i++) {
            int n = w * 16 + i;
            float v0 = Ss[(m + 0) * 132 + n];
            float v1 = Ss[(m + 1) * 132 + n];
            float v2 = Ss[(m + 2) * 132 + n];
            float v3 = Ss[(m + 3) * 132 + n];
            size_t ob = ((size_t)(b * 256 + n0 + n)) * 1024 + l0 + m;
            uint2 uh;
            uh.x = pack2(__float2bfloat16(v0), __float2bfloat16(v1));
            uh.y = pack2(__float2bfloat16(v2), __float2bfloat16(v3));
            *(uint2*)(Ch + ob) = uh;
        }
        return;
    }

#pragma unroll
    for (int mi = 0; mi < 4; mi++) {
#pragma unroll
        for (int ni = 0; ni < NI; ni++) {
            int gr = m0 + wm + mi * 16 + g;
            int gc = n0 + wn + ni * 8 + 2 * tg;
            float b0 = 0.f, b1 = 0.f;
            if (bias) { b0 = __ldg(bias + gc); b1 = __ldg(bias + gc + 1); }
#pragma unroll
            for (int half = 0; half < 2; half++) {
                size_t idx = (size_t)z * sC + (size_t)(gr + half * 8) * ldc + gc;
                float v0 = acc[mi][ni][2 * half + 0] + b0;
                float v1 = acc[mi][ni][2 * half + 1] + b1;
                if (OUT_MODE == 1) {
                    __nv_bfloat16 h0, l0b, h1, l1b;
                    bf16split(v0, h0, l0b); bf16split(v1, h1, l1b);
                    *(__nv_bfloat162*)(Ch + idx) = __halves2bfloat162(h0, h1);
                    *(__nv_bfloat162*)(Cl + idx) = __halves2bfloat162(l0b, l1b);
                } else {
                    float2 o; o.x = v0; o.y = v1;
                    *(float2*)(C + idx) = o;
                }
            }
        }
    }
}

// ---------------------------------------------------------------------------
// SIMT SGEMM (only for tiny pre-linear), B stored [N,K] row-major
// ---------------------------------------------------------------------------
__global__ __launch_bounds__(256)
void sgemm_kernel(const float* __restrict__ A, const float* __restrict__ Bm,
                  const float* __restrict__ bias, float* __restrict__ C,
                  int M, int N, int K, int lda, int ldb, int ldc)
{
    __shared__ float As[8][128];
    __shared__ float Bs[8][128];

    const int tid = threadIdx.x;
    const int m0 = blockIdx.y * 128;
    const int n0 = blockIdx.x * 128;

    const int aRow = tid >> 1;
    const int aK   = (tid & 1) << 2;
    const int tr = (tid >> 4) << 3;
    const int tc = (tid & 15) << 3;

    const bool aOK = (m0 + aRow) < M;
    const bool bOK = (n0 + aRow) < N;
    const float* aPtr = A + (long long)(m0 + aRow) * lda + aK;
    const float* bPtr = Bm + (long long)(n0 + aRow) * ldb + aK;

    float acc[8][8];
#pragma unroll
    for (int i = 0; i < 8; i++)
#pragma unroll
        for (int j = 0; j < 8; j++) acc[i][j] = 0.f;

    float4 aReg = make_float4(0.f, 0.f, 0.f, 0.f);
    float4 bReg = make_float4(0.f, 0.f, 0.f, 0.f);
    if (aOK) aReg = *(const float4*)aPtr;
    if (bOK) bReg = *(const float4*)bPtr;

    for (int k0 = 0; k0 < K; k0 += 8) {
        As[aK + 0][aRow] = aReg.x; As[aK + 1][aRow] = aReg.y;
        As[aK + 2][aRow] = aReg.z; As[aK + 3][aRow] = aReg.w;
        Bs[aK + 0][aRow] = bReg.x; Bs[aK + 1][aRow] = bReg.y;
        Bs[aK + 2][aRow] = bReg.z; Bs[aK + 3][aRow] = bReg.w;
        __syncthreads();

        if (k0 + 8 < K) {
            aReg = make_float4(0.f, 0.f, 0.f, 0.f);
            bReg = make_float4(0.f, 0.f, 0.f, 0.f);
            if (aOK) aReg = *(const float4*)(aPtr + (k0 + 8));
            if (bOK) bReg = *(const float4*)(bPtr + (k0 + 8));
        }

#pragma unroll
        for (int kk = 0; kk < 8; kk++) {
            float ar[8], br[8];
            *(float4*)&ar[0] = *(const float4*)&As[kk][tr];
            *(float4*)&ar[4] = *(const float4*)&As[kk][tr + 4];
            *(float4*)&br[0] = *(const float4*)&Bs[kk][tc];
            *(float4*)&br[4] = *(const float4*)&Bs[kk][tc + 4];
#pragma unroll
            for (int i = 0; i < 8; i++)
#pragma unroll
                for (int j = 0; j < 8; j++)
                    acc[i][j] = fmaf(ar[i], br[j], acc[i][j]);
        }
        __syncthreads();
    }

#pragma unroll
    for (int i = 0; i < 8; i++) {
        int gm = m0 + tr + i;
        if (gm < M) {
#pragma unroll
            for (int j = 0; j < 8; j += 4) {
                int gn = n0 + tc + j;
                if (gn < N) {
                    float4 o;
                    o.x = acc[i][j]; o.y = acc[i][j + 1];
                    o.z = acc[i][j + 2]; o.w = acc[i][j + 3];
                    if (bias) {
                        o.x += __ldg(bias + gn);     o.y += __ldg(bias + gn + 1);
                        o.z += __ldg(bias + gn + 2); o.w += __ldg(bias + gn + 3);
                    }
                    *(float4*)(C + (long long)gm * ldc + gn) = o;
                }
            }
        }
    }
}

// ---------------------------------------------------------------------------
// Weight prep: split wq||wk, wv, w1 into bf16 hi/lo; merge bq||bk
// ---------------------------------------------------------------------------
__global__ void wprep_kernel(const float* __restrict__ wq, const float* __restrict__ wk,
                             const float* __restrict__ wv, const float* __restrict__ w1,
                             const float* __restrict__ bq, const float* __restrict__ bk,
                             float* __restrict__ bqk,
                             __nv_bfloat16* __restrict__ wqkh, __nv_bfloat16* __restrict__ wqkl,
                             __nv_bfloat16* __restrict__ wvh,  __nv_bfloat16* __restrict__ wvl,
                             __nv_bfloat16* __restrict__ w1h,  __nv_bfloat16* __restrict__ w1l)
{
    int i = blockIdx.x * 256 + threadIdx.x;
    if (i < 16384) {
        int n = i >> 8, k = i & 255;
        float v = (n < 32) ? wq[n * 256 + k] : wk[(n - 32) * 256 + k];
        __nv_bfloat16 h, l;
        bf16split(v, h, l);
        wqkh[i] = h; wqkl[i] = l;
    } else if (i < 81920) {
        int j = i - 16384;
        __nv_bfloat16 h, l;
        bf16split(wv[j], h, l);
        wvh[j] = h; wvl[j] = l;
    } else if (i < 98304) {
        int j = i - 81920;
        __nv_bfloat16 h, l;
        bf16split(w1[j], h, l);
        w1h[j] = h; w1l[j] = l;
    }
    if (i < 64) bqk[i] = (i < 32) ? bq[i] : bk[i - 32];
}

// ---------------------------------------------------------------------------
// x0 moment stats (8 + 36 vals) per batch; deterministic reductions.
// ---------------------------------------------------------------------------
__global__ __launch_bounds__(256)
void xstats_partial(const float* __restrict__ x0, float* __restrict__ pX)
{
    const int b = blockIdx.x, t = threadIdx.x;
    const int warp = t >> 5, lane = t & 31;
    float a[44];
#pragma unroll
    for (int j = 0; j < 44; j++) a[j] = 0.f;

#pragma unroll
    for (int r = 0; r < 4; r++) {
        int l = t + r * 256;
        float v[CIN];
#pragma unroll
        for (int c = 0; c < CIN; c++)
            v[c] = x0[b * (CIN * LL) + c * LL + l];
#pragma unroll
        for (int c = 0; c < CIN; c++) a[c] += v[c];
        int idx = CIN;
#pragma unroll
        for (int c1 = 0; c1 < CIN; c1++)
#pragma unroll
            for (int c2 = c1; c2 < CIN; c2++)
                a[idx++] = fmaf(v[c1], v[c2], a[idx]);
    }
#pragma unroll
    for (int j = 0; j < 44; j++)
#pragma unroll
        for (int o = 16; o; o >>= 1)
            a[j] += __shfl_xor_sync(0xffffffffu, a[j], o);

    __shared__ float ws[8][44];
    if (lane == 0)
#pragma unroll
        for (int j = 0; j < 44; j++) ws[warp][j] = a[j];
    __syncthreads();
    if (t < 44) {
        float s = ws[0][t];
#pragma unroll
        for (int w = 1; w < 8; w++) s += ws[w][t];
        pX[b * 44 + t] = s;
    }
}

__global__ void xstats_final(const float* __restrict__ pX,
                             const float* __restrict__ w0, const float* __restrict__ b0,
                             const float* __restrict__ g0, const float* __restrict__ be0,
                             float* __restrict__ scale, float* __restrict__ shift)
{
    __shared__ float mom[44];
    __shared__ float mu[CIN];
    __shared__ float cov[CIN][CIN];
    const int t = threadIdx.x;
    if (t < 44) {
        float s = 0.f;
        for (int b = 0; b < 64; b++) s += pX[b * 44 + t];
        mom[t] = s;
    }
    __syncthreads();
    if (t == 0) {
        const float inv = 1.f / 65536.f;
        for (int c = 0; c < CIN; c++) mu[c] = mom[c] * inv;
        int idx = CIN;
        for (int c1 = 0; c1 < CIN; c1++)
            for (int c2 = c1; c2 < CIN; c2++) {
                float cv = mom[idx++] * inv - mu[c1] * mu[c2];
                cov[c1][c2] = cv; cov[c2][c1] = cv;
            }
    }
    __syncthreads();
    float w[CIN];
#pragma unroll
    for (int c = 0; c < CIN; c++) w[c] = w0[t * CIN + c];
    float mean = __ldg(b0 + t);
#pragma unroll
    for (int c = 0; c < CIN; c++) mean = fmaf(w[c], mu[c], mean);
    float var = 0.f;
#pragma unroll
    for (int c1 = 0; c1 < CIN; c1++) {
        float acc = 0.f;
#pragma unroll
        for (int c2 = 0; c2 < CIN; c2++) acc = fmaf(w[c2], cov[c1][c2], acc);
        var = fmaf(w[c1], acc, var);
    }
    float sc = __ldg(g0 + t) * rsqrtf(var + 1e-5f);
    scale[t] = sc;
    shift[t] = __ldg(be0 + t) - mean * sc;
}

// ---------------------------------------------------------------------------
// Fused conv0 + BN0 + ReLU -> xah/xal bf16
// ---------------------------------------------------------------------------
__global__ __launch_bounds__(256)
void conv0_fused(const float* __restrict__ x0, const float* __restrict__ w0,
                 const float* __restrict__ b0,
                 const float* __restrict__ sc0, const float* __restrict__ sh0,
                 __nv_bfloat16* __restrict__ xah, __nv_bfloat16* __restrict__ xal)
{
    __shared__ float ws[C0C * CIN];
    __shared__ float xs[CIN][16];
    const int t = threadIdx.x;
    for (int i = t; i < C0C * CIN; i += 256) ws[i] = w0[i];
    const int g0 = blockIdx.x * 16;
    const int b = g0 >> 10, l0 = g0 & 1023;
    if (t < 128) {
        int c = t >> 4, i = t & 15;
        xs[c][i] = x0[b * (CIN * LL) + c * LL + l0 + i];
    }
    __syncthreads();

    float wreg[CIN];
#pragma unroll
    for (int c = 0; c < CIN; c++) wreg[c] = ws[t * CIN + c];
    const float bb = __ldg(b0 + t);
    const float sc = __ldg(sc0 + t), sh = __ldg(sh0 + t);
#pragma unroll
    for (int i = 0; i < 16; i++) {
        float acc = bb;
#pragma unroll
        for (int c = 0; c < CIN; c++) acc = fmaf(wreg[c], xs[c][i], acc);
        float v = fmaxf(fmaf(acc, sc, sh), 0.f);
        __nv_bfloat16 h, l;
        bf16split(v, h, l);
        size_t o = (size_t)(g0 + i) * C0C + t;
        xah[o] = h; xal[o] = l;
    }
}

// ---------------------------------------------------------------------------
// BN stats (deterministic two-stage) — BN1 only
// ---------------------------------------------------------------------------
__global__ __launch_bounds__(256)
void bnstats_partial(const float* __restrict__ y, int nch,
                     float* __restrict__ pS, float* __restrict__ pQ)
{
    const int chunk = blockIdx.x;
    const int group = blockIdx.y;
    const int t = threadIdx.x;
    const int warp = t >> 5, lane = t & 31;
    const int ch = group * 32 + lane;
    const long long base = (long long)chunk * 1024;

    float s = 0.f, q = 0.f;
    for (int r = warp; r < 1024; r += 8) {
        float v = y[(base + r) * nch + ch];
        s += v; q = fmaf(v, v, q);
    }
    __shared__ float ss[8][32], sq[8][32];
    ss[warp][lane] = s; sq[warp][lane] = q;
    __syncthreads();
    if (warp == 0) {
        float S = ss[0][lane], Q = sq[0][lane];
#pragma unroll
        for (int w = 1; w < 8; w++) { S += ss[w][lane]; Q += sq[w][lane]; }
        pS[ch * 64 + chunk] = S;
        pQ[ch * 64 + chunk] = Q;
    }
}

__global__ void bnfinalize(const float* __restrict__ pS, const float* __restrict__ pQ,
                           const float* __restrict__ g, const float* __restrict__ be,
                           float* __restrict__ scale, float* __restrict__ shift, int nch)
{
    int ch = blockIdx.x * blockDim.x + threadIdx.x;
    if (ch >= nch) return;
    float s0 = 0.f, s1 = 0.f, s2 = 0.f, s3 = 0.f;
    float q0 = 0.f, q1 = 0.f, q2 = 0.f, q3 = 0.f;
#pragma unroll
    for (int i = 0; i < 64; i += 4) {
        s0 += pS[ch * 64 + i];     q0 += pQ[ch * 64 + i];
        s1 += pS[ch * 64 + i + 1]; q1 += pQ[ch * 64 + i + 1];
        s2 += pS[ch * 64 + i + 2]; q2 += pQ[ch * 64 + i + 2];
        s3 += pS[ch * 64 + i + 3]; q3 += pQ[ch * 64 + i + 3];
    }
    float s = (s0 + s1) + (s2 + s3);
    float q = (q0 + q1) + (q2 + q3);
    const float inv = 1.f / 65536.f;
    float mean = s * inv;
    float var = q * inv - mean * mean;
    float sc = __ldg(g + ch) * rsqrtf(var + 1e-5f);
    scale[ch] = sc;
    shift[ch] = __ldg(be + ch) - mean * sc;
}

// ---------------------------------------------------------------------------
// Row softmax over 1024 elems; emits single bf16 P (PV precision analysis:
// P bf16 error dilutes to ~1e-5 on final output — residual dominates)
// ---------------------------------------------------------------------------
__global__ __launch_bounds__(256)
void softmax_kernel(const float* __restrict__ E, __nv_bfloat16* __restrict__ Eh)
{
    const long long row = blockIdx.x;
    const float4* rp = (const float4*)(E + row * 1024);
    const int t = threadIdx.x;
    float4 v = rp[t];

    float m = fmaxf(fmaxf(v.x, v.y), fmaxf(v.z, v.w));
#pragma unroll
    for (int o = 16; o; o >>= 1) m = fmaxf(m, __shfl_xor_sync(0xffffffffu, m, o));
    __shared__ float smax[8], ssum[8];
    const int warp = t >> 5, lane = t & 31;
    if (lane == 0) smax[warp] = m;
    __syncthreads();
    float bm = smax[0];
#pragma unroll
    for (int w = 1; w < 8; w++) bm = fmaxf(bm, smax[w]);

    v.x = __expf(v.x - bm); v.y = __expf(v.y - bm);
    v.z = __expf(v.z - bm); v.w = __expf(v.w - bm);
    float s = v.x + v.y + v.z + v.w;
#pragma unroll
    for (int o = 16; o; o >>= 1) s += __shfl_xor_sync(0xffffffffu, s, o);
    if (lane == 0) ssum[warp] = s;
    __syncthreads();
    float bs = ssum[0];
#pragma unroll
    for (int w = 1; w < 8; w++) bs += ssum[w];

    const float inv = 1.f / bs;
    uint2 o2;
    o2.x = pack2(__float2bfloat16(v.x * inv), __float2bfloat16(v.y * inv));
    o2.y = pack2(__float2bfloat16(v.z * inv), __float2bfloat16(v.w * inv));
    *(uint2*)(Eh + (size_t)row * 1024 + t * 4) = o2;
}

// ---------------------------------------------------------------------------
// PV mma.sync kernel (single bf16 operands): att = gamma*(P@V) + (xah+xal)
// Stage: Eh 128x32 + vTh 128x32 at 80B pitch = 20480 B; double buffer 40960.
// 2 CTAs/SM for latency hiding.
// ---------------------------------------------------------------------------
#define PV_OP_BYTES 10240
#define PV_STAGE_BYTES 20480
#define PV_SMEM (2 * PV_STAGE_BYTES)   // 40960

__device__ __forceinline__ void pv_load(unsigned dst, int t,
    const char* a0, const char* b0, int kByte)
{
#pragma unroll
    for (int u = 0; u < 4; u++) {
        int i = t + u * 256;
        int op = i >> 9, row = (i >> 2) & 127, c = i & 3;
        const char* s = op ? b0 : a0;
        cpasync16(dst + op * PV_OP_BYTES + row * 80 + c * 16,
                  s + (size_t)row * 2048 + kByte + c * 16);
    }
}

__global__ __launch_bounds__(256, 2)
void pv_kernel(const __nv_bfloat16* __restrict__ Eh,
               const __nv_bfloat16* __restrict__ vTh,
               const __nv_bfloat16* __restrict__ resh, const __nv_bfloat16* __restrict__ resl,
               const float* __restrict__ gammaPtr,
               __nv_bfloat16* __restrict__ atth, __nv_bfloat16* __restrict__ attl)
{
    extern __shared__ char smem[];
    const unsigned sb = smem_u32(smem);
    const int t = threadIdx.x;
    const int m0 = blockIdx.x * 128, n0 = blockIdx.y * 128, b = blockIdx.z;

    const char* gA = (const char*)Eh  + (size_t)(b * 1024 + m0) * 2048;
    const char* gB = (const char*)vTh + (size_t)(b * 256 + n0) * 2048;

    const int w = t >> 5, lane = t & 31;
    const int wm = (w & 1) * 64, wn = (w >> 1) * 32;
    const int aRowSel = (lane & 7) + ((lane >> 3) & 1) * 8;
    const int aChunk  = (lane >> 4) * 16;
    const int bRowSel = (lane & 7) + (lane >> 4) * 8;
    const int bChunk  = ((lane >> 3) & 1) * 16;

    float acc[4][4][4];
#pragma unroll
    for (int mi = 0; mi < 4; mi++)
#pragma unroll
        for (int ni = 0; ni < 4; ni++)
#pragma unroll
            for (int r = 0; r < 4; r++) acc[mi][ni][r] = 0.f;

    pv_load(sb, t, gA, gB, 0);
    CP_COMMIT();

    for (int s = 0; s < 32; s++) {
        if (s + 1 < 32) {
            pv_load(sb + ((s + 1) & 1) * PV_STAGE_BYTES, t, gA, gB, (s + 1) * 64);
            CP_COMMIT();
            CP_WAIT1();
        } else {
            CP_WAIT0();
        }
        __syncthreads();

        const unsigned base = sb + (s & 1) * PV_STAGE_BYTES;
#pragma unroll
        for (int s2 = 0; s2 < 2; s2++) {
            unsigned ah[4][4];
#pragma unroll
            for (int mi = 0; mi < 4; mi++) {
                unsigned ar = base + (wm + mi * 16 + aRowSel) * 80 + s2 * 32 + aChunk;
                ldsm_x4(ah[mi][0], ah[mi][1], ah[mi][2], ah[mi][3], ar);
            }
            unsigned bh[4][2];
#pragma unroll
            for (int ngi = 0; ngi < 2; ngi++) {
                unsigned br = base + PV_OP_BYTES + (wn + ngi * 16 + bRowSel) * 80 + s2 * 32 + bChunk;
                unsigned r0, r1, r2, r3;
                ldsm_x4(r0, r1, r2, r3, br);
                bh[2 * ngi][0] = r0; bh[2 * ngi][1] = r1;
                bh[2 * ngi + 1][0] = r2; bh[2 * ngi + 1][1] = r3;
            }
#pragma unroll
            for (int mi = 0; mi < 4; mi++)
#pragma unroll
                for (int ni = 0; ni < 4; ni++)
                    mma_bf16(acc[mi][ni], ah[mi], bh[ni]);
        }
        __syncthreads();
    }

    const float gam = __ldg(gammaPtr);
    const int g = lane >> 2, tg = lane & 3;
#pragma unroll
    for (int mi = 0; mi < 4; mi++) {
#pragma unroll
        for (int ni = 0; ni < 4; ni++) {
            int gr = b * 1024 + m0 + wm + mi * 16 + g;
            int gc = n0 + wn + ni * 8 + 2 * tg;
#pragma unroll
            for (int half = 0; half < 2; half++) {
                size_t idx = (size_t)(gr + half * 8) * 256 + gc;
                __nv_bfloat162 rh = *(const __nv_bfloat162*)(resh + idx);
                __nv_bfloat162 rl = *(const __nv_bfloat162*)(resl + idx);
                float r0 = __bfloat162float(rh.x) + __bfloat162float(rl.x);
                float r1 = __bfloat162float(rh.y) + __bfloat162float(rl.y);
                float v0 = fmaf(gam, acc[mi][ni][2 * half + 0], r0);
                float v1 = fmaf(gam, acc[mi][ni][2 * half + 1], r1);
                __nv_bfloat16 h0, l0, h1, l1;
                bf16split(v0, h0, l0); bf16split(v1, h1, l1);
                *(__nv_bfloat162*)(atth + idx) = __halves2bfloat162(h0, h1);
                *(__nv_bfloat162*)(attl + idx) = __halves2bfloat162(l0, l1);
            }
        }
    }
}

// ---------------------------------------------------------------------------
// Final: out[b][cin][l] = b_out[cin] + sum_f w_out[cin][f] * relu(bn1(x1[g][f]))
// ---------------------------------------------------------------------------
__global__ __launch_bounds__(256)
void final_kernel(const float* __restrict__ x1,
                  const float* __restrict__ scale1, const float* __restrict__ shift1,
                  const float* __restrict__ w_out, const float* __restrict__ b_out,
                  float* __restrict__ out)
{
    __shared__ float xs[32][65];
    __shared__ float wsh[8][64];
    const int t = threadIdx.x;
    const int g0 = blockIdx.x * 32;

    for (int i = t; i < 32 * 64; i += 256) {
        int pos = i >> 6, f = i & 63;
        float v = x1[(size_t)(g0 + pos) * FFC + f];
        v = fmaf(v, __ldg(scale1 + f), __ldg(shift1 + f));
        xs[pos][f] = fmaxf(v, 0.f);
    }
    for (int i = t; i < 8 * 64; i += 256) wsh[i >> 6][i & 63] = w_out[i];
    __syncthreads();

    const int pos = t & 31, cin = t >> 5;
    float acc = __ldg(b_out + cin);
#pragma unroll
    for (int f = 0; f < 64; f++) acc = fmaf(wsh[cin][f], xs[pos][f], acc);

    const int b = g0 >> 10, l0 = g0 & 1023;
    out[b * (CIN * LL) + cin * LL + l0 + pos] = acc;
}

// ---------------------------------------------------------------------------
// Host launcher (graph-capturable: kernel launches only)
// ---------------------------------------------------------------------------
extern "C" void kernel_launch(void* const* d_in, const int* in_sizes, int n_in,
                              void* d_out, int out_size)
{
    const float* z     = (const float*)d_in[0];
    const float* w_pre = (const float*)d_in[1];
    const float* b_pre = (const float*)d_in[2];
    const float* w0    = (const float*)d_in[3];
    const float* b0    = (const float*)d_in[4];
    const float* g0    = (const float*)d_in[5];
    const float* be0   = (const float*)d_in[6];
    const float* wq    = (const float*)d_in[7];
    const float* bq    = (const float*)d_in[8];
    const float* wk    = (const float*)d_in[9];
    const float* bk    = (const float*)d_in[10];
    const float* wv    = (const float*)d_in[11];
    const float* bv    = (const float*)d_in[12];
    const float* gamma = (const float*)d_in[13];
    const float* w1    = (const float*)d_in[14];
    const float* b1    = (const float*)d_in[15];
    const float* g1    = (const float*)d_in[16];
    const float* be1   = (const float*)d_in[17];
    const float* w_out = (const float*)d_in[18];
    const float* b_out = (const float*)d_in[19];
    float* out = (float*)d_out;

    float *x0, *E, *x1, *pS, *pQ, *sc0, *sh0, *sc1, *sh1, *bqk;
    __nv_bfloat16 *xah, *xal, *qkh, *qkl, *Eh, *vTh, *atth, *attl;
    __nv_bfloat16 *wqkh, *wqkl, *wvh, *wvl, *w1h, *w1l;
    cudaGetSymbolAddress((void**)&x0,   g_x0);
    cudaGetSymbolAddress((void**)&xah,  g_xah);
    cudaGetSymbolAddress((void**)&xal,  g_xal);
    cudaGetSymbolAddress((void**)&qkh,  g_qkh);
    cudaGetSymbolAddress((void**)&qkl,  g_qkl);
    cudaGetSymbolAddress((void**)&E,    g_E);
    cudaGetSymbolAddress((void**)&Eh,   g_Eh);
    cudaGetSymbolAddress((void**)&vTh,  g_vTh);
    cudaGetSymbolAddress((void**)&atth, g_atth);
    cudaGetSymbolAddress((void**)&attl, g_attl);
    cudaGetSymbolAddress((void**)&x1,   g_x1);
    cudaGetSymbolAddress((void**)&pS,   g_pS);
    cudaGetSymbolAddress((void**)&pQ,   g_pQ);
    cudaGetSymbolAddress((void**)&sc0,  g_scale0);
    cudaGetSymbolAddress((void**)&sh0,  g_shift0);
    cudaGetSymbolAddress((void**)&sc1,  g_scale1);
    cudaGetSymbolAddress((void**)&sh1,  g_shift1);
    cudaGetSymbolAddress((void**)&wqkh, g_wqkh);
    cudaGetSymbolAddress((void**)&wqkl, g_wqkl);
    cudaGetSymbolAddress((void**)&wvh,  g_wvh);
    cudaGetSymbolAddress((void**)&wvl,  g_wvl);
    cudaGetSymbolAddress((void**)&w1h,  g_w1h);
    cudaGetSymbolAddress((void**)&w1l,  g_w1l);
    cudaGetSymbolAddress((void**)&bqk,  g_bqk);

    const int ST64  = 2 * (2 * 128 * 80 + 2 * 64 * 80);    // 61440
    const int ST128 = 2 * (2 * 128 * 80 + 2 * 128 * 80);   // 81920
    cudaFuncSetAttribute(pv_kernel, cudaFuncAttributeMaxDynamicSharedMemorySize, PV_SMEM);
    cudaFuncSetAttribute(mma_gemm<64, 0>,  cudaFuncAttributeMaxDynamicSharedMemorySize, ST64);
    cudaFuncSetAttribute(mma_gemm<64, 1>,  cudaFuncAttributeMaxDynamicSharedMemorySize, ST64);
    cudaFuncSetAttribute(mma_gemm<128, 0>, cudaFuncAttributeMaxDynamicSharedMemorySize, ST128);
    cudaFuncSetAttribute(mma_gemm<128, 2>, cudaFuncAttributeMaxDynamicSharedMemorySize, ST128);

    // 1) pre-linear: x0 = z @ w_pre^T + b_pre   [64 x 8192], K=128
    sgemm_kernel<<<dim3(8192 / 128, 1, 1), 256>>>(
        z, w_pre, b_pre, x0, NB, CIN * LL, ZD, ZD, ZD, CIN * LL);

    // 2) weight prep (independent)
    wprep_kernel<<<384, 256>>>(wq, wk, wv, w1, bq, bk, bqk,
                               wqkh, wqkl, wvh, wvl, w1h, w1l);

    // 3) BN0 via x0 moments (2 MB) -> analytic scale/shift
    xstats_partial<<<64, 256>>>(x0, pS);
    xstats_final<<<1, 256>>>(pS, w0, b0, g0, be0, sc0, sh0);

    // 4) fused conv0 + BN0 + ReLU -> xah/xal bf16
    conv0_fused<<<GG / 16, 256>>>(x0, w0, b0, sc0, sh0, xah, xal);

    // 5) Q+K projection (split out): [g][64], K=256
    mma_gemm<64, 1><<<dim3(1, GG / 128, 1), 256, ST64>>>(
        xah, xal, C0C, 0, wqkh, wqkl, C0C, 0, bqk,
        nullptr, qkh, qkl, 64, 0, C0C);

    // 6) V projection with fused transpose -> vTh bf16 (single), K=256
    mma_gemm<128, 2><<<dim3(2, GG / 128, 1), 256, ST128>>>(
        xah, xal, C0C, 0, wvh, wvl, C0C, 0, bv,
        nullptr, vTh, nullptr, 0, 0, C0C);

    // 7) energy: E[b] = Q[b] K[b]^T  (M=N=1024, K=32), batched over 64
    mma_gemm<128, 0><<<dim3(8, 8, NB), 256, ST128>>>(
        qkh, qkl, 64, (long long)LL * 64,
        qkh + 32, qkl + 32, 64, (long long)LL * 64,
        nullptr, E, nullptr, nullptr, LL, (long long)LL * LL, CQKC);

    // 8) row softmax -> single bf16 P
    softmax_kernel<<<GG, 256>>>(E, Eh);

    // 9) att = gamma * (P @ V) + (xah+xal)  -> bf16 hi/lo (single-bf16 mma)
    pv_kernel<<<dim3(8, 2, NB), 256, PV_SMEM>>>(Eh, vTh, xah, xal,
                                                gamma, atth, attl);

    // 10) conv1: x1 = att @ w1^T + b1  [g][64], K=256
    mma_gemm<64, 0><<<dim3(1, GG / 128, 1), 256, ST64>>>(
        atth, attl, C0C, 0, w1h, w1l, C0C, 0, b1,
        x1, nullptr, nullptr, FFC, 0, C0C);

    // 11) BN1 stats
    bnstats_partial<<<dim3(64, FFC / 32), 256>>>(x1, FFC, pS, pQ);
    bnfinalize<<<1, 64>>>(pS, pQ, g1, be1, sc1, sh1, FFC);

    // 12) fused BN1 + relu + w_out conv -> out [b][8][1024]
    final_kernel<<<GG / 32, 256>>>(x1, sc1, sh1, w_out, b_out, out);

    (void)in_sizes; (void)n_in; (void)out_size;
}

// round 11
// speedup vs baseline: 1.8964x; 1.1965x over previous
#include <cuda_runtime.h>
#include <cuda_bf16.h>

// ---------------------------------------------------------------------------
// Problem constants
// ---------------------------------------------------------------------------
#define NB    64          // batch
#define ZD    128         // latent dim
#define CIN   8
#define LL    1024        // W*H
#define C0C   256         // attention channels
#define CQKC  32
#define FFC   64          // filters
#define GG    65536       // NB * LL (total positions)

// ---------------------------------------------------------------------------
// Device scratch (allocation-free rule: __device__ globals)
// ---------------------------------------------------------------------------
__device__ __align__(16) float g_x0 [NB * CIN * LL];              //  2 MB
__device__ __align__(16) __nv_bfloat16 g_xah[(size_t)GG * C0C];   // 32 MB
__device__ __align__(16) __nv_bfloat16 g_xal[(size_t)GG * C0C];   // 32 MB
__device__ __align__(16) __nv_bfloat16 g_qkh[(size_t)GG * 64];    //  8 MB [g][q32|k32] hi
__device__ __align__(16) __nv_bfloat16 g_qkl[(size_t)GG * 64];    //  8 MB lo
__device__ __align__(16) __nv_bfloat16 g_vTh[(size_t)NB * C0C * LL]; // 32 MB V^T bf16
__device__ __align__(16) __nv_bfloat16 g_atth[(size_t)GG * C0C];  // 32 MB att hi
__device__ __align__(16) __nv_bfloat16 g_attl[(size_t)GG * C0C];  // 32 MB att lo
__device__ __align__(16) float g_x1 [(size_t)GG * FFC];           // 16 MB
// split weights
__device__ __align__(16) __nv_bfloat16 g_wqkh[64 * C0C],  g_wqkl[64 * C0C];
__device__ __align__(16) __nv_bfloat16 g_wvh [C0C * C0C], g_wvl [C0C * C0C];
__device__ __align__(16) __nv_bfloat16 g_w1h [FFC * C0C], g_w1l [FFC * C0C];
__device__ __align__(16) float g_bqk[64];
__device__ float g_pS[C0C * 64];           // reused: x0 moment partials [64][44]
__device__ float g_pQ[C0C * 64];
__device__ __align__(16) float g_scale0[C0C], g_shift0[C0C];
__device__ __align__(16) float g_scale1[FFC], g_shift1[FFC];

// ---------------------------------------------------------------------------
// PTX helpers (sm_80-level only — harness ptxas targets plain sm_100)
// ---------------------------------------------------------------------------
__device__ __forceinline__ unsigned smem_u32(const void* p) {
    unsigned a;
    asm("{ .reg .u64 t; cvta.to.shared.u64 t, %1; cvt.u32.u64 %0, t; }" : "=r"(a) : "l"(p));
    return a;
}
__device__ __forceinline__ void cpasync16(unsigned d, const void* s) {
    asm volatile("cp.async.cg.shared.global [%0], [%1], 16;" :: "r"(d), "l"(s));
}
#define CP_COMMIT() asm volatile("cp.async.commit_group;" ::: "memory")
#define CP_WAIT0()  asm volatile("cp.async.wait_group 0;" ::: "memory")
#define CP_WAIT1()  asm volatile("cp.async.wait_group 1;" ::: "memory")

__device__ __forceinline__ void ldsm_x4(unsigned& r0, unsigned& r1,
                                        unsigned& r2, unsigned& r3, unsigned addr) {
    asm volatile("ldmatrix.sync.aligned.m8n8.x4.shared.b16 {%0,%1,%2,%3}, [%4];"
                 : "=r"(r0), "=r"(r1), "=r"(r2), "=r"(r3) : "r"(addr));
}
__device__ __forceinline__ void mma_bf16(float* c, const unsigned* a, const unsigned* b) {
    asm volatile("mma.sync.aligned.m16n8k16.row.col.f32.bf16.bf16.f32 "
                 "{%0,%1,%2,%3}, {%4,%5,%6,%7}, {%8,%9}, {%0,%1,%2,%3};"
                 : "+f"(c[0]), "+f"(c[1]), "+f"(c[2]), "+f"(c[3])
                 : "r"(a[0]), "r"(a[1]), "r"(a[2]), "r"(a[3]), "r"(b[0]), "r"(b[1]));
}
__device__ __forceinline__ void bf16split(float v, __nv_bfloat16& h, __nv_bfloat16& l) {
    h = __float2bfloat16(v);
    l = __float2bfloat16(v - __bfloat162float(h));
}
__device__ __forceinline__ unsigned pack2(__nv_bfloat16 a, __nv_bfloat16 b) {
    return ((unsigned)__bfloat16_as_ushort(b) << 16) | __bfloat16_as_ushort(a);
}
__device__ __forceinline__ unsigned pack2f(float a, float b) {
    return pack2(__float2bfloat16(a), __float2bfloat16(b));
}

// ---------------------------------------------------------------------------
// Generic split-bf16 MMA GEMM.
//   OUT_MODE 0: fp32 C (+bias)
//   OUT_MODE 1: bf16 hi/lo split C (+bias)
//   OUT_MODE 2: V-projection: stage to smem, coalesced transposed vTh write.
// ---------------------------------------------------------------------------
template<int BN>
__device__ __forceinline__ void mm_load(unsigned dst, int t,
    const char* Ah, const char* Al, const char* Bh, const char* Bl,
    int ldaB, int ldbB, int m0, int n0, int kByte)
{
    constexpr int AOP = 128 * 80, BOP = BN * 80;
    constexpr int TCA = 1024, TC = TCA + BN * 8;
#pragma unroll
    for (int u = 0; u < TC / 256; u++) {
        int i = t + u * 256;
        if (i < TCA) {
            int half = i >> 9, row = (i >> 2) & 127, c = i & 3;
            const char* s = half ? Al : Ah;
            cpasync16(dst + half * AOP + row * 80 + c * 16,
                      s + (size_t)(m0 + row) * ldaB + kByte + c * 16);
        } else {
            int j = i - TCA;
            int half = j / (BN * 4), row = (j >> 2) % BN, c = j & 3;
            const char* s = half ? Bl : Bh;
            cpasync16(dst + 2 * AOP + half * BOP + row * 80 + c * 16,
                      s + (size_t)(n0 + row) * ldbB + kByte + c * 16);
        }
    }
}

template<int BN, int OUT_MODE>
__global__ __launch_bounds__(256, 1)
void mma_gemm(const __nv_bfloat16* __restrict__ Ah, const __nv_bfloat16* __restrict__ Al,
              int lda, long long sA,
              const __nv_bfloat16* __restrict__ Bh, const __nv_bfloat16* __restrict__ Bl,
              int ldb, long long sB,
              const float* __restrict__ bias,
              float* __restrict__ C,
              __nv_bfloat16* __restrict__ Ch, __nv_bfloat16* __restrict__ Cl,
              int ldc, long long sC, int K)
{
    constexpr int AOP = 128 * 80, BOP = BN * 80;
    constexpr int ST = 2 * AOP + 2 * BOP;
    constexpr int NW = BN / 4;
    constexpr int NI = NW / 8;
    constexpr int NGI = NW / 16;

    extern __shared__ char smem[];
    const unsigned sb = smem_u32(smem);
    const int t = threadIdx.x;
    const int n0 = blockIdx.x * BN, m0 = blockIdx.y * 128, z = blockIdx.z;

    const char* cAh = (const char*)(Ah + (size_t)z * sA);
    const char* cAl = (const char*)(Al + (size_t)z * sA);
    const char* cBh = (const char*)(Bh + (size_t)z * sB);
    const char* cBl = (const char*)(Bl + (size_t)z * sB);
    const int ldaB = lda * 2, ldbB = ldb * 2;

    const int w = t >> 5, lane = t & 31;
    const int wm = (w & 1) * 64, wn = (w >> 1) * NW;
    const int aRowSel = (lane & 7) + ((lane >> 3) & 1) * 8;
    const int aChunk  = (lane >> 4) * 16;
    const int bRowSel = (lane & 7) + (lane >> 4) * 8;
    const int bChunk  = ((lane >> 3) & 1) * 16;

    float acc[4][NI][4];
#pragma unroll
    for (int mi = 0; mi < 4; mi++)
#pragma unroll
        for (int ni = 0; ni < NI; ni++)
#pragma unroll
            for (int r = 0; r < 4; r++) acc[mi][ni][r] = 0.f;

    const int nst = K / 32;
    mm_load<BN>(sb, t, cAh, cAl, cBh, cBl, ldaB, ldbB, m0, n0, 0);
    CP_COMMIT();

    for (int s = 0; s < nst; s++) {
        if (s + 1 < nst) {
            mm_load<BN>(sb + ((s + 1) & 1) * ST, t, cAh, cAl, cBh, cBl,
                        ldaB, ldbB, m0, n0, (s + 1) * 64);
            CP_COMMIT();
            CP_WAIT1();
        } else {
            CP_WAIT0();
        }
        __syncthreads();

        const unsigned base = sb + (s & 1) * ST;
#pragma unroll
        for (int s2 = 0; s2 < 2; s2++) {
            unsigned ah[4][4], al[4][4];
#pragma unroll
            for (int mi = 0; mi < 4; mi++) {
                unsigned ar = base + (wm + mi * 16 + aRowSel) * 80 + s2 * 32 + aChunk;
                ldsm_x4(ah[mi][0], ah[mi][1], ah[mi][2], ah[mi][3], ar);
                ldsm_x4(al[mi][0], al[mi][1], al[mi][2], al[mi][3], ar + AOP);
            }
            unsigned bh[NI][2], bl[NI][2];
#pragma unroll
            for (int ngi = 0; ngi < NGI; ngi++) {
                unsigned br = base + 2 * AOP + (wn + ngi * 16 + bRowSel) * 80 + s2 * 32 + bChunk;
                unsigned r0, r1, r2, r3;
                ldsm_x4(r0, r1, r2, r3, br);
                bh[2 * ngi][0] = r0; bh[2 * ngi][1] = r1;
                bh[2 * ngi + 1][0] = r2; bh[2 * ngi + 1][1] = r3;
                ldsm_x4(r0, r1, r2, r3, br + BOP);
                bl[2 * ngi][0] = r0; bl[2 * ngi][1] = r1;
                bl[2 * ngi + 1][0] = r2; bl[2 * ngi + 1][1] = r3;
            }
#pragma unroll
            for (int mi = 0; mi < 4; mi++)
#pragma unroll
                for (int ni = 0; ni < NI; ni++) {
                    mma_bf16(acc[mi][ni], ah[mi], bh[ni]);
                    mma_bf16(acc[mi][ni], ah[mi], bl[ni]);
                    mma_bf16(acc[mi][ni], al[mi], bh[ni]);
                }
        }
        __syncthreads();
    }

    const int g = lane >> 2, tg = lane & 3;

    if (OUT_MODE == 2) {
        float* Ss = (float*)smem;
#pragma unroll
        for (int mi = 0; mi < 4; mi++)
#pragma unroll
            for (int ni = 0; ni < NI; ni++) {
                int col = wn + ni * 8 + 2 * tg;
                float b0 = __ldg(bias + n0 + col), b1 = __ldg(bias + n0 + col + 1);
#pragma unroll
                for (int half = 0; half < 2; half++) {
                    int row = wm + mi * 16 + half * 8 + g;
                    Ss[row * 132 + col]     = acc[mi][ni][2 * half + 0] + b0;
                    Ss[row * 132 + col + 1] = acc[mi][ni][2 * half + 1] + b1;
                }
            }
        __syncthreads();
        const int b = m0 >> 10, l0 = m0 & 1023;
        const int m = lane * 4;
#pragma unroll
        for (int i = 0; i < 16; i++) {
            int n = w * 16 + i;
            float v0 = Ss[(m + 0) * 132 + n];
            float v1 = Ss[(m + 1) * 132 + n];
            float v2 = Ss[(m + 2) * 132 + n];
            float v3 = Ss[(m + 3) * 132 + n];
            size_t ob = ((size_t)(b * 256 + n0 + n)) * 1024 + l0 + m;
            uint2 uh;
            uh.x = pack2f(v0, v1);
            uh.y = pack2f(v2, v3);
            *(uint2*)(Ch + ob) = uh;
        }
        return;
    }

#pragma unroll
    for (int mi = 0; mi < 4; mi++) {
#pragma unroll
        for (int ni = 0; ni < NI; ni++) {
            int gr = m0 + wm + mi * 16 + g;
            int gc = n0 + wn + ni * 8 + 2 * tg;
            float b0 = 0.f, b1 = 0.f;
            if (bias) { b0 = __ldg(bias + gc); b1 = __ldg(bias + gc + 1); }
#pragma unroll
            for (int half = 0; half < 2; half++) {
                size_t idx = (size_t)z * sC + (size_t)(gr + half * 8) * ldc + gc;
                float v0 = acc[mi][ni][2 * half + 0] + b0;
                float v1 = acc[mi][ni][2 * half + 1] + b1;
                if (OUT_MODE == 1) {
                    __nv_bfloat16 h0, l0b, h1, l1b;
                    bf16split(v0, h0, l0b); bf16split(v1, h1, l1b);
                    *(__nv_bfloat162*)(Ch + idx) = __halves2bfloat162(h0, h1);
                    *(__nv_bfloat162*)(Cl + idx) = __halves2bfloat162(l0b, l1b);
                } else {
                    float2 o; o.x = v0; o.y = v1;
                    *(float2*)(C + idx) = o;
                }
            }
        }
    }
}

// ---------------------------------------------------------------------------
// Fused flash attention: att = gamma * softmax(Q K^T) V + (xah+xal)
// Grid (2 n-halves, 8 m-tiles, 64 b); 256 threads, 8 warps of 16 m-rows.
// Q split resident; per 128-j chunk: S = QK^T (3-pass split), register online
// softmax (shfl over tg lanes), P (C-frag == A-frag identity) @ V accumulate.
// smem: Q 2x10240 | 2 chunk buffers x (K 2x10240 + V 4x10240) = 143360 B.
// ---------------------------------------------------------------------------
#define FA_CB   20480
#define FA_CBS  61440
#define FA_SMEM 143360

__device__ __forceinline__ void fa_load_q(unsigned sb, int t,
                                          const char* gQh, const char* gQl)
{
#pragma unroll
    for (int u = 0; u < 4; u++) {
        int i = t + u * 256;
        int half = i >> 9, row = (i >> 2) & 127, c = i & 3;
        const char* s = half ? gQl : gQh;
        cpasync16(sb + half * 10240 + row * 80 + c * 16,
                  s + (size_t)row * 128 + c * 16);
    }
}

__device__ __forceinline__ void fa_load_chunk(unsigned dst, int t,
    const char* gKh, const char* gKl, const char* gV, int ch)
{
#pragma unroll
    for (int u = 0; u < 4; u++) {     // K split: 2 x 128 rows x 64B
        int i = t + u * 256;
        int half = i >> 9, row = (i >> 2) & 127, c = i & 3;
        const char* s = half ? gKl : gKh;
        cpasync16(dst + half * 10240 + row * 80 + c * 16,
                  s + (size_t)(ch * 128 + row) * 128 + c * 16);
    }
#pragma unroll
    for (int u = 0; u < 8; u++) {     // V: 4 k-groups x 128 n x 64B
        int i = t + u * 256;
        int c = i & 3, n = (i >> 2) & 127, kg = i >> 9;
        cpasync16(dst + 20480 + kg * 10240 + n * 80 + c * 16,
                  gV + (size_t)n * 2048 + ch * 256 + kg * 64 + c * 16);
    }
}

__global__ __launch_bounds__(256, 1)
void fa_kernel(const __nv_bfloat16* __restrict__ qkh, const __nv_bfloat16* __restrict__ qkl,
               const __nv_bfloat16* __restrict__ vTh,
               const __nv_bfloat16* __restrict__ resh, const __nv_bfloat16* __restrict__ resl,
               const float* __restrict__ gammaPtr,
               __nv_bfloat16* __restrict__ atth, __nv_bfloat16* __restrict__ attl)
{
    extern __shared__ char smem[];
    const unsigned sb = smem_u32(smem);
    const int t = threadIdx.x;
    const int n0 = blockIdx.x * 128, m0 = blockIdx.y * 128, b = blockIdx.z;

    const char* gQh = (const char*)qkh + (size_t)(b * 1024 + m0) * 128;
    const char* gQl = (const char*)qkl + (size_t)(b * 1024 + m0) * 128;
    const char* gKh = (const char*)qkh + (size_t)(b * 1024) * 128 + 64;
    const char* gKl = (const char*)qkl + (size_t)(b * 1024) * 128 + 64;
    const char* gV  = (const char*)vTh + (size_t)(b * 256 + n0) * 2048;

    const int w = t >> 5, lane = t & 31;
    const int wm = w * 16;
    const int g = lane >> 2, tg = lane & 3;
    const int aRowSel = (lane & 7) + ((lane >> 3) & 1) * 8;
    const int aChunk  = (lane >> 4) * 16;
    const int bRowSel = (lane & 7) + (lane >> 4) * 8;
    const int bChunk  = ((lane >> 3) & 1) * 16;

    float oacc[16][4];
#pragma unroll
    for (int ni = 0; ni < 16; ni++)
#pragma unroll
        for (int r = 0; r < 4; r++) oacc[ni][r] = 0.f;
    float m0r = -1e30f, m1r = -1e30f, z0r = 0.f, z1r = 0.f;

    fa_load_q(sb, t, gQh, gQl);
    fa_load_chunk(sb + FA_CB, t, gKh, gKl, gV, 0);
    CP_COMMIT();

    for (int ch = 0; ch < 8; ch++) {
        if (ch + 1 < 8) {
            fa_load_chunk(sb + FA_CB + ((ch + 1) & 1) * FA_CBS, t, gKh, gKl, gV, ch + 1);
            CP_COMMIT();
            CP_WAIT1();
        } else {
            CP_WAIT0();
        }
        __syncthreads();

        const unsigned kb = sb + FA_CB + (ch & 1) * FA_CBS;

        // ---- S = Q K_chunk^T (3-pass split), 16m x 128j per warp ----
        float sacc[16][4];
#pragma unroll
        for (int ni = 0; ni < 16; ni++)
#pragma unroll
            for (int r = 0; r < 4; r++) sacc[ni][r] = 0.f;

#pragma unroll
        for (int s2 = 0; s2 < 2; s2++) {
            unsigned qh[4], ql[4];
            unsigned ar = sb + (wm + aRowSel) * 80 + s2 * 32 + aChunk;
            ldsm_x4(qh[0], qh[1], qh[2], qh[3], ar);
            ldsm_x4(ql[0], ql[1], ql[2], ql[3], ar + 10240);
#pragma unroll
            for (int ngi = 0; ngi < 8; ngi++) {
                unsigned br = kb + (ngi * 16 + bRowSel) * 80 + s2 * 32 + bChunk;
                unsigned r0, r1, r2, r3;
                ldsm_x4(r0, r1, r2, r3, br);
                unsigned bh0[2] = { r0, r1 }, bh1[2] = { r2, r3 };
                ldsm_x4(r0, r1, r2, r3, br + 10240);
                unsigned bl0[2] = { r0, r1 }, bl1[2] = { r2, r3 };
                mma_bf16(sacc[2 * ngi],     qh, bh0);
                mma_bf16(sacc[2 * ngi + 1], qh, bh1);
                mma_bf16(sacc[2 * ngi],     qh, bl0);
                mma_bf16(sacc[2 * ngi + 1], qh, bl1);
                mma_bf16(sacc[2 * ngi],     ql, bh0);
                mma_bf16(sacc[2 * ngi + 1], ql, bh1);
            }
        }

        // ---- online softmax (register + shfl over the 4 tg lanes) ----
        float cm0 = -1e30f, cm1 = -1e30f;
#pragma unroll
        for (int ni = 0; ni < 16; ni++) {
            cm0 = fmaxf(cm0, fmaxf(sacc[ni][0], sacc[ni][1]));
            cm1 = fmaxf(cm1, fmaxf(sacc[ni][2], sacc[ni][3]));
        }
        cm0 = fmaxf(cm0, __shfl_xor_sync(0xffffffffu, cm0, 1));
        cm0 = fmaxf(cm0, __shfl_xor_sync(0xffffffffu, cm0, 2));
        cm1 = fmaxf(cm1, __shfl_xor_sync(0xffffffffu, cm1, 1));
        cm1 = fmaxf(cm1, __shfl_xor_sync(0xffffffffu, cm1, 2));

        float nm0 = fmaxf(m0r, cm0), nm1 = fmaxf(m1r, cm1);
        float sc0 = __expf(m0r - nm0), sc1 = __expf(m1r - nm1);
        float cs0 = 0.f, cs1 = 0.f;
#pragma unroll
        for (int ni = 0; ni < 16; ni++) {
            sacc[ni][0] = __expf(sacc[ni][0] - nm0);
            sacc[ni][1] = __expf(sacc[ni][1] - nm0);
            sacc[ni][2] = __expf(sacc[ni][2] - nm1);
            sacc[ni][3] = __expf(sacc[ni][3] - nm1);
            cs0 += sacc[ni][0] + sacc[ni][1];
            cs1 += sacc[ni][2] + sacc[ni][3];
        }
        cs0 += __shfl_xor_sync(0xffffffffu, cs0, 1);
        cs0 += __shfl_xor_sync(0xffffffffu, cs0, 2);
        cs1 += __shfl_xor_sync(0xffffffffu, cs1, 1);
        cs1 += __shfl_xor_sync(0xffffffffu, cs1, 2);

        z0r = z0r * sc0 + cs0;
        z1r = z1r * sc1 + cs1;
        m0r = nm0; m1r = nm1;
#pragma unroll
        for (int ni = 0; ni < 16; ni++) {
            oacc[ni][0] *= sc0; oacc[ni][1] *= sc0;
            oacc[ni][2] *= sc1; oacc[ni][3] *= sc1;
        }

        // ---- O += P_chunk @ V_chunk (P from C-frag, bf16) ----
#pragma unroll
        for (int u = 0; u < 8; u++) {
            unsigned pa[4];
            pa[0] = pack2f(sacc[2 * u][0],     sacc[2 * u][1]);
            pa[1] = pack2f(sacc[2 * u][2],     sacc[2 * u][3]);
            pa[2] = pack2f(sacc[2 * u + 1][0], sacc[2 * u + 1][1]);
            pa[3] = pack2f(sacc[2 * u + 1][2], sacc[2 * u + 1][3]);
            const unsigned vgb = kb + 20480 + (u >> 1) * 10240;
            const int s2v = u & 1;
#pragma unroll
            for (int ngi = 0; ngi < 8; ngi++) {
                unsigned br = vgb + (ngi * 16 + bRowSel) * 80 + s2v * 32 + bChunk;
                unsigned r0, r1, r2, r3;
                ldsm_x4(r0, r1, r2, r3, br);
                unsigned bv0[2] = { r0, r1 }, bv1[2] = { r2, r3 };
                mma_bf16(oacc[2 * ngi],     pa, bv0);
                mma_bf16(oacc[2 * ngi + 1], pa, bv1);
            }
        }
        __syncthreads();
    }

    // ---- epilogue: att = gamma * O / z + (xah + xal) -> bf16 hi/lo ----
    const float gam = __ldg(gammaPtr);
    const float gz0 = gam / z0r, gz1 = gam / z1r;
    const int gr0 = b * 1024 + m0 + wm + g;
#pragma unroll
    for (int ni = 0; ni < 16; ni++) {
        int gc = n0 + ni * 8 + 2 * tg;
        size_t i0 = (size_t)gr0 * 256 + gc;
        size_t i1 = i0 + (size_t)8 * 256;
        __nv_bfloat162 rh0 = *(const __nv_bfloat162*)(resh + i0);
        __nv_bfloat162 rl0 = *(const __nv_bfloat162*)(resl + i0);
        __nv_bfloat162 rh1 = *(const __nv_bfloat162*)(resh + i1);
        __nv_bfloat162 rl1 = *(const __nv_bfloat162*)(resl + i1);
        float v0 = fmaf(gz0, oacc[ni][0], __bfloat162float(rh0.x) + __bfloat162float(rl0.x));
        float v1 = fmaf(gz0, oacc[ni][1], __bfloat162float(rh0.y) + __bfloat162float(rl0.y));
        float v2 = fmaf(gz1, oacc[ni][2], __bfloat162float(rh1.x) + __bfloat162float(rl1.x));
        float v3 = fmaf(gz1, oacc[ni][3], __bfloat162float(rh1.y) + __bfloat162float(rl1.y));
        __nv_bfloat16 h0, l0, h1, l1;
        bf16split(v0, h0, l0); bf16split(v1, h1, l1);
        *(__nv_bfloat162*)(atth + i0) = __halves2bfloat162(h0, h1);
        *(__nv_bfloat162*)(attl + i0) = __halves2bfloat162(l0, l1);
        bf16split(v2, h0, l0); bf16split(v3, h1, l1);
        *(__nv_bfloat162*)(atth + i1) = __halves2bfloat162(h0, h1);
        *(__nv_bfloat162*)(attl + i1) = __halves2bfloat162(l0, l1);
    }
}

// ---------------------------------------------------------------------------
// SIMT SGEMM (only for tiny pre-linear), B stored [N,K] row-major
// ---------------------------------------------------------------------------
__global__ __launch_bounds__(256)
void sgemm_kernel(const float* __restrict__ A, const float* __restrict__ Bm,
                  const float* __restrict__ bias, float* __restrict__ C,
                  int M, int N, int K, int lda, int ldb, int ldc)
{
    __shared__ float As[8][128];
    __shared__ float Bs[8][128];

    const int tid = threadIdx.x;
    const int m0 = blockIdx.y * 128;
    const int n0 = blockIdx.x * 128;

    const int aRow = tid >> 1;
    const int aK   = (tid & 1) << 2;
    const int tr = (tid >> 4) << 3;
    const int tc = (tid & 15) << 3;

    const bool aOK = (m0 + aRow) < M;
    const bool bOK = (n0 + aRow) < N;
    const float* aPtr = A + (long long)(m0 + aRow) * lda + aK;
    const float* bPtr = Bm + (long long)(n0 + aRow) * ldb + aK;

    float acc[8][8];
#pragma unroll
    for (int i = 0; i < 8; i++)
#pragma unroll
        for (int j = 0; j < 8; j++) acc[i][j] = 0.f;

    float4 aReg = make_float4(0.f, 0.f, 0.f, 0.f);
    float4 bReg = make_float4(0.f, 0.f, 0.f, 0.f);
    if (aOK) aReg = *(const float4*)aPtr;
    if (bOK) bReg = *(const float4*)bPtr;

    for (int k0 = 0; k0 < K; k0 += 8) {
        As[aK + 0][aRow] = aReg.x; As[aK + 1][aRow] = aReg.y;
        As[aK + 2][aRow] = aReg.z; As[aK + 3][aRow] = aReg.w;
        Bs[aK + 0][aRow] = bReg.x; Bs[aK + 1][aRow] = bReg.y;
        Bs[aK + 2][aRow] = bReg.z; Bs[aK + 3][aRow] = bReg.w;
        __syncthreads();

        if (k0 + 8 < K) {
            aReg = make_float4(0.f, 0.f, 0.f, 0.f);
            bReg = make_float4(0.f, 0.f, 0.f, 0.f);
            if (aOK) aReg = *(const float4*)(aPtr + (k0 + 8));
            if (bOK) bReg = *(const float4*)(bPtr + (k0 + 8));
        }

#pragma unroll
        for (int kk = 0; kk < 8; kk++) {
            float ar[8], br[8];
            *(float4*)&ar[0] = *(const float4*)&As[kk][tr];
            *(float4*)&ar[4] = *(const float4*)&As[kk][tr + 4];
            *(float4*)&br[0] = *(const float4*)&Bs[kk][tc];
            *(float4*)&br[4] = *(const float4*)&Bs[kk][tc + 4];
#pragma unroll
            for (int i = 0; i < 8; i++)
#pragma unroll
                for (int j = 0; j < 8; j++)
                    acc[i][j] = fmaf(ar[i], br[j], acc[i][j]);
        }
        __syncthreads();
    }

#pragma unroll
    for (int i = 0; i < 8; i++) {
        int gm = m0 + tr + i;
        if (gm < M) {
#pragma unroll
            for (int j = 0; j < 8; j += 4) {
                int gn = n0 + tc + j;
                if (gn < N) {
                    float4 o;
                    o.x = acc[i][j]; o.y = acc[i][j + 1];
                    o.z = acc[i][j + 2]; o.w = acc[i][j + 3];
                    if (bias) {
                        o.x += __ldg(bias + gn);     o.y += __ldg(bias + gn + 1);
                        o.z += __ldg(bias + gn + 2); o.w += __ldg(bias + gn + 3);
                    }
                    *(float4*)(C + (long long)gm * ldc + gn) = o;
                }
            }
        }
    }
}

// ---------------------------------------------------------------------------
// Weight prep: split wq||wk, wv, w1 into bf16 hi/lo; merge bq||bk
// ---------------------------------------------------------------------------
__global__ void wprep_kernel(const float* __restrict__ wq, const float* __restrict__ wk,
                             const float* __restrict__ wv, const float* __restrict__ w1,
                             const float* __restrict__ bq, const float* __restrict__ bk,
                             float* __restrict__ bqk,
                             __nv_bfloat16* __restrict__ wqkh, __nv_bfloat16* __restrict__ wqkl,
                             __nv_bfloat16* __restrict__ wvh,  __nv_bfloat16* __restrict__ wvl,
                             __nv_bfloat16* __restrict__ w1h,  __nv_bfloat16* __restrict__ w1l)
{
    int i = blockIdx.x * 256 + threadIdx.x;
    if (i < 16384) {
        int n = i >> 8, k = i & 255;
        float v = (n < 32) ? wq[n * 256 + k] : wk[(n - 32) * 256 + k];
        __nv_bfloat16 h, l;
        bf16split(v, h, l);
        wqkh[i] = h; wqkl[i] = l;
    } else if (i < 81920) {
        int j = i - 16384;
        __nv_bfloat16 h, l;
        bf16split(wv[j], h, l);
        wvh[j] = h; wvl[j] = l;
    } else if (i < 98304) {
        int j = i - 81920;
        __nv_bfloat16 h, l;
        bf16split(w1[j], h, l);
        w1h[j] = h; w1l[j] = l;
    }
    if (i < 64) bqk[i] = (i < 32) ? bq[i] : bk[i - 32];
}

// ---------------------------------------------------------------------------
// x0 moment stats (8 + 36 vals) per batch; deterministic reductions.
// ---------------------------------------------------------------------------
__global__ __launch_bounds__(256)
void xstats_partial(const float* __restrict__ x0, float* __restrict__ pX)
{
    const int b = blockIdx.x, t = threadIdx.x;
    const int warp = t >> 5, lane = t & 31;
    float a[44];
#pragma unroll
    for (int j = 0; j < 44; j++) a[j] = 0.f;

#pragma unroll
    for (int r = 0; r < 4; r++) {
        int l = t + r * 256;
        float v[CIN];
#pragma unroll
        for (int c = 0; c < CIN; c++)
            v[c] = x0[b * (CIN * LL) + c * LL + l];
#pragma unroll
        for (int c = 0; c < CIN; c++) a[c] += v[c];
        int idx = CIN;
#pragma unroll
        for (int c1 = 0; c1 < CIN; c1++)
#pragma unroll
            for (int c2 = c1; c2 < CIN; c2++)
                a[idx++] = fmaf(v[c1], v[c2], a[idx]);
    }
#pragma unroll
    for (int j = 0; j < 44; j++)
#pragma unroll
        for (int o = 16; o; o >>= 1)
            a[j] += __shfl_xor_sync(0xffffffffu, a[j], o);

    __shared__ float ws[8][44];
    if (lane == 0)
#pragma unroll
        for (int j = 0; j < 44; j++) ws[warp][j] = a[j];
    __syncthreads();
    if (t < 44) {
        float s = ws[0][t];
#pragma unroll
        for (int w = 1; w < 8; w++) s += ws[w][t];
        pX[b * 44 + t] = s;
    }
}

__global__ void xstats_final(const float* __restrict__ pX,
                             const float* __restrict__ w0, const float* __restrict__ b0,
                             const float* __restrict__ g0, const float* __restrict__ be0,
                             float* __restrict__ scale, float* __restrict__ shift)
{
    __shared__ float mom[44];
    __shared__ float mu[CIN];
    __shared__ float cov[CIN][CIN];
    const int t = threadIdx.x;
    if (t < 44) {
        float s = 0.f;
        for (int b = 0; b < 64; b++) s += pX[b * 44 + t];
        mom[t] = s;
    }
    __syncthreads();
    if (t == 0) {
        const float inv = 1.f / 65536.f;
        for (int c = 0; c < CIN; c++) mu[c] = mom[c] * inv;
        int idx = CIN;
        for (int c1 = 0; c1 < CIN; c1++)
            for (int c2 = c1; c2 < CIN; c2++) {
                float cv = mom[idx++] * inv - mu[c1] * mu[c2];
                cov[c1][c2] = cv; cov[c2][c1] = cv;
            }
    }
    __syncthreads();
    float w[CIN];
#pragma unroll
    for (int c = 0; c < CIN; c++) w[c] = w0[t * CIN + c];
    float mean = __ldg(b0 + t);
#pragma unroll
    for (int c = 0; c < CIN; c++) mean = fmaf(w[c], mu[c], mean);
    float var = 0.f;
#pragma unroll
    for (int c1 = 0; c1 < CIN; c1++) {
        float acc = 0.f;
#pragma unroll
        for (int c2 = 0; c2 < CIN; c2++) acc = fmaf(w[c2], cov[c1][c2], acc);
        var = fmaf(w[c1], acc, var);
    }
    float sc = __ldg(g0 + t) * rsqrtf(var + 1e-5f);
    scale[t] = sc;
    shift[t] = __ldg(be0 + t) - mean * sc;
}

// ---------------------------------------------------------------------------
// Fused conv0 + BN0 + ReLU -> xah/xal bf16
// ---------------------------------------------------------------------------
__global__ __launch_bounds__(256)
void conv0_fused(const float* __restrict__ x0, const float* __restrict__ w0,
                 const float* __restrict__ b0,
                 const float* __restrict__ sc0, const float* __restrict__ sh0,
                 __nv_bfloat16* __restrict__ xah, __nv_bfloat16* __restrict__ xal)
{
    __shared__ float ws[C0C * CIN];
    __shared__ float xs[CIN][16];
    const int t = threadIdx.x;
    for (int i = t; i < C0C * CIN; i += 256) ws[i] = w0[i];
    const int g0 = blockIdx.x * 16;
    const int b = g0 >> 10, l0 = g0 & 1023;
    if (t < 128) {
        int c = t >> 4, i = t & 15;
        xs[c][i] = x0[b * (CIN * LL) + c * LL + l0 + i];
    }
    __syncthreads();

    float wreg[CIN];
#pragma unroll
    for (int c = 0; c < CIN; c++) wreg[c] = ws[t * CIN + c];
    const float bb = __ldg(b0 + t);
    const float sc = __ldg(sc0 + t), sh = __ldg(sh0 + t);
#pragma unroll
    for (int i = 0; i < 16; i++) {
        float acc = bb;
#pragma unroll
        for (int c = 0; c < CIN; c++) acc = fmaf(wreg[c], xs[c][i], acc);
        float v = fmaxf(fmaf(acc, sc, sh), 0.f);
        __nv_bfloat16 h, l;
        bf16split(v, h, l);
        size_t o = (size_t)(g0 + i) * C0C + t;
        xah[o] = h; xal[o] = l;
    }
}

// ---------------------------------------------------------------------------
// BN stats (deterministic two-stage) — BN1 only
// ---------------------------------------------------------------------------
__global__ __launch_bounds__(256)
void bnstats_partial(const float* __restrict__ y, int nch,
                     float* __restrict__ pS, float* __restrict__ pQ)
{
    const int chunk = blockIdx.x;
    const int group = blockIdx.y;
    const int t = threadIdx.x;
    const int warp = t >> 5, lane = t & 31;
    const int ch = group * 32 + lane;
    const long long base = (long long)chunk * 1024;

    float s = 0.f, q = 0.f;
    for (int r = warp; r < 1024; r += 8) {
        float v = y[(base + r) * nch + ch];
        s += v; q = fmaf(v, v, q);
    }
    __shared__ float ss[8][32], sq[8][32];
    ss[warp][lane] = s; sq[warp][lane] = q;
    __syncthreads();
    if (warp == 0) {
        float S = ss[0][lane], Q = sq[0][lane];
#pragma unroll
        for (int w = 1; w < 8; w++) { S += ss[w][lane]; Q += sq[w][lane]; }
        pS[ch * 64 + chunk] = S;
        pQ[ch * 64 + chunk] = Q;
    }
}

__global__ void bnfinalize(const float* __restrict__ pS, const float* __restrict__ pQ,
                           const float* __restrict__ g, const float* __restrict__ be,
                           float* __restrict__ scale, float* __restrict__ shift, int nch)
{
    int ch = blockIdx.x * blockDim.x + threadIdx.x;
    if (ch >= nch) return;
    float s0 = 0.f, s1 = 0.f, s2 = 0.f, s3 = 0.f;
    float q0 = 0.f, q1 = 0.f, q2 = 0.f, q3 = 0.f;
#pragma unroll
    for (int i = 0; i < 64; i += 4) {
        s0 += pS[ch * 64 + i];     q0 += pQ[ch * 64 + i];
        s1 += pS[ch * 64 + i + 1]; q1 += pQ[ch * 64 + i + 1];
        s2 += pS[ch * 64 + i + 2]; q2 += pQ[ch * 64 + i + 2];
        s3 += pS[ch * 64 + i + 3]; q3 += pQ[ch * 64 + i + 3];
    }
    float s = (s0 + s1) + (s2 + s3);
    float q = (q0 + q1) + (q2 + q3);
    const float inv = 1.f / 65536.f;
    float mean = s * inv;
    float var = q * inv - mean * mean;
    float sc = __ldg(g + ch) * rsqrtf(var + 1e-5f);
    scale[ch] = sc;
    shift[ch] = __ldg(be + ch) - mean * sc;
}

// ---------------------------------------------------------------------------
// Final: out[b][cin][l] = b_out[cin] + sum_f w_out[cin][f] * relu(bn1(x1[g][f]))
// ---------------------------------------------------------------------------
__global__ __launch_bounds__(256)
void final_kernel(const float* __restrict__ x1,
                  const float* __restrict__ scale1, const float* __restrict__ shift1,
                  const float* __restrict__ w_out, const float* __restrict__ b_out,
                  float* __restrict__ out)
{
    __shared__ float xs[32][65];
    __shared__ float wsh[8][64];
    const int t = threadIdx.x;
    const int g0 = blockIdx.x * 32;

    for (int i = t; i < 32 * 64; i += 256) {
        int pos = i >> 6, f = i & 63;
        float v = x1[(size_t)(g0 + pos) * FFC + f];
        v = fmaf(v, __ldg(scale1 + f), __ldg(shift1 + f));
        xs[pos][f] = fmaxf(v, 0.f);
    }
    for (int i = t; i < 8 * 64; i += 256) wsh[i >> 6][i & 63] = w_out[i];
    __syncthreads();

    const int pos = t & 31, cin = t >> 5;
    float acc = __ldg(b_out + cin);
#pragma unroll
    for (int f = 0; f < 64; f++) acc = fmaf(wsh[cin][f], xs[pos][f], acc);

    const int b = g0 >> 10, l0 = g0 & 1023;
    out[b * (CIN * LL) + cin * LL + l0 + pos] = acc;
}

// ---------------------------------------------------------------------------
// Host launcher (graph-capturable: kernel launches only)
// ---------------------------------------------------------------------------
extern "C" void kernel_launch(void* const* d_in, const int* in_sizes, int n_in,
                              void* d_out, int out_size)
{
    const float* z     = (const float*)d_in[0];
    const float* w_pre = (const float*)d_in[1];
    const float* b_pre = (const float*)d_in[2];
    const float* w0    = (const float*)d_in[3];
    const float* b0    = (const float*)d_in[4];
    const float* g0    = (const float*)d_in[5];
    const float* be0   = (const float*)d_in[6];
    const float* wq    = (const float*)d_in[7];
    const float* bq    = (const float*)d_in[8];
    const float* wk    = (const float*)d_in[9];
    const float* bk    = (const float*)d_in[10];
    const float* wv    = (const float*)d_in[11];
    const float* bv    = (const float*)d_in[12];
    const float* gamma = (const float*)d_in[13];
    const float* w1    = (const float*)d_in[14];
    const float* b1    = (const float*)d_in[15];
    const float* g1    = (const float*)d_in[16];
    const float* be1   = (const float*)d_in[17];
    const float* w_out = (const float*)d_in[18];
    const float* b_out = (const float*)d_in[19];
    float* out = (float*)d_out;

    float *x0, *x1, *pS, *pQ, *sc0, *sh0, *sc1, *sh1, *bqk;
    __nv_bfloat16 *xah, *xal, *qkh, *qkl, *vTh, *atth, *attl;
    __nv_bfloat16 *wqkh, *wqkl, *wvh, *wvl, *w1h, *w1l;
    cudaGetSymbolAddress((void**)&x0,   g_x0);
    cudaGetSymbolAddress((void**)&xah,  g_xah);
    cudaGetSymbolAddress((void**)&xal,  g_xal);
    cudaGetSymbolAddress((void**)&qkh,  g_qkh);
    cudaGetSymbolAddress((void**)&qkl,  g_qkl);
    cudaGetSymbolAddress((void**)&vTh,  g_vTh);
    cudaGetSymbolAddress((void**)&atth, g_atth);
    cudaGetSymbolAddress((void**)&attl, g_attl);
    cudaGetSymbolAddress((void**)&x1,   g_x1);
    cudaGetSymbolAddress((void**)&pS,   g_pS);
    cudaGetSymbolAddress((void**)&pQ,   g_pQ);
    cudaGetSymbolAddress((void**)&sc0,  g_scale0);
    cudaGetSymbolAddress((void**)&sh0,  g_shift0);
    cudaGetSymbolAddress((void**)&sc1,  g_scale1);
    cudaGetSymbolAddress((void**)&sh1,  g_shift1);
    cudaGetSymbolAddress((void**)&wqkh, g_wqkh);
    cudaGetSymbolAddress((void**)&wqkl, g_wqkl);
    cudaGetSymbolAddress((void**)&wvh,  g_wvh);
    cudaGetSymbolAddress((void**)&wvl,  g_wvl);
    cudaGetSymbolAddress((void**)&w1h,  g_w1h);
    cudaGetSymbolAddress((void**)&w1l,  g_w1l);
    cudaGetSymbolAddress((void**)&bqk,  g_bqk);

    const int ST64  = 2 * (2 * 128 * 80 + 2 * 64 * 80);    // 61440
    const int ST128 = 2 * (2 * 128 * 80 + 2 * 128 * 80);   // 81920
    cudaFuncSetAttribute(fa_kernel, cudaFuncAttributeMaxDynamicSharedMemorySize, FA_SMEM);
    cudaFuncSetAttribute(mma_gemm<64, 0>,  cudaFuncAttributeMaxDynamicSharedMemorySize, ST64);
    cudaFuncSetAttribute(mma_gemm<64, 1>,  cudaFuncAttributeMaxDynamicSharedMemorySize, ST64);
    cudaFuncSetAttribute(mma_gemm<128, 2>, cudaFuncAttributeMaxDynamicSharedMemorySize, ST128);

    // 1) pre-linear: x0 = z @ w_pre^T + b_pre   [64 x 8192], K=128
    sgemm_kernel<<<dim3(8192 / 128, 1, 1), 256>>>(
        z, w_pre, b_pre, x0, NB, CIN * LL, ZD, ZD, ZD, CIN * LL);

    // 2) weight prep (independent)
    wprep_kernel<<<384, 256>>>(wq, wk, wv, w1, bq, bk, bqk,
                               wqkh, wqkl, wvh, wvl, w1h, w1l);

    // 3) BN0 via x0 moments (2 MB) -> analytic scale/shift
    xstats_partial<<<64, 256>>>(x0, pS);
    xstats_final<<<1, 256>>>(pS, w0, b0, g0, be0, sc0, sh0);

    // 4) fused conv0 + BN0 + ReLU -> xah/xal bf16
    conv0_fused<<<GG / 16, 256>>>(x0, w0, b0, sc0, sh0, xah, xal);

    // 5) Q+K projection (split out): [g][64], K=256
    mma_gemm<64, 1><<<dim3(1, GG / 128, 1), 256, ST64>>>(
        xah, xal, C0C, 0, wqkh, wqkl, C0C, 0, bqk,
        nullptr, qkh, qkl, 64, 0, C0C);

    // 6) V projection with fused transpose -> vTh bf16 (single), K=256
    mma_gemm<128, 2><<<dim3(2, GG / 128, 1), 256, ST128>>>(
        xah, xal, C0C, 0, wvh, wvl, C0C, 0, bv,
        nullptr, vTh, nullptr, 0, 0, C0C);

    // 7) fused flash attention: att = gamma*softmax(QK^T)V + xa -> bf16 hi/lo
    fa_kernel<<<dim3(2, 8, NB), 256, FA_SMEM>>>(qkh, qkl, vTh, xah, xal,
                                                gamma, atth, attl);

    // 8) conv1: x1 = att @ w1^T + b1  [g][64], K=256
    mma_gemm<64, 0><<<dim3(1, GG / 128, 1), 256, ST64>>>(
        atth, attl, C0C, 0, w1h, w1l, C0C, 0, b1,
        x1, nullptr, nullptr, FFC, 0, C0C);

    // 9) BN1 stats
    bnstats_partial<<<dim3(64, FFC / 32), 256>>>(x1, FFC, pS, pQ);
    bnfinalize<<<1, 64>>>(pS, pQ, g1, be1, sc1, sh1, FFC);

    // 10) fused BN1 + relu + w_out conv -> out [b][8][1024]
    final_kernel<<<GG / 32, 256>>>(x1, sc1, sh1, w_out, b_out, out);

    (void)in_sizes; (void)n_in; (void)out_size;
}

// round 12
// speedup vs baseline: 2.3429x; 1.2354x over previous
#include <cuda_runtime.h>
#include <cuda_bf16.h>

// ---------------------------------------------------------------------------
// Problem constants
// ---------------------------------------------------------------------------
#define NB    64          // batch
#define ZD    128         // latent dim
#define CIN   8
#define LL    1024        // W*H
#define C0C   256         // attention channels
#define CQKC  32
#define FFC   64          // filters
#define GG    65536       // NB * LL (total positions)

// ---------------------------------------------------------------------------
// Device scratch (allocation-free rule: __device__ globals)
// ---------------------------------------------------------------------------
__device__ __align__(16) float g_x0 [NB * CIN * LL];              //  2 MB
__device__ __align__(16) __nv_bfloat16 g_xah[(size_t)GG * C0C];   // 32 MB
__device__ __align__(16) __nv_bfloat16 g_xal[(size_t)GG * C0C];   // 32 MB
__device__ __align__(16) __nv_bfloat16 g_qkh[(size_t)GG * 64];    //  8 MB [g][q32|k32]
__device__ __align__(16) __nv_bfloat16 g_vTh[(size_t)NB * C0C * LL]; // 32 MB V^T bf16
__device__ __align__(16) __nv_bfloat16 g_atth[(size_t)GG * C0C];  // 32 MB att hi
__device__ __align__(16) __nv_bfloat16 g_attl[(size_t)GG * C0C];  // 32 MB att lo
__device__ __align__(16) float g_x1 [(size_t)GG * FFC];           // 16 MB
// weights
__device__ __align__(16) __nv_bfloat16 g_wqkh[64 * C0C];
__device__ __align__(16) __nv_bfloat16 g_wvh [C0C * C0C];
__device__ __align__(16) __nv_bfloat16 g_w1h [FFC * C0C], g_w1l [FFC * C0C];
__device__ __align__(16) float g_bqk[64];
__device__ float g_pS[C0C * 64];           // reused: x0 moment partials [64][44]
__device__ float g_pQ[C0C * 64];
__device__ __align__(16) float g_scale0[C0C], g_shift0[C0C];
__device__ __align__(16) float g_scale1[FFC], g_shift1[FFC];

// ---------------------------------------------------------------------------
// PTX helpers (sm_80-level only — harness ptxas targets plain sm_100)
// ---------------------------------------------------------------------------
__device__ __forceinline__ unsigned smem_u32(const void* p) {
    unsigned a;
    asm("{ .reg .u64 t; cvta.to.shared.u64 t, %1; cvt.u32.u64 %0, t; }" : "=r"(a) : "l"(p));
    return a;
}
__device__ __forceinline__ void cpasync16(unsigned d, const void* s) {
    asm volatile("cp.async.cg.shared.global [%0], [%1], 16;" :: "r"(d), "l"(s));
}
#define CP_COMMIT() asm volatile("cp.async.commit_group;" ::: "memory")
#define CP_WAIT0()  asm volatile("cp.async.wait_group 0;" ::: "memory")
#define CP_WAIT1()  asm volatile("cp.async.wait_group 1;" ::: "memory")

__device__ __forceinline__ void ldsm_x4(unsigned& r0, unsigned& r1,
                                        unsigned& r2, unsigned& r3, unsigned addr) {
    asm volatile("ldmatrix.sync.aligned.m8n8.x4.shared.b16 {%0,%1,%2,%3}, [%4];"
                 : "=r"(r0), "=r"(r1), "=r"(r2), "=r"(r3) : "r"(addr));
}
__device__ __forceinline__ void mma_bf16(float* c, const unsigned* a, const unsigned* b) {
    asm volatile("mma.sync.aligned.m16n8k16.row.col.f32.bf16.bf16.f32 "
                 "{%0,%1,%2,%3}, {%4,%5,%6,%7}, {%8,%9}, {%0,%1,%2,%3};"
                 : "+f"(c[0]), "+f"(c[1]), "+f"(c[2]), "+f"(c[3])
                 : "r"(a[0]), "r"(a[1]), "r"(a[2]), "r"(a[3]), "r"(b[0]), "r"(b[1]));
}
__device__ __forceinline__ void bf16split(float v, __nv_bfloat16& h, __nv_bfloat16& l) {
    h = __float2bfloat16(v);
    l = __float2bfloat16(v - __bfloat162float(h));
}
__device__ __forceinline__ unsigned pack2(__nv_bfloat16 a, __nv_bfloat16 b) {
    return ((unsigned)__bfloat16_as_ushort(b) << 16) | __bfloat16_as_ushort(a);
}
__device__ __forceinline__ unsigned pack2f(float a, float b) {
    return pack2(__float2bfloat16(a), __float2bfloat16(b));
}

// ---------------------------------------------------------------------------
// Generic MMA GEMM, SPLIT in {0,1} (1 = hi/lo 3-pass split operands).
//   OUT_MODE 0: fp32 C (+bias)
//   OUT_MODE 1: bf16 hi/lo split C (+bias)
//   OUT_MODE 2: V-projection: stage to smem, coalesced transposed vTh write
//   OUT_MODE 3: single bf16 C (+bias)
// ---------------------------------------------------------------------------
template<int BN, int SPLIT>
__device__ __forceinline__ void mm_load(unsigned dst, int t,
    const char* Ah, const char* Al, const char* Bh, const char* Bl,
    int ldaB, int ldbB, int m0, int n0, int kByte)
{
    constexpr int AOP = 128 * 80, BOP = BN * 80;
    constexpr int NA = 512 * (1 + SPLIT);
    constexpr int TC = NA + BN * 4 * (1 + SPLIT);
#pragma unroll
    for (int u = 0; u < TC / 256; u++) {
        int i = t + u * 256;
        if (i < NA) {
            int half = SPLIT ? (i >> 9) : 0;
            int row = (i >> 2) & 127, c = i & 3;
            const char* s = half ? Al : Ah;
            cpasync16(dst + half * AOP + row * 80 + c * 16,
                      s + (size_t)(m0 + row) * ldaB + kByte + c * 16);
        } else {
            int j = i - NA;
            int half = SPLIT ? (j / (BN * 4)) : 0;
            int row = (j >> 2) % BN, c = j & 3;
            const char* s = half ? Bl : Bh;
            cpasync16(dst + (1 + SPLIT) * AOP + half * BOP + row * 80 + c * 16,
                      s + (size_t)(n0 + row) * ldbB + kByte + c * 16);
        }
    }
}

template<int BN, int OUT_MODE, int SPLIT>
__global__ __launch_bounds__(256, 1)
void mma_gemm(const __nv_bfloat16* __restrict__ Ah, const __nv_bfloat16* __restrict__ Al,
              int lda, long long sA,
              const __nv_bfloat16* __restrict__ Bh, const __nv_bfloat16* __restrict__ Bl,
              int ldb, long long sB,
              const float* __restrict__ bias,
              float* __restrict__ C,
              __nv_bfloat16* __restrict__ Ch, __nv_bfloat16* __restrict__ Cl,
              int ldc, long long sC, int K)
{
    constexpr int AOP = 128 * 80, BOP = BN * 80;
    constexpr int BBASE = (1 + SPLIT) * AOP;
    constexpr int ST = (1 + SPLIT) * (AOP + BOP);
    constexpr int NW = BN / 4;
    constexpr int NI = NW / 8;
    constexpr int NGI = NW / 16;

    extern __shared__ char smem[];
    const unsigned sb = smem_u32(smem);
    const int t = threadIdx.x;
    const int n0 = blockIdx.x * BN, m0 = blockIdx.y * 128, z = blockIdx.z;

    const char* cAh = (const char*)(Ah + (size_t)z * sA);
    const char* cAl = SPLIT ? (const char*)(Al + (size_t)z * sA) : cAh;
    const char* cBh = (const char*)(Bh + (size_t)z * sB);
    const char* cBl = SPLIT ? (const char*)(Bl + (size_t)z * sB) : cBh;
    const int ldaB = lda * 2, ldbB = ldb * 2;

    const int w = t >> 5, lane = t & 31;
    const int wm = (w & 1) * 64, wn = (w >> 1) * NW;
    const int aRowSel = (lane & 7) + ((lane >> 3) & 1) * 8;
    const int aChunk  = (lane >> 4) * 16;
    const int bRowSel = (lane & 7) + (lane >> 4) * 8;
    const int bChunk  = ((lane >> 3) & 1) * 16;

    float acc[4][NI][4];
#pragma unroll
    for (int mi = 0; mi < 4; mi++)
#pragma unroll
        for (int ni = 0; ni < NI; ni++)
#pragma unroll
            for (int r = 0; r < 4; r++) acc[mi][ni][r] = 0.f;

    const int nst = K / 32;
    mm_load<BN, SPLIT>(sb, t, cAh, cAl, cBh, cBl, ldaB, ldbB, m0, n0, 0);
    CP_COMMIT();

    for (int s = 0; s < nst; s++) {
        if (s + 1 < nst) {
            mm_load<BN, SPLIT>(sb + ((s + 1) & 1) * ST, t, cAh, cAl, cBh, cBl,
                               ldaB, ldbB, m0, n0, (s + 1) * 64);
            CP_COMMIT();
            CP_WAIT1();
        } else {
            CP_WAIT0();
        }
        __syncthreads();

        const unsigned base = sb + (s & 1) * ST;
#pragma unroll
        for (int s2 = 0; s2 < 2; s2++) {
            unsigned ah[4][4], al[4][4];
#pragma unroll
            for (int mi = 0; mi < 4; mi++) {
                unsigned ar = base + (wm + mi * 16 + aRowSel) * 80 + s2 * 32 + aChunk;
                ldsm_x4(ah[mi][0], ah[mi][1], ah[mi][2], ah[mi][3], ar);
                if (SPLIT) ldsm_x4(al[mi][0], al[mi][1], al[mi][2], al[mi][3], ar + AOP);
            }
            unsigned bh[NI][2], bl[NI][2];
#pragma unroll
            for (int ngi = 0; ngi < NGI; ngi++) {
                unsigned br = base + BBASE + (wn + ngi * 16 + bRowSel) * 80 + s2 * 32 + bChunk;
                unsigned r0, r1, r2, r3;
                ldsm_x4(r0, r1, r2, r3, br);
                bh[2 * ngi][0] = r0; bh[2 * ngi][1] = r1;
                bh[2 * ngi + 1][0] = r2; bh[2 * ngi + 1][1] = r3;
                if (SPLIT) {
                    ldsm_x4(r0, r1, r2, r3, br + BOP);
                    bl[2 * ngi][0] = r0; bl[2 * ngi][1] = r1;
                    bl[2 * ngi + 1][0] = r2; bl[2 * ngi + 1][1] = r3;
                }
            }
#pragma unroll
            for (int mi = 0; mi < 4; mi++)
#pragma unroll
                for (int ni = 0; ni < NI; ni++) {
                    mma_bf16(acc[mi][ni], ah[mi], bh[ni]);
                    if (SPLIT) {
                        mma_bf16(acc[mi][ni], ah[mi], bl[ni]);
                        mma_bf16(acc[mi][ni], al[mi], bh[ni]);
                    }
                }
        }
        __syncthreads();
    }

    const int g = lane >> 2, tg = lane & 3;

    if (OUT_MODE == 2) {
        float* Ss = (float*)smem;
#pragma unroll
        for (int mi = 0; mi < 4; mi++)
#pragma unroll
            for (int ni = 0; ni < NI; ni++) {
                int col = wn + ni * 8 + 2 * tg;
                float b0 = __ldg(bias + n0 + col), b1 = __ldg(bias + n0 + col + 1);
#pragma unroll
                for (int half = 0; half < 2; half++) {
                    int row = wm + mi * 16 + half * 8 + g;
                    Ss[row * 132 + col]     = acc[mi][ni][2 * half + 0] + b0;
                    Ss[row * 132 + col + 1] = acc[mi][ni][2 * half + 1] + b1;
                }
            }
        __syncthreads();
        const int b = m0 >> 10, l0 = m0 & 1023;
        const int m = lane * 4;
#pragma unroll
        for (int i = 0; i < 16; i++) {
            int n = w * 16 + i;
            float v0 = Ss[(m + 0) * 132 + n];
            float v1 = Ss[(m + 1) * 132 + n];
            float v2 = Ss[(m + 2) * 132 + n];
            float v3 = Ss[(m + 3) * 132 + n];
            size_t ob = ((size_t)(b * 256 + n0 + n)) * 1024 + l0 + m;
            uint2 uh;
            uh.x = pack2f(v0, v1);
            uh.y = pack2f(v2, v3);
            *(uint2*)(Ch + ob) = uh;
        }
        return;
    }

#pragma unroll
    for (int mi = 0; mi < 4; mi++) {
#pragma unroll
        for (int ni = 0; ni < NI; ni++) {
            int gr = m0 + wm + mi * 16 + g;
            int gc = n0 + wn + ni * 8 + 2 * tg;
            float b0 = 0.f, b1 = 0.f;
            if (bias) { b0 = __ldg(bias + gc); b1 = __ldg(bias + gc + 1); }
#pragma unroll
            for (int half = 0; half < 2; half++) {
                size_t idx = (size_t)z * sC + (size_t)(gr + half * 8) * ldc + gc;
                float v0 = acc[mi][ni][2 * half + 0] + b0;
                float v1 = acc[mi][ni][2 * half + 1] + b1;
                if (OUT_MODE == 1) {
                    __nv_bfloat16 h0, l0b, h1, l1b;
                    bf16split(v0, h0, l0b); bf16split(v1, h1, l1b);
                    *(__nv_bfloat162*)(Ch + idx) = __halves2bfloat162(h0, h1);
                    *(__nv_bfloat162*)(Cl + idx) = __halves2bfloat162(l0b, l1b);
                } else if (OUT_MODE == 3) {
                    *(unsigned*)(Ch + idx) = pack2f(v0, v1);
                } else {
                    float2 o; o.x = v0; o.y = v1;
                    *(float2*)(C + idx) = o;
                }
            }
        }
    }
}

// ---------------------------------------------------------------------------
// Fused flash attention (single-bf16 Q/K/V): att = gamma*softmax(QK^T)V + xa
// Grid (2 n-halves, 8 m-tiles, 64 b); 256 threads, 8 warps of 16 m-rows.
// smem: Q 10240 | 2 chunk buffers x (K 10240 + V 4x10240) = 112640 B.
// ---------------------------------------------------------------------------
#define FA_CBS  51200
#define FA_SMEM 112640

__device__ __forceinline__ void fa_load_q(unsigned sb, int t, const char* gQ)
{
#pragma unroll
    for (int u = 0; u < 2; u++) {
        int i = t + u * 256;
        int row = i >> 2, c = i & 3;
        cpasync16(sb + row * 80 + c * 16, gQ + (size_t)row * 128 + c * 16);
    }
}

__device__ __forceinline__ void fa_load_chunk(unsigned dst, int t,
    const char* gK, const char* gV, int ch)
{
#pragma unroll
    for (int u = 0; u < 2; u++) {     // K: 128 rows x 64B
        int i = t + u * 256;
        int row = i >> 2, c = i & 3;
        cpasync16(dst + row * 80 + c * 16,
                  gK + (size_t)(ch * 128 + row) * 128 + c * 16);
    }
#pragma unroll
    for (int u = 0; u < 8; u++) {     // V: 4 k-groups x 128 n x 64B
        int i = t + u * 256;
        int c = i & 3, n = (i >> 2) & 127, kg = i >> 9;
        cpasync16(dst + 10240 + kg * 10240 + n * 80 + c * 16,
                  gV + (size_t)n * 2048 + ch * 256 + kg * 64 + c * 16);
    }
}

__global__ __launch_bounds__(256, 1)
void fa_kernel(const __nv_bfloat16* __restrict__ qkh,
               const __nv_bfloat16* __restrict__ vTh,
               const __nv_bfloat16* __restrict__ resh, const __nv_bfloat16* __restrict__ resl,
               const float* __restrict__ gammaPtr,
               __nv_bfloat16* __restrict__ atth, __nv_bfloat16* __restrict__ attl)
{
    extern __shared__ char smem[];
    const unsigned sb = smem_u32(smem);
    const int t = threadIdx.x;
    const int n0 = blockIdx.x * 128, m0 = blockIdx.y * 128, b = blockIdx.z;

    const char* gQ = (const char*)qkh + (size_t)(b * 1024 + m0) * 128;
    const char* gK = (const char*)qkh + (size_t)(b * 1024) * 128 + 64;
    const char* gV = (const char*)vTh + (size_t)(b * 256 + n0) * 2048;

    const int w = t >> 5, lane = t & 31;
    const int wm = w * 16;
    const int g = lane >> 2, tg = lane & 3;
    const int aRowSel = (lane & 7) + ((lane >> 3) & 1) * 8;
    const int aChunk  = (lane >> 4) * 16;
    const int bRowSel = (lane & 7) + (lane >> 4) * 8;
    const int bChunk  = ((lane >> 3) & 1) * 16;

    float oacc[16][4];
#pragma unroll
    for (int ni = 0; ni < 16; ni++)
#pragma unroll
        for (int r = 0; r < 4; r++) oacc[ni][r] = 0.f;
    float m0r = -1e30f, m1r = -1e30f, z0r = 0.f, z1r = 0.f;

    fa_load_q(sb, t, gQ);
    fa_load_chunk(sb + 10240, t, gK, gV, 0);
    CP_COMMIT();

    for (int ch = 0; ch < 8; ch++) {
        if (ch + 1 < 8) {
            fa_load_chunk(sb + 10240 + ((ch + 1) & 1) * FA_CBS, t, gK, gV, ch + 1);
            CP_COMMIT();
            CP_WAIT1();
        } else {
            CP_WAIT0();
        }
        __syncthreads();

        const unsigned kb = sb + 10240 + (ch & 1) * FA_CBS;

        // ---- S = Q K_chunk^T (single pass), 16m x 128j per warp ----
        float sacc[16][4];
#pragma unroll
        for (int ni = 0; ni < 16; ni++)
#pragma unroll
            for (int r = 0; r < 4; r++) sacc[ni][r] = 0.f;

#pragma unroll
        for (int s2 = 0; s2 < 2; s2++) {
            unsigned qh[4];
            ldsm_x4(qh[0], qh[1], qh[2], qh[3],
                    sb + (wm + aRowSel) * 80 + s2 * 32 + aChunk);
#pragma unroll
            for (int ngi = 0; ngi < 8; ngi++) {
                unsigned br = kb + (ngi * 16 + bRowSel) * 80 + s2 * 32 + bChunk;
                unsigned r0, r1, r2, r3;
                ldsm_x4(r0, r1, r2, r3, br);
                unsigned b0[2] = { r0, r1 }, b1[2] = { r2, r3 };
                mma_bf16(sacc[2 * ngi],     qh, b0);
                mma_bf16(sacc[2 * ngi + 1], qh, b1);
            }
        }

        // ---- online softmax (register + shfl over the 4 tg lanes) ----
        float cm0 = -1e30f, cm1 = -1e30f;
#pragma unroll
        for (int ni = 0; ni < 16; ni++) {
            cm0 = fmaxf(cm0, fmaxf(sacc[ni][0], sacc[ni][1]));
            cm1 = fmaxf(cm1, fmaxf(sacc[ni][2], sacc[ni][3]));
        }
        cm0 = fmaxf(cm0, __shfl_xor_sync(0xffffffffu, cm0, 1));
        cm0 = fmaxf(cm0, __shfl_xor_sync(0xffffffffu, cm0, 2));
        cm1 = fmaxf(cm1, __shfl_xor_sync(0xffffffffu, cm1, 1));
        cm1 = fmaxf(cm1, __shfl_xor_sync(0xffffffffu, cm1, 2));

        float nm0 = fmaxf(m0r, cm0), nm1 = fmaxf(m1r, cm1);
        float sc0 = __expf(m0r - nm0), sc1 = __expf(m1r - nm1);
        float cs0 = 0.f, cs1 = 0.f;
#pragma unroll
        for (int ni = 0; ni < 16; ni++) {
            sacc[ni][0] = __expf(sacc[ni][0] - nm0);
            sacc[ni][1] = __expf(sacc[ni][1] - nm0);
            sacc[ni][2] = __expf(sacc[ni][2] - nm1);
            sacc[ni][3] = __expf(sacc[ni][3] - nm1);
            cs0 += sacc[ni][0] + sacc[ni][1];
            cs1 += sacc[ni][2] + sacc[ni][3];
        }
        cs0 += __shfl_xor_sync(0xffffffffu, cs0, 1);
        cs0 += __shfl_xor_sync(0xffffffffu, cs0, 2);
        cs1 += __shfl_xor_sync(0xffffffffu, cs1, 1);
        cs1 += __shfl_xor_sync(0xffffffffu, cs1, 2);

        z0r = z0r * sc0 + cs0;
        z1r = z1r * sc1 + cs1;
        m0r = nm0; m1r = nm1;
#pragma unroll
        for (int ni = 0; ni < 16; ni++) {
            oacc[ni][0] *= sc0; oacc[ni][1] *= sc0;
            oacc[ni][2] *= sc1; oacc[ni][3] *= sc1;
        }

        // ---- O += P_chunk @ V_chunk (P from C-frag, bf16) ----
#pragma unroll
        for (int u = 0; u < 8; u++) {
            unsigned pa[4];
            pa[0] = pack2f(sacc[2 * u][0],     sacc[2 * u][1]);
            pa[1] = pack2f(sacc[2 * u][2],     sacc[2 * u][3]);
            pa[2] = pack2f(sacc[2 * u + 1][0], sacc[2 * u + 1][1]);
            pa[3] = pack2f(sacc[2 * u + 1][2], sacc[2 * u + 1][3]);
            const unsigned vgb = kb + 10240 + (u >> 1) * 10240;
            const int s2v = u & 1;
#pragma unroll
            for (int ngi = 0; ngi < 8; ngi++) {
                unsigned br = vgb + (ngi * 16 + bRowSel) * 80 + s2v * 32 + bChunk;
                unsigned r0, r1, r2, r3;
                ldsm_x4(r0, r1, r2, r3, br);
                unsigned bv0[2] = { r0, r1 }, bv1[2] = { r2, r3 };
                mma_bf16(oacc[2 * ngi],     pa, bv0);
                mma_bf16(oacc[2 * ngi + 1], pa, bv1);
            }
        }
        __syncthreads();
    }

    // ---- epilogue: att = gamma * O / z + (xah + xal) -> bf16 hi/lo ----
    const float gam = __ldg(gammaPtr);
    const float gz0 = gam / z0r, gz1 = gam / z1r;
    const int gr0 = b * 1024 + m0 + wm + g;
#pragma unroll
    for (int ni = 0; ni < 16; ni++) {
        int gc = n0 + ni * 8 + 2 * tg;
        size_t i0 = (size_t)gr0 * 256 + gc;
        size_t i1 = i0 + (size_t)8 * 256;
        __nv_bfloat162 rh0 = *(const __nv_bfloat162*)(resh + i0);
        __nv_bfloat162 rl0 = *(const __nv_bfloat162*)(resl + i0);
        __nv_bfloat162 rh1 = *(const __nv_bfloat162*)(resh + i1);
        __nv_bfloat162 rl1 = *(const __nv_bfloat162*)(resl + i1);
        float v0 = fmaf(gz0, oacc[ni][0], __bfloat162float(rh0.x) + __bfloat162float(rl0.x));
        float v1 = fmaf(gz0, oacc[ni][1], __bfloat162float(rh0.y) + __bfloat162float(rl0.y));
        float v2 = fmaf(gz1, oacc[ni][2], __bfloat162float(rh1.x) + __bfloat162float(rl1.x));
        float v3 = fmaf(gz1, oacc[ni][3], __bfloat162float(rh1.y) + __bfloat162float(rl1.y));
        __nv_bfloat16 h0, l0, h1, l1;
        bf16split(v0, h0, l0); bf16split(v1, h1, l1);
        *(__nv_bfloat162*)(atth + i0) = __halves2bfloat162(h0, h1);
        *(__nv_bfloat162*)(attl + i0) = __halves2bfloat162(l0, l1);
        bf16split(v2, h0, l0); bf16split(v3, h1, l1);
        *(__nv_bfloat162*)(atth + i1) = __halves2bfloat162(h0, h1);
        *(__nv_bfloat162*)(attl + i1) = __halves2bfloat162(l0, l1);
    }
}

// ---------------------------------------------------------------------------
// SIMT SGEMM (only for tiny pre-linear), B stored [N,K] row-major
// ---------------------------------------------------------------------------
__global__ __launch_bounds__(256)
void sgemm_kernel(const float* __restrict__ A, const float* __restrict__ Bm,
                  const float* __restrict__ bias, float* __restrict__ C,
                  int M, int N, int K, int lda, int ldb, int ldc)
{
    __shared__ float As[8][128];
    __shared__ float Bs[8][128];

    const int tid = threadIdx.x;
    const int m0 = blockIdx.y * 128;
    const int n0 = blockIdx.x * 128;

    const int aRow = tid >> 1;
    const int aK   = (tid & 1) << 2;
    const int tr = (tid >> 4) << 3;
    const int tc = (tid & 15) << 3;

    const bool aOK = (m0 + aRow) < M;
    const bool bOK = (n0 + aRow) < N;
    const float* aPtr = A + (long long)(m0 + aRow) * lda + aK;
    const float* bPtr = Bm + (long long)(n0 + aRow) * ldb + aK;

    float acc[8][8];
#pragma unroll
    for (int i = 0; i < 8; i++)
#pragma unroll
        for (int j = 0; j < 8; j++) acc[i][j] = 0.f;

    float4 aReg = make_float4(0.f, 0.f, 0.f, 0.f);
    float4 bReg = make_float4(0.f, 0.f, 0.f, 0.f);
    if (aOK) aReg = *(const float4*)aPtr;
    if (bOK) bReg = *(const float4*)bPtr;

    for (int k0 = 0; k0 < K; k0 += 8) {
        As[aK + 0][aRow] = aReg.x; As[aK + 1][aRow] = aReg.y;
        As[aK + 2][aRow] = aReg.z; As[aK + 3][aRow] = aReg.w;
        Bs[aK + 0][aRow] = bReg.x; Bs[aK + 1][aRow] = bReg.y;
        Bs[aK + 2][aRow] = bReg.z; Bs[aK + 3][aRow] = bReg.w;
        __syncthreads();

        if (k0 + 8 < K) {
            aReg = make_float4(0.f, 0.f, 0.f, 0.f);
            bReg = make_float4(0.f, 0.f, 0.f, 0.f);
            if (aOK) aReg = *(const float4*)(aPtr + (k0 + 8));
            if (bOK) bReg = *(const float4*)(bPtr + (k0 + 8));
        }

#pragma unroll
        for (int kk = 0; kk < 8; kk++) {
            float ar[8], br[8];
            *(float4*)&ar[0] = *(const float4*)&As[kk][tr];
            *(float4*)&ar[4] = *(const float4*)&As[kk][tr + 4];
            *(float4*)&br[0] = *(const float4*)&Bs[kk][tc];
            *(float4*)&br[4] = *(const float4*)&Bs[kk][tc + 4];
#pragma unroll
            for (int i = 0; i < 8; i++)
#pragma unroll
                for (int j = 0; j < 8; j++)
                    acc[i][j] = fmaf(ar[i], br[j], acc[i][j]);
        }
        __syncthreads();
    }

#pragma unroll
    for (int i = 0; i < 8; i++) {
        int gm = m0 + tr + i;
        if (gm < M) {
#pragma unroll
            for (int j = 0; j < 8; j += 4) {
                int gn = n0 + tc + j;
                if (gn < N) {
                    float4 o;
                    o.x = acc[i][j]; o.y = acc[i][j + 1];
                    o.z = acc[i][j + 2]; o.w = acc[i][j + 3];
                    if (bias) {
                        o.x += __ldg(bias + gn);     o.y += __ldg(bias + gn + 1);
                        o.z += __ldg(bias + gn + 2); o.w += __ldg(bias + gn + 3);
                    }
                    *(float4*)(C + (long long)gm * ldc + gn) = o;
                }
            }
        }
    }
}

// ---------------------------------------------------------------------------
// Weight prep: wq||wk single bf16; wv single bf16; w1 split; merge bq||bk
// ---------------------------------------------------------------------------
__global__ void wprep_kernel(const float* __restrict__ wq, const float* __restrict__ wk,
                             const float* __restrict__ wv, const float* __restrict__ w1,
                             const float* __restrict__ bq, const float* __restrict__ bk,
                             float* __restrict__ bqk,
                             __nv_bfloat16* __restrict__ wqkh,
                             __nv_bfloat16* __restrict__ wvh,
                             __nv_bfloat16* __restrict__ w1h, __nv_bfloat16* __restrict__ w1l)
{
    int i = blockIdx.x * 256 + threadIdx.x;
    if (i < 16384) {
        int n = i >> 8, k = i & 255;
        float v = (n < 32) ? wq[n * 256 + k] : wk[(n - 32) * 256 + k];
        wqkh[i] = __float2bfloat16(v);
    } else if (i < 81920) {
        int j = i - 16384;
        wvh[j] = __float2bfloat16(wv[j]);
    } else if (i < 98304) {
        int j = i - 81920;
        __nv_bfloat16 h, l;
        bf16split(w1[j], h, l);
        w1h[j] = h; w1l[j] = l;
    }
    if (i < 64) bqk[i] = (i < 32) ? bq[i] : bk[i - 32];
}

// ---------------------------------------------------------------------------
// x0 moment stats (8 + 36 vals) per batch; deterministic reductions.
// ---------------------------------------------------------------------------
__global__ __launch_bounds__(256)
void xstats_partial(const float* __restrict__ x0, float* __restrict__ pX)
{
    const int b = blockIdx.x, t = threadIdx.x;
    const int warp = t >> 5, lane = t & 31;
    float a[44];
#pragma unroll
    for (int j = 0; j < 44; j++) a[j] = 0.f;

#pragma unroll
    for (int r = 0; r < 4; r++) {
        int l = t + r * 256;
        float v[CIN];
#pragma unroll
        for (int c = 0; c < CIN; c++)
            v[c] = x0[b * (CIN * LL) + c * LL + l];
#pragma unroll
        for (int c = 0; c < CIN; c++) a[c] += v[c];
        int idx = CIN;
#pragma unroll
        for (int c1 = 0; c1 < CIN; c1++)
#pragma unroll
            for (int c2 = c1; c2 < CIN; c2++)
                a[idx++] = fmaf(v[c1], v[c2], a[idx]);
    }
#pragma unroll
    for (int j = 0; j < 44; j++)
#pragma unroll
        for (int o = 16; o; o >>= 1)
            a[j] += __shfl_xor_sync(0xffffffffu, a[j], o);

    __shared__ float ws[8][44];
    if (lane == 0)
#pragma unroll
        for (int j = 0; j < 44; j++) ws[warp][j] = a[j];
    __syncthreads();
    if (t < 44) {
        float s = ws[0][t];
#pragma unroll
        for (int w = 1; w < 8; w++) s += ws[w][t];
        pX[b * 44 + t] = s;
    }
}

__global__ void xstats_final(const float* __restrict__ pX,
                             const float* __restrict__ w0, const float* __restrict__ b0,
                             const float* __restrict__ g0, const float* __restrict__ be0,
                             float* __restrict__ scale, float* __restrict__ shift)
{
    __shared__ float mom[44];
    __shared__ float mu[CIN];
    __shared__ float cov[CIN][CIN];
    const int t = threadIdx.x;
    if (t < 44) {
        float s = 0.f;
        for (int b = 0; b < 64; b++) s += pX[b * 44 + t];
        mom[t] = s;
    }
    __syncthreads();
    if (t == 0) {
        const float inv = 1.f / 65536.f;
        for (int c = 0; c < CIN; c++) mu[c] = mom[c] * inv;
        int idx = CIN;
        for (int c1 = 0; c1 < CIN; c1++)
            for (int c2 = c1; c2 < CIN; c2++) {
                float cv = mom[idx++] * inv - mu[c1] * mu[c2];
                cov[c1][c2] = cv; cov[c2][c1] = cv;
            }
    }
    __syncthreads();
    float w[CIN];
#pragma unroll
    for (int c = 0; c < CIN; c++) w[c] = w0[t * CIN + c];
    float mean = __ldg(b0 + t);
#pragma unroll
    for (int c = 0; c < CIN; c++) mean = fmaf(w[c], mu[c], mean);
    float var = 0.f;
#pragma unroll
    for (int c1 = 0; c1 < CIN; c1++) {
        float acc = 0.f;
#pragma unroll
        for (int c2 = 0; c2 < CIN; c2++) acc = fmaf(w[c2], cov[c1][c2], acc);
        var = fmaf(w[c1], acc, var);
    }
    float sc = __ldg(g0 + t) * rsqrtf(var + 1e-5f);
    scale[t] = sc;
    shift[t] = __ldg(be0 + t) - mean * sc;
}

// ---------------------------------------------------------------------------
// Fused conv0 + BN0 + ReLU -> xah/xal bf16
// ---------------------------------------------------------------------------
__global__ __launch_bounds__(256)
void conv0_fused(const float* __restrict__ x0, const float* __restrict__ w0,
                 const float* __restrict__ b0,
                 const float* __restrict__ sc0, const float* __restrict__ sh0,
                 __nv_bfloat16* __restrict__ xah, __nv_bfloat16* __restrict__ xal)
{
    __shared__ float ws[C0C * CIN];
    __shared__ float xs[CIN][16];
    const int t = threadIdx.x;
    for (int i = t; i < C0C * CIN; i += 256) ws[i] = w0[i];
    const int g0 = blockIdx.x * 16;
    const int b = g0 >> 10, l0 = g0 & 1023;
    if (t < 128) {
        int c = t >> 4, i = t & 15;
        xs[c][i] = x0[b * (CIN * LL) + c * LL + l0 + i];
    }
    __syncthreads();

    float wreg[CIN];
#pragma unroll
    for (int c = 0; c < CIN; c++) wreg[c] = ws[t * CIN + c];
    const float bb = __ldg(b0 + t);
    const float sc = __ldg(sc0 + t), sh = __ldg(sh0 + t);
#pragma unroll
    for (int i = 0; i < 16; i++) {
        float acc = bb;
#pragma unroll
        for (int c = 0; c < CIN; c++) acc = fmaf(wreg[c], xs[c][i], acc);
        float v = fmaxf(fmaf(acc, sc, sh), 0.f);
        __nv_bfloat16 h, l;
        bf16split(v, h, l);
        size_t o = (size_t)(g0 + i) * C0C + t;
        xah[o] = h; xal[o] = l;
    }
}

// ---------------------------------------------------------------------------
// BN stats (deterministic two-stage) — BN1 only
// ---------------------------------------------------------------------------
__global__ __launch_bounds__(256)
void bnstats_partial(const float* __restrict__ y, int nch,
                     float* __restrict__ pS, float* __restrict__ pQ)
{
    const int chunk = blockIdx.x;
    const int group = blockIdx.y;
    const int t = threadIdx.x;
    const int warp = t >> 5, lane = t & 31;
    const int ch = group * 32 + lane;
    const long long base = (long long)chunk * 1024;

    float s = 0.f, q = 0.f;
    for (int r = warp; r < 1024; r += 8) {
        float v = y[(base + r) * nch + ch];
        s += v; q = fmaf(v, v, q);
    }
    __shared__ float ss[8][32], sq[8][32];
    ss[warp][lane] = s; sq[warp][lane] = q;
    __syncthreads();
    if (warp == 0) {
        float S = ss[0][lane], Q = sq[0][lane];
#pragma unroll
        for (int w = 1; w < 8; w++) { S += ss[w][lane]; Q += sq[w][lane]; }
        pS[ch * 64 + chunk] = S;
        pQ[ch * 64 + chunk] = Q;
    }
}

__global__ void bnfinalize(const float* __restrict__ pS, const float* __restrict__ pQ,
                           const float* __restrict__ g, const float* __restrict__ be,
                           float* __restrict__ scale, float* __restrict__ shift, int nch)
{
    int ch = blockIdx.x * blockDim.x + threadIdx.x;
    if (ch >= nch) return;
    float s0 = 0.f, s1 = 0.f, s2 = 0.f, s3 = 0.f;
    float q0 = 0.f, q1 = 0.f, q2 = 0.f, q3 = 0.f;
#pragma unroll
    for (int i = 0; i < 64; i += 4) {
        s0 += pS[ch * 64 + i];     q0 += pQ[ch * 64 + i];
        s1 += pS[ch * 64 + i + 1]; q1 += pQ[ch * 64 + i + 1];
        s2 += pS[ch * 64 + i + 2]; q2 += pQ[ch * 64 + i + 2];
        s3 += pS[ch * 64 + i + 3]; q3 += pQ[ch * 64 + i + 3];
    }
    float s = (s0 + s1) + (s2 + s3);
    float q = (q0 + q1) + (q2 + q3);
    const float inv = 1.f / 65536.f;
    float mean = s * inv;
    float var = q * inv - mean * mean;
    float sc = __ldg(g + ch) * rsqrtf(var + 1e-5f);
    scale[ch] = sc;
    shift[ch] = __ldg(be + ch) - mean * sc;
}

// ---------------------------------------------------------------------------
// Final: out[b][cin][l] = b_out[cin] + sum_f w_out[cin][f] * relu(bn1(x1[g][f]))
// ---------------------------------------------------------------------------
__global__ __launch_bounds__(256)
void final_kernel(const float* __restrict__ x1,
                  const float* __restrict__ scale1, const float* __restrict__ shift1,
                  const float* __restrict__ w_out, const float* __restrict__ b_out,
                  float* __restrict__ out)
{
    __shared__ float xs[32][65];
    __shared__ float wsh[8][64];
    const int t = threadIdx.x;
    const int g0 = blockIdx.x * 32;

    for (int i = t; i < 32 * 64; i += 256) {
        int pos = i >> 6, f = i & 63;
        float v = x1[(size_t)(g0 + pos) * FFC + f];
        v = fmaf(v, __ldg(scale1 + f), __ldg(shift1 + f));
        xs[pos][f] = fmaxf(v, 0.f);
    }
    for (int i = t; i < 8 * 64; i += 256) wsh[i >> 6][i & 63] = w_out[i];
    __syncthreads();

    const int pos = t & 31, cin = t >> 5;
    float acc = __ldg(b_out + cin);
#pragma unroll
    for (int f = 0; f < 64; f++) acc = fmaf(wsh[cin][f], xs[pos][f], acc);

    const int b = g0 >> 10, l0 = g0 & 1023;
    out[b * (CIN * LL) + cin * LL + l0 + pos] = acc;
}

// ---------------------------------------------------------------------------
// Host launcher (graph-capturable: kernel launches only)
// ---------------------------------------------------------------------------
extern "C" void kernel_launch(void* const* d_in, const int* in_sizes, int n_in,
                              void* d_out, int out_size)
{
    const float* z     = (const float*)d_in[0];
    const float* w_pre = (const float*)d_in[1];
    const float* b_pre = (const float*)d_in[2];
    const float* w0    = (const float*)d_in[3];
    const float* b0    = (const float*)d_in[4];
    const float* g0    = (const float*)d_in[5];
    const float* be0   = (const float*)d_in[6];
    const float* wq    = (const float*)d_in[7];
    const float* bq    = (const float*)d_in[8];
    const float* wk    = (const float*)d_in[9];
    const float* bk    = (const float*)d_in[10];
    const float* wv    = (const float*)d_in[11];
    const float* bv    = (const float*)d_in[12];
    const float* gamma = (const float*)d_in[13];
    const float* w1    = (const float*)d_in[14];
    const float* b1    = (const float*)d_in[15];
    const float* g1    = (const float*)d_in[16];
    const float* be1   = (const float*)d_in[17];
    const float* w_out = (const float*)d_in[18];
    const float* b_out = (const float*)d_in[19];
    float* out = (float*)d_out;

    float *x0, *x1, *pS, *pQ, *sc0, *sh0, *sc1, *sh1, *bqk;
    __nv_bfloat16 *xah, *xal, *qkh, *vTh, *atth, *attl;
    __nv_bfloat16 *wqkh, *wvh, *w1h, *w1l;
    cudaGetSymbolAddress((void**)&x0,   g_x0);
    cudaGetSymbolAddress((void**)&xah,  g_xah);
    cudaGetSymbolAddress((void**)&xal,  g_xal);
    cudaGetSymbolAddress((void**)&qkh,  g_qkh);
    cudaGetSymbolAddress((void**)&vTh,  g_vTh);
    cudaGetSymbolAddress((void**)&atth, g_atth);
    cudaGetSymbolAddress((void**)&attl, g_attl);
    cudaGetSymbolAddress((void**)&x1,   g_x1);
    cudaGetSymbolAddress((void**)&pS,   g_pS);
    cudaGetSymbolAddress((void**)&pQ,   g_pQ);
    cudaGetSymbolAddress((void**)&sc0,  g_scale0);
    cudaGetSymbolAddress((void**)&sh0,  g_shift0);
    cudaGetSymbolAddress((void**)&sc1,  g_scale1);
    cudaGetSymbolAddress((void**)&sh1,  g_shift1);
    cudaGetSymbolAddress((void**)&wqkh, g_wqkh);
    cudaGetSymbolAddress((void**)&wvh,  g_wvh);
    cudaGetSymbolAddress((void**)&w1h,  g_w1h);
    cudaGetSymbolAddress((void**)&w1l,  g_w1l);
    cudaGetSymbolAddress((void**)&bqk,  g_bqk);

    const int ST_QK   = 2 * (128 * 80 + 64 * 80);           // 30720 (SPLIT=0)
    const int ST_VP   = 67584;                              // max(2*20480, Ss 128*132*4)
    const int ST_C1   = 2 * (2 * 128 * 80 + 2 * 64 * 80);   // 61440 (SPLIT=1)
    cudaFuncSetAttribute(fa_kernel, cudaFuncAttributeMaxDynamicSharedMemorySize, FA_SMEM);
    cudaFuncSetAttribute(mma_gemm<64, 3, 0>,  cudaFuncAttributeMaxDynamicSharedMemorySize, ST_QK);
    cudaFuncSetAttribute(mma_gemm<128, 2, 0>, cudaFuncAttributeMaxDynamicSharedMemorySize, ST_VP);
    cudaFuncSetAttribute(mma_gemm<64, 0, 1>,  cudaFuncAttributeMaxDynamicSharedMemorySize, ST_C1);

    // 1) pre-linear: x0 = z @ w_pre^T + b_pre   [64 x 8192], K=128
    sgemm_kernel<<<dim3(8192 / 128, 1, 1), 256>>>(
        z, w_pre, b_pre, x0, NB, CIN * LL, ZD, ZD, ZD, CIN * LL);

    // 2) weight prep (independent)
    wprep_kernel<<<384, 256>>>(wq, wk, wv, w1, bq, bk, bqk,
                               wqkh, wvh, w1h, w1l);

    // 3) BN0 via x0 moments (2 MB) -> analytic scale/shift
    xstats_partial<<<64, 256>>>(x0, pS);
    xstats_final<<<1, 256>>>(pS, w0, b0, g0, be0, sc0, sh0);

    // 4) fused conv0 + BN0 + ReLU -> xah/xal bf16
    conv0_fused<<<GG / 16, 256>>>(x0, w0, b0, sc0, sh0, xah, xal);

    // 5) Q+K projection (single bf16 in/out): [g][64], K=256
    mma_gemm<64, 3, 0><<<dim3(1, GG / 128, 1), 256, ST_QK>>>(
        xah, nullptr, C0C, 0, wqkh, nullptr, C0C, 0, bqk,
        nullptr, qkh, nullptr, 64, 0, C0C);

    // 6) V projection (single bf16 in) with fused transpose -> vTh, K=256
    mma_gemm<128, 2, 0><<<dim3(2, GG / 128, 1), 256, ST_VP>>>(
        xah, nullptr, C0C, 0, wvh, nullptr, C0C, 0, bv,
        nullptr, vTh, nullptr, 0, 0, C0C);

    // 7) fused flash attention: att = gamma*softmax(QK^T)V + xa -> bf16 hi/lo
    fa_kernel<<<dim3(2, 8, NB), 256, FA_SMEM>>>(qkh, vTh, xah, xal,
                                                gamma, atth, attl);

    // 8) conv1 (split operands): x1 = att @ w1^T + b1  [g][64], K=256
    mma_gemm<64, 0, 1><<<dim3(1, GG / 128, 1), 256, ST_C1>>>(
        atth, attl, C0C, 0, w1h, w1l, C0C, 0, b1,
        x1, nullptr, nullptr, FFC, 0, C0C);

    // 9) BN1 stats
    bnstats_partial<<<dim3(64, FFC / 32), 256>>>(x1, FFC, pS, pQ);
    bnfinalize<<<1, 64>>>(pS, pQ, g1, be1, sc1, sh1, FFC);

    // 10) fused BN1 + relu + w_out conv -> out [b][8][1024]
    final_kernel<<<GG / 32, 256>>>(x1, sc1, sh1, w_out, b_out, out);

    (void)in_sizes; (void)n_in; (void)out_size;
}

// round 13
// speedup vs baseline: 2.4286x; 1.0366x over previous
#include <cuda_runtime.h>
#include <cuda_bf16.h>

// ---------------------------------------------------------------------------
// Problem constants
// ---------------------------------------------------------------------------
#define NB    64          // batch
#define ZD    128         // latent dim
#define CIN   8
#define LL    1024        // W*H
#define C0C   256         // attention channels
#define CQKC  32
#define FFC   64          // filters
#define GG    65536       // NB * LL (total positions)

// ---------------------------------------------------------------------------
// Device scratch (allocation-free rule: __device__ globals)
// ---------------------------------------------------------------------------
__device__ __align__(16) float g_x0 [NB * CIN * LL];              //  2 MB
__device__ __align__(16) __nv_bfloat16 g_xah[(size_t)GG * C0C];   // 32 MB
__device__ __align__(16) __nv_bfloat16 g_xal[(size_t)GG * C0C];   // 32 MB
__device__ __align__(16) __nv_bfloat16 g_qkh[(size_t)GG * 64];    //  8 MB [g][q32|k32]
__device__ __align__(16) __nv_bfloat16 g_vTh[(size_t)NB * C0C * LL]; // 32 MB V^T bf16
__device__ __align__(16) __nv_bfloat16 g_atth[(size_t)GG * C0C];  // 32 MB att hi
__device__ __align__(16) __nv_bfloat16 g_attl[(size_t)GG * C0C];  // 32 MB att lo
__device__ __align__(16) float g_x1 [(size_t)GG * FFC];           // 16 MB
// weights
__device__ __align__(16) __nv_bfloat16 g_wqkh[64 * C0C];
__device__ __align__(16) __nv_bfloat16 g_wvh [C0C * C0C];
__device__ __align__(16) __nv_bfloat16 g_w1h [FFC * C0C], g_w1l [FFC * C0C];
__device__ __align__(16) float g_bqk[64];
__device__ float g_pS[C0C * 64];           // reused: x0 moment partials [64][44]
__device__ float g_pQ[C0C * 64];
__device__ __align__(16) float g_scale0[C0C], g_shift0[C0C];
__device__ __align__(16) float g_scale1[FFC], g_shift1[FFC];

// ---------------------------------------------------------------------------
// PTX helpers (sm_80-level only — harness ptxas targets plain sm_100)
// ---------------------------------------------------------------------------
__device__ __forceinline__ unsigned smem_u32(const void* p) {
    unsigned a;
    asm("{ .reg .u64 t; cvta.to.shared.u64 t, %1; cvt.u32.u64 %0, t; }" : "=r"(a) : "l"(p));
    return a;
}
__device__ __forceinline__ void cpasync16(unsigned d, const void* s) {
    asm volatile("cp.async.cg.shared.global [%0], [%1], 16;" :: "r"(d), "l"(s));
}
#define CP_COMMIT() asm volatile("cp.async.commit_group;" ::: "memory")
#define CP_WAIT0()  asm volatile("cp.async.wait_group 0;" ::: "memory")
#define CP_WAIT1()  asm volatile("cp.async.wait_group 1;" ::: "memory")

__device__ __forceinline__ void ldsm_x4(unsigned& r0, unsigned& r1,
                                        unsigned& r2, unsigned& r3, unsigned addr) {
    asm volatile("ldmatrix.sync.aligned.m8n8.x4.shared.b16 {%0,%1,%2,%3}, [%4];"
                 : "=r"(r0), "=r"(r1), "=r"(r2), "=r"(r3) : "r"(addr));
}
__device__ __forceinline__ void mma_bf16(float* c, const unsigned* a, const unsigned* b) {
    asm volatile("mma.sync.aligned.m16n8k16.row.col.f32.bf16.bf16.f32 "
                 "{%0,%1,%2,%3}, {%4,%5,%6,%7}, {%8,%9}, {%0,%1,%2,%3};"
                 : "+f"(c[0]), "+f"(c[1]), "+f"(c[2]), "+f"(c[3])
                 : "r"(a[0]), "r"(a[1]), "r"(a[2]), "r"(a[3]), "r"(b[0]), "r"(b[1]));
}
__device__ __forceinline__ void bf16split(float v, __nv_bfloat16& h, __nv_bfloat16& l) {
    h = __float2bfloat16(v);
    l = __float2bfloat16(v - __bfloat162float(h));
}
__device__ __forceinline__ unsigned pack2(__nv_bfloat16 a, __nv_bfloat16 b) {
    return ((unsigned)__bfloat16_as_ushort(b) << 16) | __bfloat16_as_ushort(a);
}
__device__ __forceinline__ unsigned pack2f(float a, float b) {
    return pack2(__float2bfloat16(a), __float2bfloat16(b));
}

// ---------------------------------------------------------------------------
// Generic MMA GEMM, SPLIT in {0,1} (1 = hi/lo 3-pass split operands).
//   OUT_MODE 0: fp32 C (+bias)
//   OUT_MODE 1: bf16 hi/lo split C (+bias)
//   OUT_MODE 2: V-projection: stage to smem, coalesced transposed vTh write
//   OUT_MODE 3: single bf16 C (+bias)
// ---------------------------------------------------------------------------
template<int BN, int SPLIT>
__device__ __forceinline__ void mm_load(unsigned dst, int t,
    const char* Ah, const char* Al, const char* Bh, const char* Bl,
    int ldaB, int ldbB, int m0, int n0, int kByte)
{
    constexpr int AOP = 128 * 80, BOP = BN * 80;
    constexpr int NA = 512 * (1 + SPLIT);
    constexpr int TC = NA + BN * 4 * (1 + SPLIT);
#pragma unroll
    for (int u = 0; u < TC / 256; u++) {
        int i = t + u * 256;
        if (i < NA) {
            int half = SPLIT ? (i >> 9) : 0;
            int row = (i >> 2) & 127, c = i & 3;
            const char* s = half ? Al : Ah;
            cpasync16(dst + half * AOP + row * 80 + c * 16,
                      s + (size_t)(m0 + row) * ldaB + kByte + c * 16);
        } else {
            int j = i - NA;
            int half = SPLIT ? (j / (BN * 4)) : 0;
            int row = (j >> 2) % BN, c = j & 3;
            const char* s = half ? Bl : Bh;
            cpasync16(dst + (1 + SPLIT) * AOP + half * BOP + row * 80 + c * 16,
                      s + (size_t)(n0 + row) * ldbB + kByte + c * 16);
        }
    }
}

template<int BN, int OUT_MODE, int SPLIT>
__global__ __launch_bounds__(256, 1)
void mma_gemm(const __nv_bfloat16* __restrict__ Ah, const __nv_bfloat16* __restrict__ Al,
              int lda, long long sA,
              const __nv_bfloat16* __restrict__ Bh, const __nv_bfloat16* __restrict__ Bl,
              int ldb, long long sB,
              const float* __restrict__ bias,
              float* __restrict__ C,
              __nv_bfloat16* __restrict__ Ch, __nv_bfloat16* __restrict__ Cl,
              int ldc, long long sC, int K)
{
    constexpr int AOP = 128 * 80, BOP = BN * 80;
    constexpr int BBASE = (1 + SPLIT) * AOP;
    constexpr int ST = (1 + SPLIT) * (AOP + BOP);
    constexpr int NW = BN / 4;
    constexpr int NI = NW / 8;
    constexpr int NGI = NW / 16;

    extern __shared__ char smem[];
    const unsigned sb = smem_u32(smem);
    const int t = threadIdx.x;
    const int n0 = blockIdx.x * BN, m0 = blockIdx.y * 128, z = blockIdx.z;

    const char* cAh = (const char*)(Ah + (size_t)z * sA);
    const char* cAl = SPLIT ? (const char*)(Al + (size_t)z * sA) : cAh;
    const char* cBh = (const char*)(Bh + (size_t)z * sB);
    const char* cBl = SPLIT ? (const char*)(Bl + (size_t)z * sB) : cBh;
    const int ldaB = lda * 2, ldbB = ldb * 2;

    const int w = t >> 5, lane = t & 31;
    const int wm = (w & 1) * 64, wn = (w >> 1) * NW;
    const int aRowSel = (lane & 7) + ((lane >> 3) & 1) * 8;
    const int aChunk  = (lane >> 4) * 16;
    const int bRowSel = (lane & 7) + (lane >> 4) * 8;
    const int bChunk  = ((lane >> 3) & 1) * 16;

    float acc[4][NI][4];
#pragma unroll
    for (int mi = 0; mi < 4; mi++)
#pragma unroll
        for (int ni = 0; ni < NI; ni++)
#pragma unroll
            for (int r = 0; r < 4; r++) acc[mi][ni][r] = 0.f;

    const int nst = K / 32;
    mm_load<BN, SPLIT>(sb, t, cAh, cAl, cBh, cBl, ldaB, ldbB, m0, n0, 0);
    CP_COMMIT();

    for (int s = 0; s < nst; s++) {
        if (s + 1 < nst) {
            mm_load<BN, SPLIT>(sb + ((s + 1) & 1) * ST, t, cAh, cAl, cBh, cBl,
                               ldaB, ldbB, m0, n0, (s + 1) * 64);
            CP_COMMIT();
            CP_WAIT1();
        } else {
            CP_WAIT0();
        }
        __syncthreads();

        const unsigned base = sb + (s & 1) * ST;
#pragma unroll
        for (int s2 = 0; s2 < 2; s2++) {
            unsigned ah[4][4], al[4][4];
#pragma unroll
            for (int mi = 0; mi < 4; mi++) {
                unsigned ar = base + (wm + mi * 16 + aRowSel) * 80 + s2 * 32 + aChunk;
                ldsm_x4(ah[mi][0], ah[mi][1], ah[mi][2], ah[mi][3], ar);
                if (SPLIT) ldsm_x4(al[mi][0], al[mi][1], al[mi][2], al[mi][3], ar + AOP);
            }
            unsigned bh[NI][2], bl[NI][2];
#pragma unroll
            for (int ngi = 0; ngi < NGI; ngi++) {
                unsigned br = base + BBASE + (wn + ngi * 16 + bRowSel) * 80 + s2 * 32 + bChunk;
                unsigned r0, r1, r2, r3;
                ldsm_x4(r0, r1, r2, r3, br);
                bh[2 * ngi][0] = r0; bh[2 * ngi][1] = r1;
                bh[2 * ngi + 1][0] = r2; bh[2 * ngi + 1][1] = r3;
                if (SPLIT) {
                    ldsm_x4(r0, r1, r2, r3, br + BOP);
                    bl[2 * ngi][0] = r0; bl[2 * ngi][1] = r1;
                    bl[2 * ngi + 1][0] = r2; bl[2 * ngi + 1][1] = r3;
                }
            }
#pragma unroll
            for (int mi = 0; mi < 4; mi++)
#pragma unroll
                for (int ni = 0; ni < NI; ni++) {
                    mma_bf16(acc[mi][ni], ah[mi], bh[ni]);
                    if (SPLIT) {
                        mma_bf16(acc[mi][ni], ah[mi], bl[ni]);
                        mma_bf16(acc[mi][ni], al[mi], bh[ni]);
                    }
                }
        }
        __syncthreads();
    }

    const int g = lane >> 2, tg = lane & 3;

    if (OUT_MODE == 2) {
        float* Ss = (float*)smem;
#pragma unroll
        for (int mi = 0; mi < 4; mi++)
#pragma unroll
            for (int ni = 0; ni < NI; ni++) {
                int col = wn + ni * 8 + 2 * tg;
                float b0 = __ldg(bias + n0 + col), b1 = __ldg(bias + n0 + col + 1);
#pragma unroll
                for (int half = 0; half < 2; half++) {
                    int row = wm + mi * 16 + half * 8 + g;
                    Ss[row * 132 + col]     = acc[mi][ni][2 * half + 0] + b0;
                    Ss[row * 132 + col + 1] = acc[mi][ni][2 * half + 1] + b1;
                }
            }
        __syncthreads();
        const int b = m0 >> 10, l0 = m0 & 1023;
        const int m = lane * 4;
#pragma unroll
        for (int i = 0; i < 16; i++) {
            int n = w * 16 + i;
            float v0 = Ss[(m + 0) * 132 + n];
            float v1 = Ss[(m + 1) * 132 + n];
            float v2 = Ss[(m + 2) * 132 + n];
            float v3 = Ss[(m + 3) * 132 + n];
            size_t ob = ((size_t)(b * 256 + n0 + n)) * 1024 + l0 + m;
            uint2 uh;
            uh.x = pack2f(v0, v1);
            uh.y = pack2f(v2, v3);
            *(uint2*)(Ch + ob) = uh;
        }
        return;
    }

#pragma unroll
    for (int mi = 0; mi < 4; mi++) {
#pragma unroll
        for (int ni = 0; ni < NI; ni++) {
            int gr = m0 + wm + mi * 16 + g;
            int gc = n0 + wn + ni * 8 + 2 * tg;
            float b0 = 0.f, b1 = 0.f;
            if (bias) { b0 = __ldg(bias + gc); b1 = __ldg(bias + gc + 1); }
#pragma unroll
            for (int half = 0; half < 2; half++) {
                size_t idx = (size_t)z * sC + (size_t)(gr + half * 8) * ldc + gc;
                float v0 = acc[mi][ni][2 * half + 0] + b0;
                float v1 = acc[mi][ni][2 * half + 1] + b1;
                if (OUT_MODE == 1) {
                    __nv_bfloat16 h0, l0b, h1, l1b;
                    bf16split(v0, h0, l0b); bf16split(v1, h1, l1b);
                    *(__nv_bfloat162*)(Ch + idx) = __halves2bfloat162(h0, h1);
                    *(__nv_bfloat162*)(Cl + idx) = __halves2bfloat162(l0b, l1b);
                } else if (OUT_MODE == 3) {
                    *(unsigned*)(Ch + idx) = pack2f(v0, v1);
                } else {
                    float2 o; o.x = v0; o.y = v1;
                    *(float2*)(C + idx) = o;
                }
            }
        }
    }
}

// ---------------------------------------------------------------------------
// Fused flash attention (full 256-ch per CTA — no duplicated S/softmax):
// att = gamma*softmax(QK^T)V + xa.  Grid (8 m-tiles, 64 b); 256 threads,
// 8 warps of 16 m-rows; each warp: S 16x128, O 16x256.
// smem: Q 10240 | 2 chunk buffers x (K 10240 + V 4x20480) = 194560 B.
// ---------------------------------------------------------------------------
#define FA_CBS  92160
#define FA_SMEM 194560

__device__ __forceinline__ void fa_load_q(unsigned sb, int t, const char* gQ)
{
#pragma unroll
    for (int u = 0; u < 2; u++) {
        int i = t + u * 256;
        int row = i >> 2, c = i & 3;
        cpasync16(sb + row * 80 + c * 16, gQ + (size_t)row * 128 + c * 16);
    }
}

__device__ __forceinline__ void fa_load_chunk(unsigned dst, int t,
    const char* gK, const char* gV, int ch)
{
#pragma unroll
    for (int u = 0; u < 2; u++) {     // K: 128 rows x 64B
        int i = t + u * 256;
        int row = i >> 2, c = i & 3;
        cpasync16(dst + row * 80 + c * 16,
                  gK + (size_t)(ch * 128 + row) * 128 + c * 16);
    }
#pragma unroll
    for (int u = 0; u < 16; u++) {    // V: 4 k-groups x 256 n x 64B
        int i = t + u * 256;
        int c = i & 3, n = (i >> 2) & 255, kg = i >> 10;
        cpasync16(dst + 10240 + kg * 20480 + n * 80 + c * 16,
                  gV + (size_t)n * 2048 + ch * 256 + kg * 64 + c * 16);
    }
}

__global__ __launch_bounds__(256, 1)
void fa_kernel(const __nv_bfloat16* __restrict__ qkh,
               const __nv_bfloat16* __restrict__ vTh,
               const __nv_bfloat16* __restrict__ resh, const __nv_bfloat16* __restrict__ resl,
               const float* __restrict__ gammaPtr,
               __nv_bfloat16* __restrict__ atth, __nv_bfloat16* __restrict__ attl)
{
    extern __shared__ char smem[];
    const unsigned sb = smem_u32(smem);
    const int t = threadIdx.x;
    const int m0 = blockIdx.x * 128, b = blockIdx.y;

    const char* gQ = (const char*)qkh + (size_t)(b * 1024 + m0) * 128;
    const char* gK = (const char*)qkh + (size_t)(b * 1024) * 128 + 64;
    const char* gV = (const char*)vTh + (size_t)(b * 256) * 2048;

    const int w = t >> 5, lane = t & 31;
    const int wm = w * 16;
    const int g = lane >> 2, tg = lane & 3;
    const int aRowSel = (lane & 7) + ((lane >> 3) & 1) * 8;
    const int aChunk  = (lane >> 4) * 16;
    const int bRowSel = (lane & 7) + (lane >> 4) * 8;
    const int bChunk  = ((lane >> 3) & 1) * 16;

    float oacc[32][4];
#pragma unroll
    for (int ni = 0; ni < 32; ni++)
#pragma unroll
        for (int r = 0; r < 4; r++) oacc[ni][r] = 0.f;
    float m0r = -1e30f, m1r = -1e30f, z0r = 0.f, z1r = 0.f;

    fa_load_q(sb, t, gQ);
    fa_load_chunk(sb + 10240, t, gK, gV, 0);
    CP_COMMIT();

    for (int ch = 0; ch < 8; ch++) {
        if (ch + 1 < 8) {
            fa_load_chunk(sb + 10240 + ((ch + 1) & 1) * FA_CBS, t, gK, gV, ch + 1);
            CP_COMMIT();
            CP_WAIT1();
        } else {
            CP_WAIT0();
        }
        __syncthreads();

        const unsigned kb = sb + 10240 + (ch & 1) * FA_CBS;

        // ---- S = Q K_chunk^T (single pass), 16m x 128j per warp ----
        float sacc[16][4];
#pragma unroll
        for (int ni = 0; ni < 16; ni++)
#pragma unroll
            for (int r = 0; r < 4; r++) sacc[ni][r] = 0.f;

#pragma unroll
        for (int s2 = 0; s2 < 2; s2++) {
            unsigned qh[4];
            ldsm_x4(qh[0], qh[1], qh[2], qh[3],
                    sb + (wm + aRowSel) * 80 + s2 * 32 + aChunk);
#pragma unroll
            for (int ngi = 0; ngi < 8; ngi++) {
                unsigned br = kb + (ngi * 16 + bRowSel) * 80 + s2 * 32 + bChunk;
                unsigned r0, r1, r2, r3;
                ldsm_x4(r0, r1, r2, r3, br);
                unsigned b0[2] = { r0, r1 }, b1[2] = { r2, r3 };
                mma_bf16(sacc[2 * ngi],     qh, b0);
                mma_bf16(sacc[2 * ngi + 1], qh, b1);
            }
        }

        // ---- online softmax (register + shfl over the 4 tg lanes) ----
        float cm0 = -1e30f, cm1 = -1e30f;
#pragma unroll
        for (int ni = 0; ni < 16; ni++) {
            cm0 = fmaxf(cm0, fmaxf(sacc[ni][0], sacc[ni][1]));
            cm1 = fmaxf(cm1, fmaxf(sacc[ni][2], sacc[ni][3]));
        }
        cm0 = fmaxf(cm0, __shfl_xor_sync(0xffffffffu, cm0, 1));
        cm0 = fmaxf(cm0, __shfl_xor_sync(0xffffffffu, cm0, 2));
        cm1 = fmaxf(cm1, __shfl_xor_sync(0xffffffffu, cm1, 1));
        cm1 = fmaxf(cm1, __shfl_xor_sync(0xffffffffu, cm1, 2));

        float nm0 = fmaxf(m0r, cm0), nm1 = fmaxf(m1r, cm1);
        float sc0 = __expf(m0r - nm0), sc1 = __expf(m1r - nm1);
        float cs0 = 0.f, cs1 = 0.f;
#pragma unroll
        for (int ni = 0; ni < 16; ni++) {
            sacc[ni][0] = __expf(sacc[ni][0] - nm0);
            sacc[ni][1] = __expf(sacc[ni][1] - nm0);
            sacc[ni][2] = __expf(sacc[ni][2] - nm1);
            sacc[ni][3] = __expf(sacc[ni][3] - nm1);
            cs0 += sacc[ni][0] + sacc[ni][1];
            cs1 += sacc[ni][2] + sacc[ni][3];
        }
        cs0 += __shfl_xor_sync(0xffffffffu, cs0, 1);
        cs0 += __shfl_xor_sync(0xffffffffu, cs0, 2);
        cs1 += __shfl_xor_sync(0xffffffffu, cs1, 1);
        cs1 += __shfl_xor_sync(0xffffffffu, cs1, 2);

        z0r = z0r * sc0 + cs0;
        z1r = z1r * sc1 + cs1;
        m0r = nm0; m1r = nm1;
#pragma unroll
        for (int ni = 0; ni < 32; ni++) {
            oacc[ni][0] *= sc0; oacc[ni][1] *= sc0;
            oacc[ni][2] *= sc1; oacc[ni][3] *= sc1;
        }

        // ---- O += P_chunk @ V_chunk (full 256 n; P from C-frag, bf16) ----
#pragma unroll
        for (int u = 0; u < 8; u++) {
            unsigned pa[4];
            pa[0] = pack2f(sacc[2 * u][0],     sacc[2 * u][1]);
            pa[1] = pack2f(sacc[2 * u][2],     sacc[2 * u][3]);
            pa[2] = pack2f(sacc[2 * u + 1][0], sacc[2 * u + 1][1]);
            pa[3] = pack2f(sacc[2 * u + 1][2], sacc[2 * u + 1][3]);
            const unsigned vgb = kb + 10240 + (u >> 1) * 20480;
            const int s2v = u & 1;
#pragma unroll
            for (int ngi = 0; ngi < 16; ngi++) {
                unsigned br = vgb + (ngi * 16 + bRowSel) * 80 + s2v * 32 + bChunk;
                unsigned r0, r1, r2, r3;
                ldsm_x4(r0, r1, r2, r3, br);
                unsigned bv0[2] = { r0, r1 }, bv1[2] = { r2, r3 };
                mma_bf16(oacc[2 * ngi],     pa, bv0);
                mma_bf16(oacc[2 * ngi + 1], pa, bv1);
            }
        }
        __syncthreads();
    }

    // ---- epilogue: att = gamma * O / z + (xah + xal) -> bf16 hi/lo ----
    const float gam = __ldg(gammaPtr);
    const float gz0 = gam / z0r, gz1 = gam / z1r;
    const int gr0 = b * 1024 + m0 + wm + g;
#pragma unroll
    for (int ni = 0; ni < 32; ni++) {
        int gc = ni * 8 + 2 * tg;
        size_t i0 = (size_t)gr0 * 256 + gc;
        size_t i1 = i0 + (size_t)8 * 256;
        __nv_bfloat162 rh0 = *(const __nv_bfloat162*)(resh + i0);
        __nv_bfloat162 rl0 = *(const __nv_bfloat162*)(resl + i0);
        __nv_bfloat162 rh1 = *(const __nv_bfloat162*)(resh + i1);
        __nv_bfloat162 rl1 = *(const __nv_bfloat162*)(resl + i1);
        float v0 = fmaf(gz0, oacc[ni][0], __bfloat162float(rh0.x) + __bfloat162float(rl0.x));
        float v1 = fmaf(gz0, oacc[ni][1], __bfloat162float(rh0.y) + __bfloat162float(rl0.y));
        float v2 = fmaf(gz1, oacc[ni][2], __bfloat162float(rh1.x) + __bfloat162float(rl1.x));
        float v3 = fmaf(gz1, oacc[ni][3], __bfloat162float(rh1.y) + __bfloat162float(rl1.y));
        __nv_bfloat16 h0, l0, h1, l1;
        bf16split(v0, h0, l0); bf16split(v1, h1, l1);
        *(__nv_bfloat162*)(atth + i0) = __halves2bfloat162(h0, h1);
        *(__nv_bfloat162*)(attl + i0) = __halves2bfloat162(l0, l1);
        bf16split(v2, h0, l0); bf16split(v3, h1, l1);
        *(__nv_bfloat162*)(atth + i1) = __halves2bfloat162(h0, h1);
        *(__nv_bfloat162*)(attl + i1) = __halves2bfloat162(l0, l1);
    }
}

// ---------------------------------------------------------------------------
// SIMT SGEMM (only for tiny pre-linear), B stored [N,K] row-major
// ---------------------------------------------------------------------------
__global__ __launch_bounds__(256)
void sgemm_kernel(const float* __restrict__ A, const float* __restrict__ Bm,
                  const float* __restrict__ bias, float* __restrict__ C,
                  int M, int N, int K, int lda, int ldb, int ldc)
{
    __shared__ float As[8][128];
    __shared__ float Bs[8][128];

    const int tid = threadIdx.x;
    const int m0 = blockIdx.y * 128;
    const int n0 = blockIdx.x * 128;

    const int aRow = tid >> 1;
    const int aK   = (tid & 1) << 2;
    const int tr = (tid >> 4) << 3;
    const int tc = (tid & 15) << 3;

    const bool aOK = (m0 + aRow) < M;
    const bool bOK = (n0 + aRow) < N;
    const float* aPtr = A + (long long)(m0 + aRow) * lda + aK;
    const float* bPtr = Bm + (long long)(n0 + aRow) * ldb + aK;

    float acc[8][8];
#pragma unroll
    for (int i = 0; i < 8; i++)
#pragma unroll
        for (int j = 0; j < 8; j++) acc[i][j] = 0.f;

    float4 aReg = make_float4(0.f, 0.f, 0.f, 0.f);
    float4 bReg = make_float4(0.f, 0.f, 0.f, 0.f);
    if (aOK) aReg = *(const float4*)aPtr;
    if (bOK) bReg = *(const float4*)bPtr;

    for (int k0 = 0; k0 < K; k0 += 8) {
        As[aK + 0][aRow] = aReg.x; As[aK + 1][aRow] = aReg.y;
        As[aK + 2][aRow] = aReg.z; As[aK + 3][aRow] = aReg.w;
        Bs[aK + 0][aRow] = bReg.x; Bs[aK + 1][aRow] = bReg.y;
        Bs[aK + 2][aRow] = bReg.z; Bs[aK + 3][aRow] = bReg.w;
        __syncthreads();

        if (k0 + 8 < K) {
            aReg = make_float4(0.f, 0.f, 0.f, 0.f);
            bReg = make_float4(0.f, 0.f, 0.f, 0.f);
            if (aOK) aReg = *(const float4*)(aPtr + (k0 + 8));
            if (bOK) bReg = *(const float4*)(bPtr + (k0 + 8));
        }

#pragma unroll
        for (int kk = 0; kk < 8; kk++) {
            float ar[8], br[8];
            *(float4*)&ar[0] = *(const float4*)&As[kk][tr];
            *(float4*)&ar[4] = *(const float4*)&As[kk][tr + 4];
            *(float4*)&br[0] = *(const float4*)&Bs[kk][tc];
            *(float4*)&br[4] = *(const float4*)&Bs[kk][tc + 4];
#pragma unroll
            for (int i = 0; i < 8; i++)
#pragma unroll
                for (int j = 0; j < 8; j++)
                    acc[i][j] = fmaf(ar[i], br[j], acc[i][j]);
        }
        __syncthreads();
    }

#pragma unroll
    for (int i = 0; i < 8; i++) {
        int gm = m0 + tr + i;
        if (gm < M) {
#pragma unroll
            for (int j = 0; j < 8; j += 4) {
                int gn = n0 + tc + j;
                if (gn < N) {
                    float4 o;
                    o.x = acc[i][j]; o.y = acc[i][j + 1];
                    o.z = acc[i][j + 2]; o.w = acc[i][j + 3];
                    if (bias) {
                        o.x += __ldg(bias + gn);     o.y += __ldg(bias + gn + 1);
                        o.z += __ldg(bias + gn + 2); o.w += __ldg(bias + gn + 3);
                    }
                    *(float4*)(C + (long long)gm * ldc + gn) = o;
                }
            }
        }
    }
}

// ---------------------------------------------------------------------------
// Weight prep: wq||wk single bf16; wv single bf16; w1 split; merge bq||bk
// ---------------------------------------------------------------------------
__global__ void wprep_kernel(const float* __restrict__ wq, const float* __restrict__ wk,
                             const float* __restrict__ wv, const float* __restrict__ w1,
                             const float* __restrict__ bq, const float* __restrict__ bk,
                             float* __restrict__ bqk,
                             __nv_bfloat16* __restrict__ wqkh,
                             __nv_bfloat16* __restrict__ wvh,
                             __nv_bfloat16* __restrict__ w1h, __nv_bfloat16* __restrict__ w1l)
{
    int i = blockIdx.x * 256 + threadIdx.x;
    if (i < 16384) {
        int n = i >> 8, k = i & 255;
        float v = (n < 32) ? wq[n * 256 + k] : wk[(n - 32) * 256 + k];
        wqkh[i] = __float2bfloat16(v);
    } else if (i < 81920) {
        int j = i - 16384;
        wvh[j] = __float2bfloat16(wv[j]);
    } else if (i < 98304) {
        int j = i - 81920;
        __nv_bfloat16 h, l;
        bf16split(w1[j], h, l);
        w1h[j] = h; w1l[j] = l;
    }
    if (i < 64) bqk[i] = (i < 32) ? bq[i] : bk[i - 32];
}

// ---------------------------------------------------------------------------
// x0 moment stats (8 + 36 vals) per batch; deterministic reductions.
// ---------------------------------------------------------------------------
__global__ __launch_bounds__(256)
void xstats_partial(const float* __restrict__ x0, float* __restrict__ pX)
{
    const int b = blockIdx.x, t = threadIdx.x;
    const int warp = t >> 5, lane = t & 31;
    float a[44];
#pragma unroll
    for (int j = 0; j < 44; j++) a[j] = 0.f;

#pragma unroll
    for (int r = 0; r < 4; r++) {
        int l = t + r * 256;
        float v[CIN];
#pragma unroll
        for (int c = 0; c < CIN; c++)
            v[c] = x0[b * (CIN * LL) + c * LL + l];
#pragma unroll
        for (int c = 0; c < CIN; c++) a[c] += v[c];
        int idx = CIN;
#pragma unroll
        for (int c1 = 0; c1 < CIN; c1++)
#pragma unroll
            for (int c2 = c1; c2 < CIN; c2++)
                a[idx++] = fmaf(v[c1], v[c2], a[idx]);
    }
#pragma unroll
    for (int j = 0; j < 44; j++)
#pragma unroll
        for (int o = 16; o; o >>= 1)
            a[j] += __shfl_xor_sync(0xffffffffu, a[j], o);

    __shared__ float ws[8][44];
    if (lane == 0)
#pragma unroll
        for (int j = 0; j < 44; j++) ws[warp][j] = a[j];
    __syncthreads();
    if (t < 44) {
        float s = ws[0][t];
#pragma unroll
        for (int w = 1; w < 8; w++) s += ws[w][t];
        pX[b * 44 + t] = s;
    }
}

__global__ void xstats_final(const float* __restrict__ pX,
                             const float* __restrict__ w0, const float* __restrict__ b0,
                             const float* __restrict__ g0, const float* __restrict__ be0,
                             float* __restrict__ scale, float* __restrict__ shift)
{
    __shared__ float mom[44];
    __shared__ float mu[CIN];
    __shared__ float cov[CIN][CIN];
    const int t = threadIdx.x;
    if (t < 44) {
        float s = 0.f;
        for (int b = 0; b < 64; b++) s += pX[b * 44 + t];
        mom[t] = s;
    }
    __syncthreads();
    if (t == 0) {
        const float inv = 1.f / 65536.f;
        for (int c = 0; c < CIN; c++) mu[c] = mom[c] * inv;
        int idx = CIN;
        for (int c1 = 0; c1 < CIN; c1++)
            for (int c2 = c1; c2 < CIN; c2++) {
                float cv = mom[idx++] * inv - mu[c1] * mu[c2];
                cov[c1][c2] = cv; cov[c2][c1] = cv;
            }
    }
    __syncthreads();
    float w[CIN];
#pragma unroll
    for (int c = 0; c < CIN; c++) w[c] = w0[t * CIN + c];
    float mean = __ldg(b0 + t);
#pragma unroll
    for (int c = 0; c < CIN; c++) mean = fmaf(w[c], mu[c], mean);
    float var = 0.f;
#pragma unroll
    for (int c1 = 0; c1 < CIN; c1++) {
        float acc = 0.f;
#pragma unroll
        for (int c2 = 0; c2 < CIN; c2++) acc = fmaf(w[c2], cov[c1][c2], acc);
        var = fmaf(w[c1], acc, var);
    }
    float sc = __ldg(g0 + t) * rsqrtf(var + 1e-5f);
    scale[t] = sc;
    shift[t] = __ldg(be0 + t) - mean * sc;
}

// ---------------------------------------------------------------------------
// Fused conv0 + BN0 + ReLU -> xah/xal bf16
// ---------------------------------------------------------------------------
__global__ __launch_bounds__(256)
void conv0_fused(const float* __restrict__ x0, const float* __restrict__ w0,
                 const float* __restrict__ b0,
                 const float* __restrict__ sc0, const float* __restrict__ sh0,
                 __nv_bfloat16* __restrict__ xah, __nv_bfloat16* __restrict__ xal)
{
    __shared__ float ws[C0C * CIN];
    __shared__ float xs[CIN][16];
    const int t = threadIdx.x;
    for (int i = t; i < C0C * CIN; i += 256) ws[i] = w0[i];
    const int g0 = blockIdx.x * 16;
    const int b = g0 >> 10, l0 = g0 & 1023;
    if (t < 128) {
        int c = t >> 4, i = t & 15;
        xs[c][i] = x0[b * (CIN * LL) + c * LL + l0 + i];
    }
    __syncthreads();

    float wreg[CIN];
#pragma unroll
    for (int c = 0; c < CIN; c++) wreg[c] = ws[t * CIN + c];
    const float bb = __ldg(b0 + t);
    const float sc = __ldg(sc0 + t), sh = __ldg(sh0 + t);
#pragma unroll
    for (int i = 0; i < 16; i++) {
        float acc = bb;
#pragma unroll
        for (int c = 0; c < CIN; c++) acc = fmaf(wreg[c], xs[c][i], acc);
        float v = fmaxf(fmaf(acc, sc, sh), 0.f);
        __nv_bfloat16 h, l;
        bf16split(v, h, l);
        size_t o = (size_t)(g0 + i) * C0C + t;
        xah[o] = h; xal[o] = l;
    }
}

// ---------------------------------------------------------------------------
// BN stats (deterministic two-stage) — BN1 only
// ---------------------------------------------------------------------------
__global__ __launch_bounds__(256)
void bnstats_partial(const float* __restrict__ y, int nch,
                     float* __restrict__ pS, float* __restrict__ pQ)
{
    const int chunk = blockIdx.x;
    const int group = blockIdx.y;
    const int t = threadIdx.x;
    const int warp = t >> 5, lane = t & 31;
    const int ch = group * 32 + lane;
    const long long base = (long long)chunk * 1024;

    float s = 0.f, q = 0.f;
    for (int r = warp; r < 1024; r += 8) {
        float v = y[(base + r) * nch + ch];
        s += v; q = fmaf(v, v, q);
    }
    __shared__ float ss[8][32], sq[8][32];
    ss[warp][lane] = s; sq[warp][lane] = q;
    __syncthreads();
    if (warp == 0) {
        float S = ss[0][lane], Q = sq[0][lane];
#pragma unroll
        for (int w = 1; w < 8; w++) { S += ss[w][lane]; Q += sq[w][lane]; }
        pS[ch * 64 + chunk] = S;
        pQ[ch * 64 + chunk] = Q;
    }
}

__global__ void bnfinalize(const float* __restrict__ pS, const float* __restrict__ pQ,
                           const float* __restrict__ g, const float* __restrict__ be,
                           float* __restrict__ scale, float* __restrict__ shift, int nch)
{
    int ch = blockIdx.x * blockDim.x + threadIdx.x;
    if (ch >= nch) return;
    float s0 = 0.f, s1 = 0.f, s2 = 0.f, s3 = 0.f;
    float q0 = 0.f, q1 = 0.f, q2 = 0.f, q3 = 0.f;
#pragma unroll
    for (int i = 0; i < 64; i += 4) {
        s0 += pS[ch * 64 + i];     q0 += pQ[ch * 64 + i];
        s1 += pS[ch * 64 + i + 1]; q1 += pQ[ch * 64 + i + 1];
        s2 += pS[ch * 64 + i + 2]; q2 += pQ[ch * 64 + i + 2];
        s3 += pS[ch * 64 + i + 3]; q3 += pQ[ch * 64 + i + 3];
    }
    float s = (s0 + s1) + (s2 + s3);
    float q = (q0 + q1) + (q2 + q3);
    const float inv = 1.f / 65536.f;
    float mean = s * inv;
    float var = q * inv - mean * mean;
    float sc = __ldg(g + ch) * rsqrtf(var + 1e-5f);
    scale[ch] = sc;
    shift[ch] = __ldg(be + ch) - mean * sc;
}

// ---------------------------------------------------------------------------
// Final: out[b][cin][l] = b_out[cin] + sum_f w_out[cin][f] * relu(bn1(x1[g][f]))
// ---------------------------------------------------------------------------
__global__ __launch_bounds__(256)
void final_kernel(const float* __restrict__ x1,
                  const float* __restrict__ scale1, const float* __restrict__ shift1,
                  const float* __restrict__ w_out, const float* __restrict__ b_out,
                  float* __restrict__ out)
{
    __shared__ float xs[32][65];
    __shared__ float wsh[8][64];
    const int t = threadIdx.x;
    const int g0 = blockIdx.x * 32;

    for (int i = t; i < 32 * 64; i += 256) {
        int pos = i >> 6, f = i & 63;
        float v = x1[(size_t)(g0 + pos) * FFC + f];
        v = fmaf(v, __ldg(scale1 + f), __ldg(shift1 + f));
        xs[pos][f] = fmaxf(v, 0.f);
    }
    for (int i = t; i < 8 * 64; i += 256) wsh[i >> 6][i & 63] = w_out[i];
    __syncthreads();

    const int pos = t & 31, cin = t >> 5;
    float acc = __ldg(b_out + cin);
#pragma unroll
    for (int f = 0; f < 64; f++) acc = fmaf(wsh[cin][f], xs[pos][f], acc);

    const int b = g0 >> 10, l0 = g0 & 1023;
    out[b * (CIN * LL) + cin * LL + l0 + pos] = acc;
}

// ---------------------------------------------------------------------------
// Host launcher (graph-capturable: kernel launches only)
// ---------------------------------------------------------------------------
extern "C" void kernel_launch(void* const* d_in, const int* in_sizes, int n_in,
                              void* d_out, int out_size)
{
    const float* z     = (const float*)d_in[0];
    const float* w_pre = (const float*)d_in[1];
    const float* b_pre = (const float*)d_in[2];
    const float* w0    = (const float*)d_in[3];
    const float* b0    = (const float*)d_in[4];
    const float* g0    = (const float*)d_in[5];
    const float* be0   = (const float*)d_in[6];
    const float* wq    = (const float*)d_in[7];
    const float* bq    = (const float*)d_in[8];
    const float* wk    = (const float*)d_in[9];
    const float* bk    = (const float*)d_in[10];
    const float* wv    = (const float*)d_in[11];
    const float* bv    = (const float*)d_in[12];
    const float* gamma = (const float*)d_in[13];
    const float* w1    = (const float*)d_in[14];
    const float* b1    = (const float*)d_in[15];
    const float* g1    = (const float*)d_in[16];
    const float* be1   = (const float*)d_in[17];
    const float* w_out = (const float*)d_in[18];
    const float* b_out = (const float*)d_in[19];
    float* out = (float*)d_out;

    float *x0, *x1, *pS, *pQ, *sc0, *sh0, *sc1, *sh1, *bqk;
    __nv_bfloat16 *xah, *xal, *qkh, *vTh, *atth, *attl;
    __nv_bfloat16 *wqkh, *wvh, *w1h, *w1l;
    cudaGetSymbolAddress((void**)&x0,   g_x0);
    cudaGetSymbolAddress((void**)&xah,  g_xah);
    cudaGetSymbolAddress((void**)&xal,  g_xal);
    cudaGetSymbolAddress((void**)&qkh,  g_qkh);
    cudaGetSymbolAddress((void**)&vTh,  g_vTh);
    cudaGetSymbolAddress((void**)&atth, g_atth);
    cudaGetSymbolAddress((void**)&attl, g_attl);
    cudaGetSymbolAddress((void**)&x1,   g_x1);
    cudaGetSymbolAddress((void**)&pS,   g_pS);
    cudaGetSymbolAddress((void**)&pQ,   g_pQ);
    cudaGetSymbolAddress((void**)&sc0,  g_scale0);
    cudaGetSymbolAddress((void**)&sh0,  g_shift0);
    cudaGetSymbolAddress((void**)&sc1,  g_scale1);
    cudaGetSymbolAddress((void**)&sh1,  g_shift1);
    cudaGetSymbolAddress((void**)&wqkh, g_wqkh);
    cudaGetSymbolAddress((void**)&wvh,  g_wvh);
    cudaGetSymbolAddress((void**)&w1h,  g_w1h);
    cudaGetSymbolAddress((void**)&w1l,  g_w1l);
    cudaGetSymbolAddress((void**)&bqk,  g_bqk);

    const int ST_QK   = 2 * (128 * 80 + 64 * 80);           // 30720 (SPLIT=0)
    const int ST_VP   = 67584;                              // max(2*20480, Ss 128*132*4)
    const int ST_C1   = 2 * (2 * 128 * 80 + 2 * 64 * 80);   // 61440 (SPLIT=1)
    cudaFuncSetAttribute(fa_kernel, cudaFuncAttributeMaxDynamicSharedMemorySize, FA_SMEM);
    cudaFuncSetAttribute(mma_gemm<64, 3, 0>,  cudaFuncAttributeMaxDynamicSharedMemorySize, ST_QK);
    cudaFuncSetAttribute(mma_gemm<128, 2, 0>, cudaFuncAttributeMaxDynamicSharedMemorySize, ST_VP);
    cudaFuncSetAttribute(mma_gemm<64, 0, 1>,  cudaFuncAttributeMaxDynamicSharedMemorySize, ST_C1);

    // 1) pre-linear: x0 = z @ w_pre^T + b_pre   [64 x 8192], K=128
    sgemm_kernel<<<dim3(8192 / 128, 1, 1), 256>>>(
        z, w_pre, b_pre, x0, NB, CIN * LL, ZD, ZD, ZD, CIN * LL);

    // 2) weight prep (independent)
    wprep_kernel<<<384, 256>>>(wq, wk, wv, w1, bq, bk, bqk,
                               wqkh, wvh, w1h, w1l);

    // 3) BN0 via x0 moments (2 MB) -> analytic scale/shift
    xstats_partial<<<64, 256>>>(x0, pS);
    xstats_final<<<1, 256>>>(pS, w0, b0, g0, be0, sc0, sh0);

    // 4) fused conv0 + BN0 + ReLU -> xah/xal bf16
    conv0_fused<<<GG / 16, 256>>>(x0, w0, b0, sc0, sh0, xah, xal);

    // 5) Q+K projection (single bf16 in/out): [g][64], K=256
    mma_gemm<64, 3, 0><<<dim3(1, GG / 128, 1), 256, ST_QK>>>(
        xah, nullptr, C0C, 0, wqkh, nullptr, C0C, 0, bqk,
        nullptr, qkh, nullptr, 64, 0, C0C);

    // 6) V projection (single bf16 in) with fused transpose -> vTh, K=256
    mma_gemm<128, 2, 0><<<dim3(2, GG / 128, 1), 256, ST_VP>>>(
        xah, nullptr, C0C, 0, wvh, nullptr, C0C, 0, bv,
        nullptr, vTh, nullptr, 0, 0, C0C);

    // 7) fused flash attention (full 256-ch CTA): att -> bf16 hi/lo
    fa_kernel<<<dim3(8, NB), 256, FA_SMEM>>>(qkh, vTh, xah, xal,
                                             gamma, atth, attl);

    // 8) conv1 (split operands): x1 = att @ w1^T + b1  [g][64], K=256
    mma_gemm<64, 0, 1><<<dim3(1, GG / 128, 1), 256, ST_C1>>>(
        atth, attl, C0C, 0, w1h, w1l, C0C, 0, b1,
        x1, nullptr, nullptr, FFC, 0, C0C);

    // 9) BN1 stats
    bnstats_partial<<<dim3(64, FFC / 32), 256>>>(x1, FFC, pS, pQ);
    bnfinalize<<<1, 64>>>(pS, pQ, g1, be1, sc1, sh1, FFC);

    // 10) fused BN1 + relu + w_out conv -> out [b][8][1024]
    final_kernel<<<GG / 32, 256>>>(x1, sc1, sh1, w_out, b_out, out);

    (void)in_sizes; (void)n_in; (void)out_size;
}